// round 2
// baseline (speedup 1.0000x reference)
#include <cuda_runtime.h>
#include <math.h>

#define BB 2
#define CCH 32
#define HH 128
#define WW 128
#define NN (HH*WW)
#define NHEADS 8

// ---------------- scratch (static device globals; no allocation) ----------------
__device__ float g_cat96p[BB*96*NN];   // [l1 | l2 | xg]
__device__ float g_qkv[BB*96*NN];
__device__ float g_qkvd[BB*96*NN];     // q|k|v after grouped dwconv
__device__ float g_catxy[BB*64*NN];
__device__ float g_pool[BB*64*64*64];
__device__ float g_asmall[BB*166*62*62];
__device__ float g_bmid[BB*166*NN];
__device__ float g_offs[BB*166*NN];
__device__ float g_catf[BB*96*NN];     // [f3 | f5 | f7]
__device__ float g_kfeat[BB*CCH*NN];
__device__ float g_prompt[BB*CCH*NN];
__device__ float g_norms_in[BB*64];    // q norms (0..31), k norms (32..63)
__device__ float g_A_in[BB*NHEADS*4*4];
__device__ float g_Meff_in[BB*32*32];
__device__ float g_nf[BB*64];          // x norms (0..31), prompt norms (32..63)
__device__ float g_nk[BB*32];
__device__ float g_A_f[BB*NHEADS*8*4];
__device__ float g_Meff_f[BB*32*32];

// compile-time scratch-buffer resolution (no host-side symbol lookups needed)
template<int ID> __device__ __forceinline__ float* gbuf();
template<> __device__ __forceinline__ float* gbuf<1>()  { return g_cat96p; }
template<> __device__ __forceinline__ float* gbuf<4>()  { return g_catxy; }
template<> __device__ __forceinline__ float* gbuf<5>()  { return g_pool; }
template<> __device__ __forceinline__ float* gbuf<6>()  { return g_asmall; }
template<> __device__ __forceinline__ float* gbuf<7>()  { return g_bmid; }
template<> __device__ __forceinline__ float* gbuf<8>()  { return g_offs; }
template<> __device__ __forceinline__ float* gbuf<11>() { return g_prompt; }

// ---------------- fused LayerNorm + l1 (1x1) + qkv (1x1) ----------------
__global__ void k_ln_l1_qkv(const float* __restrict__ x, const float* __restrict__ ln_g,
                            const float* __restrict__ ln_b, const float* __restrict__ w_lp1,
                            const float* __restrict__ w_qkv) {
    __shared__ float s_w1[32*32];
    __shared__ float s_wq[96*32];
    __shared__ float s_g[32], s_b[32];
    int tid = threadIdx.x;
    for (int i = tid; i < 32*32; i += 256) s_w1[i] = w_lp1[i];
    for (int i = tid; i < 96*32; i += 256) s_wq[i] = w_qkv[i];
    if (tid < 32) { s_g[tid] = ln_g[tid]; s_b[tid] = ln_b[tid]; }
    __syncthreads();
    int gid = blockIdx.x*256 + tid;          // B*N threads exactly
    int b = gid / NN, p = gid % NN;
    float xv[32];
#pragma unroll
    for (int c = 0; c < 32; c++) xv[c] = x[(b*32 + c)*NN + p];
    float mu = 0.f;
#pragma unroll
    for (int c = 0; c < 32; c++) mu += xv[c];
    mu *= (1.f/32.f);
    float var = 0.f;
#pragma unroll
    for (int c = 0; c < 32; c++) { float d = xv[c]-mu; var += d*d; }
    var *= (1.f/32.f);
    float inv = rsqrtf(var + 1e-5f);
    float xn[32];
#pragma unroll
    for (int c = 0; c < 32; c++) xn[c] = (xv[c]-mu)*inv*s_g[c] + s_b[c];
    for (int o = 0; o < 32; o++) {
        float a = 0.f;
#pragma unroll
        for (int c = 0; c < 32; c++) a += s_w1[o*32+c]*xv[c];
        g_cat96p[(b*96 + o)*NN + p] = a;     // l1 -> channels 0..31
    }
    for (int o = 0; o < 96; o++) {
        float a = 0.f;
#pragma unroll
        for (int c = 0; c < 32; c++) a += s_wq[o*32+c]*xn[c];
        g_qkv[(b*96 + o)*NN + p] = a;
    }
}

// ---------------- generic tiled conv3x3 ----------------
// EPI: 0 plain, 1 sigmoid, 2 multiply by nearest-upsampled aux (62x62 -> HoutxWout)
// SRC: 0 -> use `in` param (harness input), else scratch buffer ID
template<int OCPB, int PAD, int EPI, int SRC, int DST>
__global__ void k_conv3x3(const float* __restrict__ in, const float* __restrict__ w,
                          int Cin, int Cout, int Hin, int Win, int Hout, int Wout,
                          int inChTot, int outChTot, int outCh0) {
    const float* src = (SRC == 0) ? in : gbuf<(SRC == 0) ? 1 : SRC>();
    float* dst = gbuf<DST>();
    __shared__ float st[2][10][34];
    __shared__ float ws[2][OCPB][9];
    int tilesX = (Wout + 31) / 32;
    int tx0 = (blockIdx.x % tilesX) * 32;
    int ty0 = (blockIdx.x / tilesX) * 8;
    int oc0 = blockIdx.y * OCPB;
    int b = blockIdx.z;
    int tid = threadIdx.x;
    int lx = tid & 31, ly = tid >> 5;
    float acc[OCPB];
#pragma unroll
    for (int i = 0; i < OCPB; i++) acc[i] = 0.f;
    for (int ci = 0; ci < Cin; ci += 2) {
        for (int i = tid; i < 2*OCPB*9; i += 256) {
            int cc = i/(OCPB*9), r = i%(OCPB*9), oc = r/9, kk = r%9;
            ws[cc][oc][kk] = (oc0+oc < Cout) ? w[((oc0+oc)*Cin + ci+cc)*9 + kk] : 0.f;
        }
        for (int i = tid; i < 680; i += 256) {
            int cc = i/340, r = i%340, iy = r/34, ix = r%34;
            int gy = ty0 - PAD + iy, gx = tx0 - PAD + ix;
            float v = 0.f;
            if (gy >= 0 && gy < Hin && gx >= 0 && gx < Win)
                v = src[((size_t)(b*inChTot + ci+cc)*Hin + gy)*Win + gx];
            st[cc][iy][ix] = v;
        }
        __syncthreads();
#pragma unroll
        for (int cc = 0; cc < 2; cc++) {
            float v0 = st[cc][ly  ][lx], v1 = st[cc][ly  ][lx+1], v2 = st[cc][ly  ][lx+2];
            float v3 = st[cc][ly+1][lx], v4 = st[cc][ly+1][lx+1], v5 = st[cc][ly+1][lx+2];
            float v6 = st[cc][ly+2][lx], v7 = st[cc][ly+2][lx+1], v8 = st[cc][ly+2][lx+2];
#pragma unroll
            for (int oc = 0; oc < OCPB; oc++) {
                acc[oc] += ws[cc][oc][0]*v0 + ws[cc][oc][1]*v1 + ws[cc][oc][2]*v2
                         + ws[cc][oc][3]*v3 + ws[cc][oc][4]*v4 + ws[cc][oc][5]*v5
                         + ws[cc][oc][6]*v6 + ws[cc][oc][7]*v7 + ws[cc][oc][8]*v8;
            }
        }
        __syncthreads();
    }
    int oy = ty0 + ly, ox = tx0 + lx;
    if (oy < Hout && ox < Wout) {
#pragma unroll
        for (int oc = 0; oc < OCPB; oc++) {
            if (oc0 + oc >= Cout) break;
            float v = acc[oc];
            if (EPI == 1) v = 1.f / (1.f + expf(-v));
            if (EPI == 2) {
                int ay = (oy * 62) >> 7, ax = (ox * 62) >> 7;
                v *= g_asmall[((size_t)(b*166 + oc0+oc)*62 + ay)*62 + ax];
            }
            dst[((size_t)(b*outChTot + outCh0 + oc0+oc)*Hout + oy)*Wout + ox] = v;
        }
    }
}

// ---------------- grouped 3x3 conv (96 ch, groups=32, in/out 3 per group) ----------------
__global__ void k_qkvd(const float* __restrict__ w) {
    __shared__ float ws[96*27];
    int tid = threadIdx.x;
    for (int i = tid; i < 96*27; i += 256) ws[i] = w[i];
    __syncthreads();
    int gid = blockIdx.x*256 + tid;          // B*32*N
    int p = gid % NN;
    int g = (gid / NN) % 32;
    int b = gid / (32*NN);
    int y = p >> 7, xx = p & 127;
    float a0 = 0.f, a1 = 0.f, a2 = 0.f;
    const float* inb = g_qkv + (size_t)(b*96 + 3*g)*NN;
#pragma unroll
    for (int ky = 0; ky < 3; ky++) {
        int gy = y - 1 + ky;
        if (gy < 0 || gy >= HH) continue;
#pragma unroll
        for (int kx = 0; kx < 3; kx++) {
            int gx = xx - 1 + kx;
            if (gx < 0 || gx >= WW) continue;
            int kk = ky*3 + kx;
#pragma unroll
            for (int ci = 0; ci < 3; ci++) {
                float v = inb[ci*NN + gy*WW + gx];
                a0 += ws[(3*g+0)*27 + ci*9 + kk]*v;
                a1 += ws[(3*g+1)*27 + ci*9 + kk]*v;
                a2 += ws[(3*g+2)*27 + ci*9 + kk]*v;
            }
        }
    }
    g_qkvd[(size_t)(b*96 + 3*g+0)*NN + p] = a0;
    g_qkvd[(size_t)(b*96 + 3*g+1)*NN + p] = a1;
    g_qkvd[(size_t)(b*96 + 3*g+2)*NN + p] = a2;
}

// ---------------- L2 norms of channel rows ----------------
// MODE 0: g_qkvd ch0..63 -> g_norms_in[0..63]
// MODE 1: x param       -> g_nf[0..31]
// MODE 2: g_prompt      -> g_nf[32..63]
// MODE 3: g_kfeat       -> g_nk[0..31]
template<int MODE>
__global__ void k_norms(const float* __restrict__ xin) {
    int numCh = (MODE == 0) ? 64 : 32;
    int b = blockIdx.x / numCh;
    int c = blockIdx.x % numCh;
    const float* pl;
    if (MODE == 0) pl = g_qkvd + (size_t)(b*96 + c)*NN;
    else if (MODE == 1) pl = xin + (size_t)(b*32 + c)*NN;
    else if (MODE == 2) pl = g_prompt + (size_t)(b*32 + c)*NN;
    else pl = g_kfeat + (size_t)(b*32 + c)*NN;
    float s = 0.f;
    for (int i = threadIdx.x; i < NN; i += 256) { float v = pl[i]; s += v*v; }
    __shared__ float red[8];
    int lane = threadIdx.x & 31, wid = threadIdx.x >> 5;
#pragma unroll
    for (int o = 16; o > 0; o >>= 1) s += __shfl_down_sync(0xffffffffu, s, o);
    if (lane == 0) red[wid] = s;
    __syncthreads();
    if (threadIdx.x == 0) {
        float t = 0.f;
        for (int i = 0; i < 8; i++) t += red[i];
        float r = sqrtf(t);
        if (MODE == 0)      g_norms_in[b*64 + c] = r;
        else if (MODE == 1) g_nf[b*64 + c] = r;
        else if (MODE == 2) g_nf[b*64 + 32 + c] = r;
        else                g_nk[b*32 + c] = r;
    }
}

// ---------------- gram matrix + per-head softmax ----------------
// MODE 0 (inner): q=g_qkvd ch0..31, k=g_qkvd ch32..63, D=4,E=4 -> g_A_in
// MODE 1 (final): q=concat(x, g_prompt), k=g_kfeat, D=8,E=4    -> g_A_f
template<int MODE, int D, int E>
__global__ void k_gram(const float* __restrict__ xin, const float* __restrict__ tempv) {
    int b = blockIdx.x / NHEADS, h = blockIdx.x % NHEADS;
    const float* qrow[D];
    const float* krow[E];
#pragma unroll
    for (int d = 0; d < D; d++) {
        int ch = h*D + d;
        if (MODE == 0) qrow[d] = g_qkvd + (size_t)(b*96 + ch)*NN;
        else qrow[d] = (ch < 32) ? xin + (size_t)(b*32 + ch)*NN
                                 : g_prompt + (size_t)(b*32 + (ch-32))*NN;
    }
#pragma unroll
    for (int e = 0; e < E; e++) {
        if (MODE == 0) krow[e] = g_qkvd + (size_t)(b*96 + 32 + h*E + e)*NN;
        else           krow[e] = g_kfeat + (size_t)(b*32 + h*E + e)*NN;
    }
    float s[D*E];
#pragma unroll
    for (int i = 0; i < D*E; i++) s[i] = 0.f;
    for (int n = threadIdx.x; n < NN; n += 256) {
        float qv[D], kv[E];
#pragma unroll
        for (int d = 0; d < D; d++) qv[d] = qrow[d][n];
#pragma unroll
        for (int e = 0; e < E; e++) kv[e] = krow[e][n];
#pragma unroll
        for (int d = 0; d < D; d++)
#pragma unroll
            for (int e = 0; e < E; e++) s[d*E+e] += qv[d]*kv[e];
    }
    __shared__ float sh[D*E];
    if (threadIdx.x < D*E) sh[threadIdx.x] = 0.f;
    __syncthreads();
    int lane = threadIdx.x & 31;
#pragma unroll
    for (int i = 0; i < D*E; i++) {
        float v = s[i];
#pragma unroll
        for (int o = 16; o > 0; o >>= 1) v += __shfl_down_sync(0xffffffffu, v, o);
        if (lane == 0) atomicAdd(&sh[i], v);
    }
    __syncthreads();
    if (threadIdx.x < D) {
        int d = threadIdx.x;
        float t = tempv[h];
        float qq, kk0;
        if (MODE == 0) qq = fmaxf(g_norms_in[b*64 + h*D + d], 1e-12f);
        else           qq = fmaxf(g_nf[b*64 + h*D + d], 1e-12f);
        float row[E];
        float mx = -1e30f;
#pragma unroll
        for (int e = 0; e < E; e++) {
            if (MODE == 0) kk0 = fmaxf(g_norms_in[b*64 + 32 + h*E + e], 1e-12f);
            else           kk0 = fmaxf(g_nk[b*32 + h*E + e], 1e-12f);
            row[e] = sh[d*E+e] / (qq*kk0) * t;
            mx = fmaxf(mx, row[e]);
        }
        float sum = 0.f;
#pragma unroll
        for (int e = 0; e < E; e++) { row[e] = expf(row[e]-mx); sum += row[e]; }
        float isum = 1.f/sum;
#pragma unroll
        for (int e = 0; e < E; e++) {
            float v = row[e]*isum;
            if (MODE == 0) g_A_in[((b*NHEADS + h)*D + d)*E + e] = v;
            else           g_A_f[((b*NHEADS + h)*D + d)*E + e] = v;
        }
    }
}

// ---------------- fold attention matrix with 1x1 conv weights ----------------
// Meff[o][h*4+e] = sum_d wmat[o, h*D+d] * A[b,h,d,e]
template<int MODE, int D>
__global__ void k_meff(const float* __restrict__ wmat) {
    int b = blockIdx.x;
    int t = threadIdx.x;                      // 1024 threads
    int o = t >> 5, vc = t & 31, h = vc >> 2, e = vc & 3;
    const float* A = (MODE == 0) ? g_A_in : g_A_f;
    float s = 0.f;
#pragma unroll
    for (int d = 0; d < D; d++)
        s += wmat[o*(8*D) + h*D + d] * A[((b*NHEADS + h)*D + d)*4 + e];
    float* M = (MODE == 0) ? g_Meff_in : g_Meff_f;
    M[b*1024 + o*32 + vc] = s;
}

// ---------------- per-pixel 32x32 matmul apply ----------------
// MODE 0: in=g_qkvd ch64..95, M=g_Meff_in, resid=x -> g_cat96p ch64..95
// MODE 1: in=x, M=g_Meff_f                          -> outp (d_out)
template<int MODE>
__global__ void k_apply(const float* __restrict__ xin, float* __restrict__ outp) {
    __shared__ float sm[1024];
    int tid = threadIdx.x;
    int gid = blockIdx.x*256 + tid;
    int b = gid / NN, p = gid % NN;
    const float* M = (MODE == 0) ? g_Meff_in : g_Meff_f;
    for (int i = tid; i < 1024; i += 256) sm[i] = M[b*1024 + i];
    __syncthreads();
    float vv[32];
#pragma unroll
    for (int c = 0; c < 32; c++) {
        if (MODE == 0) vv[c] = g_qkvd[(size_t)(b*96 + 64 + c)*NN + p];
        else           vv[c] = xin[(size_t)(b*32 + c)*NN + p];
    }
    for (int o = 0; o < 32; o++) {
        float a = (MODE == 0) ? xin[(size_t)(b*32 + o)*NN + p] : 0.f;
#pragma unroll
        for (int c = 0; c < 32; c++) a += sm[o*32+c]*vv[c];
        if (MODE == 0) g_cat96p[(size_t)(b*96 + 64 + o)*NN + p] = a;
        else           outp[(size_t)(b*32 + o)*NN + p] = a;
    }
}

// ---------------- concat x,y ----------------
__global__ void k_catxy(const float* __restrict__ x, const float* __restrict__ y) {
    int gid = blockIdx.x*256 + threadIdx.x;   // B*64*N
    int p = gid % NN;
    int c = (gid / NN) % 64;
    int b = gid / (64*NN);
    float v = (c < 32) ? x[(size_t)(b*32 + c)*NN + p] : y[(size_t)(b*32 + (c-32))*NN + p];
    g_catxy[gid] = v;
}

// ---------------- 2x2 avgpool of concat(x,y) ----------------
__global__ void k_pool(const float* __restrict__ x, const float* __restrict__ y) {
    int gid = blockIdx.x*256 + threadIdx.x;   // B*64*64*64
    int xx = gid & 63;
    int yy = (gid >> 6) & 63;
    int c  = (gid >> 12) & 63;
    int b  = gid >> 18;
    const float* src = (c < 32) ? x + (size_t)(b*32 + c)*NN : y + (size_t)(b*32 + (c-32))*NN;
    int iy = yy*2, ix = xx*2;
    float v = 0.25f*(src[iy*WW+ix] + src[iy*WW+ix+1] + src[(iy+1)*WW+ix] + src[(iy+1)*WW+ix+1]);
    g_pool[((size_t)(b*64 + c)*64 + yy)*64 + xx] = v;
}

// ---------------- deformable conv (groups=8, Cout=32) ----------------
template<int K, int PAD, int OFF0, int OUT0>
__global__ void k_deform(const float* __restrict__ x, const float* __restrict__ w,
                         const float* __restrict__ bias) {
    constexpr int K2 = K*K;
    __shared__ float ws[16*K2];
    __shared__ float bsh[4];
    int tid = threadIdx.x;
    int gid = blockIdx.x*256 + tid;           // B*8*N (N%256==0 -> g,b uniform in block)
    int p = gid % NN;
    int g = (gid / NN) & 7;
    int b = gid / (8*NN);
    for (int i = tid; i < 16*K2; i += 256) ws[i] = w[(g*4)*(4*K2) + i];
    if (tid < 4) bsh[tid] = bias[g*4 + tid];
    __syncthreads();
    int yy = p >> 7, xx = p & 127;
    float acc0 = 0.f, acc1 = 0.f, acc2 = 0.f, acc3 = 0.f;
    const float* offb = g_offs + (size_t)(b*166 + OFF0)*NN + p;
    const float* xb = x + (size_t)(b*32 + g*4)*NN;
    for (int k2 = 0; k2 < K2; k2++) {
        float dy = offb[(size_t)(2*k2)*NN];
        float dx = offb[(size_t)(2*k2+1)*NN];
        float py = (float)(yy - PAD + k2 / K) + dy;
        float px = (float)(xx - PAD + k2 % K) + dx;
        float y0f = floorf(py), x0f = floorf(px);
        float wy = py - y0f, wx = px - x0f;
        int y0 = (int)y0f, x0 = (int)x0f;
        float w00 = (1.f-wy)*(1.f-wx), w01 = (1.f-wy)*wx, w10 = wy*(1.f-wx), w11 = wy*wx;
        bool iy0 = (y0 >= 0 && y0 < HH), iy1 = (y0+1 >= 0 && y0+1 < HH);
        bool ix0 = (x0 >= 0 && x0 < WW), ix1 = (x0+1 >= 0 && x0+1 < WW);
        bool v00 = iy0 && ix0, v01 = iy0 && ix1, v10 = iy1 && ix0, v11 = iy1 && ix1;
#pragma unroll
        for (int c = 0; c < 4; c++) {
            const float* pl = xb + c*NN;
            float s = 0.f;
            if (v00) s += w00*pl[y0*WW + x0];
            if (v01) s += w01*pl[y0*WW + x0 + 1];
            if (v10) s += w10*pl[(y0+1)*WW + x0];
            if (v11) s += w11*pl[(y0+1)*WW + x0 + 1];
            acc0 += ws[(0*4+c)*K2 + k2]*s;
            acc1 += ws[(1*4+c)*K2 + k2]*s;
            acc2 += ws[(2*4+c)*K2 + k2]*s;
            acc3 += ws[(3*4+c)*K2 + k2]*s;
        }
    }
    g_catf[(size_t)(b*96 + OUT0 + g*4 + 0)*NN + p] = fmaxf(acc0 + bsh[0], 0.f);
    g_catf[(size_t)(b*96 + OUT0 + g*4 + 1)*NN + p] = fmaxf(acc1 + bsh[1], 0.f);
    g_catf[(size_t)(b*96 + OUT0 + g*4 + 2)*NN + p] = fmaxf(acc2 + bsh[2], 0.f);
    g_catf[(size_t)(b*96 + OUT0 + g*4 + 3)*NN + p] = fmaxf(acc3 + bsh[3], 0.f);
}

// ---------------- pointwise conv 96->32 with bias ----------------
__global__ void k_pw(const float* __restrict__ w, const float* __restrict__ bias) {
    __shared__ float ws[32*96];
    __shared__ float bs[32];
    int tid = threadIdx.x;
    for (int i = tid; i < 32*96; i += 256) ws[i] = w[i];
    if (tid < 32) bs[tid] = bias[tid];
    __syncthreads();
    int gid = blockIdx.x*256 + tid;
    int b = gid / NN, p = gid % NN;
    float acc[32];
#pragma unroll
    for (int o = 0; o < 32; o++) acc[o] = bs[o];
    for (int c = 0; c < 96; c++) {
        float v = g_catf[(size_t)(b*96 + c)*NN + p];
#pragma unroll
        for (int o = 0; o < 32; o++) acc[o] += ws[o*96 + c]*v;
    }
#pragma unroll
    for (int o = 0; o < 32; o++) g_kfeat[(size_t)(b*32 + o)*NN + p] = acc[o];
}

// ---------------- launch (kernel launches ONLY — nothing else) ----------------
extern "C" void kernel_launch(void* const* d_in, const int* in_sizes, int n_in,
                              void* d_out, int out_size) {
    const float* x       = (const float*)d_in[0];
    const float* y       = (const float*)d_in[1];
    const float* temp    = (const float*)d_in[2];
    const float* w_po    = (const float*)d_in[3];
    const float* w_lp1   = (const float*)d_in[4];
    const float* w_lp2   = (const float*)d_in[5];
    const float* ln_g    = (const float*)d_in[6];
    const float* ln_b    = (const float*)d_in[7];
    const float* temp_in = (const float*)d_in[8];
    const float* w_qkv   = (const float*)d_in[9];
    const float* w_qkvd  = (const float*)d_in[10];
    const float* w_mproj = (const float*)d_in[11];
    const float* w_c3    = (const float*)d_in[12];
    const float* w_k2    = (const float*)d_in[13];
    const float* w_k3    = (const float*)d_in[14];
    const float* w_k4    = (const float*)d_in[15];
    const float* w_d3    = (const float*)d_in[16];
    const float* b_d3    = (const float*)d_in[17];
    const float* w_d5    = (const float*)d_in[18];
    const float* b_d5    = (const float*)d_in[19];
    const float* w_d7    = (const float*)d_in[20];
    const float* b_d7    = (const float*)d_in[21];
    const float* w_pw    = (const float*)d_in[22];
    const float* b_pw    = (const float*)d_in[23];

    // ---- prompt branch ----
    k_ln_l1_qkv<<<(BB*NN)/256, 256>>>(x, ln_g, ln_b, w_lp1, w_qkv);
    // l2 = conv3x3(x, w_lp2) -> g_cat96p channels 32..63
    k_conv3x3<16,1,0,0,1><<<dim3(64, 2, BB), 256>>>(x, w_lp2,
        32, 32, HH, WW, HH, WW, 32, 96, 32);
    k_qkvd<<<(BB*32*NN)/256, 256>>>(w_qkvd);
    k_norms<0><<<BB*64, 256>>>(nullptr);
    k_gram<0,4,4><<<BB*NHEADS, 256>>>(nullptr, temp_in);
    k_meff<0,4><<<BB, 1024>>>(w_mproj);
    // xg = x + Meff_in @ v  -> g_cat96p channels 64..95
    k_apply<0><<<(BB*NN)/256, 256>>>(x, nullptr);
    // prompt = conv3x3(g_cat96p, w_c3)
    k_conv3x3<16,1,0,1,11><<<dim3(64, 2, BB), 256>>>(nullptr, w_c3,
        96, 32, HH, WW, HH, WW, 96, 32, 0);

    // ---- alignment branch ----
    k_catxy<<<(BB*64*NN)/256, 256>>>(x, y);
    k_pool<<<(BB*64*64*64)/256, 256>>>(x, y);
    // a = sigmoid(conv3x3(pool, w_k2, pad=0)) at 62x62
    k_conv3x3<16,0,1,5,6><<<dim3(16, 11, BB), 256>>>(nullptr, w_k2,
        64, 166, 64, 64, 62, 62, 64, 166, 0);
    // bmid = conv3x3(catxy, w_k3) * nearest_up(a)
    k_conv3x3<16,1,2,4,7><<<dim3(64, 11, BB), 256>>>(nullptr, w_k3,
        64, 166, HH, WW, HH, WW, 64, 166, 0);
    // offs = conv3x3(bmid, w_k4)
    k_conv3x3<16,1,0,7,8><<<dim3(64, 11, BB), 256>>>(nullptr, w_k4,
        166, 166, HH, WW, HH, WW, 166, 166, 0);
    // deformable convs -> g_catf
    k_deform<3,1,0,0><<<(BB*8*NN)/256, 256>>>(x, w_d3, b_d3);
    k_deform<5,2,18,32><<<(BB*8*NN)/256, 256>>>(x, w_d5, b_d5);
    k_deform<7,3,68,64><<<(BB*8*NN)/256, 256>>>(x, w_d7, b_d7);
    k_pw<<<(BB*NN)/256, 256>>>(w_pw, b_pw);

    // ---- final prompted channel attention ----
    k_norms<1><<<BB*32, 256>>>(x);
    k_norms<2><<<BB*32, 256>>>(nullptr);
    k_norms<3><<<BB*32, 256>>>(nullptr);
    k_gram<1,8,4><<<BB*NHEADS, 256>>>(x, temp);
    k_meff<1,8><<<BB, 1024>>>(w_po);
    // out = Meff_f @ x
    k_apply<1><<<(BB*NN)/256, 256>>>(x, (float*)d_out);
}

// round 3
// speedup vs baseline: 1.4033x; 1.4033x over previous
#include <cuda_runtime.h>
#include <math.h>
#include <stdint.h>

#define BB 2
#define CCH 32
#define HH 128
#define WW 128
#define NN (HH*WW)
#define NHEADS 8

// ---------------- scratch (static device globals; no allocation) ----------------
__device__ float g_cat96p[BB*96*NN];   // [l1 | l2 | xg]
__device__ float g_qkv[BB*96*NN];
__device__ float g_qkvd[BB*96*NN];     // q|k|v after grouped dwconv
__device__ float g_catxy[BB*64*NN];
__device__ float g_pool[BB*64*64*64];
__device__ float g_asmall[BB*166*62*62];
__device__ float g_bmid[BB*166*NN];
__device__ float g_offs[BB*166*NN];
__device__ float g_catf[BB*96*NN];     // [f3 | f5 | f7]
__device__ float g_kfeat[BB*CCH*NN];
__device__ float g_prompt[BB*CCH*NN];
__device__ float g_norms_in[BB*64];    // q norms (0..31), k norms (32..63)
__device__ float g_A_in[BB*NHEADS*4*4];
__device__ float g_Meff_in[BB*32*32];
__device__ float g_nf[BB*64];          // x norms (0..31), prompt norms (32..63)
__device__ float g_nk[BB*32];
__device__ float g_A_f[BB*NHEADS*8*4];
__device__ float g_Meff_f[BB*32*32];

// compile-time scratch-buffer resolution
template<int ID> __device__ __forceinline__ float* gbuf();
template<> __device__ __forceinline__ float* gbuf<1>()  { return g_cat96p; }
template<> __device__ __forceinline__ float* gbuf<4>()  { return g_catxy; }
template<> __device__ __forceinline__ float* gbuf<5>()  { return g_pool; }
template<> __device__ __forceinline__ float* gbuf<6>()  { return g_asmall; }
template<> __device__ __forceinline__ float* gbuf<7>()  { return g_bmid; }
template<> __device__ __forceinline__ float* gbuf<8>()  { return g_offs; }
template<> __device__ __forceinline__ float* gbuf<11>() { return g_prompt; }

// ---------------- tf32 helpers ----------------
__device__ __forceinline__ uint32_t f2tf32(float x) {
    uint32_t r;
    asm("cvt.rna.tf32.f32 %0, %1;" : "=r"(r) : "f"(x));
    return r;
}
__device__ __forceinline__ void mma_tf32(float* d, uint32_t a0, uint32_t a1,
                                         uint32_t a2, uint32_t a3,
                                         uint32_t b0, uint32_t b1) {
    asm volatile("mma.sync.aligned.m16n8k8.row.col.f32.tf32.tf32.f32 "
        "{%0,%1,%2,%3}, {%4,%5,%6,%7}, {%8,%9}, {%0,%1,%2,%3};\n"
        : "+f"(d[0]), "+f"(d[1]), "+f"(d[2]), "+f"(d[3])
        : "r"(a0), "r"(a1), "r"(a2), "r"(a3), "r"(b0), "r"(b1));
}

// ---------------- tensor-core conv3x3 (pad=1, H=W=128) ----------------
// Block: 256 threads = 8 warps (2 M x 4 N). Output tile: 32 oc x 128 px (one row).
// K-loop: ci chunks of 8, 9 shifted GEMMs per chunk via mma.m16n8k8 tf32.
// EPI: 0 plain, 2 multiply by nearest-upsampled sigmoid aux (g_asmall, 62x62)
template<int CIN, int COUT, int EPI, int SRC, int DST, int OUTCH0, int OUTCHTOT>
__global__ void k_conv3x3_tc(const float* __restrict__ inp, const float* __restrict__ w) {
    const float* src = (SRC == 0) ? inp : gbuf<(SRC == 0) ? 1 : SRC>();
    float* dst = gbuf<DST>();
    __shared__ float sIn[8*3*132];           // [ci][row(3)][px 132: 0->gx=-1, 129->gx=128]
    __shared__ float sW[8*9*33];             // [(ci*9+k)*33 + oc]
    const int y   = blockIdx.x;              // output row
    const int oc0 = blockIdx.y * 32;
    const int b   = blockIdx.z;
    const int tid = threadIdx.x;
    const int lane = tid & 31, wid5 = tid >> 5;
    const int wm = wid5 >> 2, wn = wid5 & 3; // warp M (0-1), warp N (0-3)
    const int g = lane >> 2, tg = lane & 3;  // groupID, threadID_in_group

    float acc[4][4];
#pragma unroll
    for (int t = 0; t < 4; t++)
#pragma unroll
        for (int r = 0; r < 4; r++) acc[t][r] = 0.f;

    const int NCHUNK = (CIN + 7) / 8;
    for (int ch = 0; ch < NCHUNK; ch++) {
        const int cibase = ch * 8;
        // ---- fill input tile (rows y-1..y+1, px -1..128, zero pad) ----
        for (int i = tid; i < 8*3*132; i += 256) {
            int ci = i / 396; int r = i % 396; int row = r / 132; int px = r % 132;
            int gy = y + row - 1, gx = px - 1;
            int c = cibase + ci;
            float v = 0.f;
            if (c < CIN && gy >= 0 && gy < HH && gx >= 0 && gx < WW && px < 130)
                v = src[((size_t)(b*CIN + c)*HH + gy)*WW + gx];
            sIn[i] = v;
        }
        // ---- fill weights (zero-padded past COUT / CIN) ----
        for (int i = tid; i < 8*9*32; i += 256) {
            int ci = i / 288; int r = i % 288; int k = r >> 5; int oc = r & 31;
            int ocg = oc0 + oc, c = cibase + ci;
            float v = 0.f;
            if (ocg < COUT && c < CIN) v = w[((size_t)ocg*CIN + c)*9 + k];
            sW[(ci*9 + k)*33 + oc] = v;
        }
        __syncthreads();
        // ---- 9 shifted GEMMs ----
#pragma unroll
        for (int kpos = 0; kpos < 9; kpos++) {
            const int ky = kpos / 3, kx = kpos % 3;
            const int aoc = wm*16 + g;
            uint32_t a0 = f2tf32(sW[(tg*9 + kpos)*33 + aoc]);
            uint32_t a1 = f2tf32(sW[(tg*9 + kpos)*33 + aoc + 8]);
            uint32_t a2 = f2tf32(sW[((tg+4)*9 + kpos)*33 + aoc]);
            uint32_t a3 = f2tf32(sW[((tg+4)*9 + kpos)*33 + aoc + 8]);
#pragma unroll
            for (int t = 0; t < 4; t++) {
                int px = wn*32 + t*8 + g;      // output pixel (B col)
                uint32_t b0 = f2tf32(sIn[(tg*3 + ky)*132 + px + kx]);
                uint32_t b1 = f2tf32(sIn[((tg+4)*3 + ky)*132 + px + kx]);
                mma_tf32(acc[t], a0, a1, a2, a3, b0, b1);
            }
        }
        __syncthreads();
    }
    // ---- store ----
    const int ocr0 = oc0 + wm*16 + g;        // rows for c0/c1; +8 for c2/c3
    const int ay = (y * 62) >> 7;
#pragma unroll
    for (int t = 0; t < 4; t++) {
        int px = wn*32 + t*8 + 2*tg;
#pragma unroll
        for (int half = 0; half < 2; half++) {
            int ocr = ocr0 + half*8;
            if (ocr >= COUT) continue;
            float v0 = acc[t][half*2 + 0];
            float v1 = acc[t][half*2 + 1];
            if (EPI == 2) {
                int ax0 = (px * 62) >> 7, ax1 = ((px+1) * 62) >> 7;
                const float* ap = g_asmall + ((size_t)(b*166 + ocr)*62 + ay)*62;
                v0 *= ap[ax0];
                v1 *= ap[ax1];
            }
            float* op = dst + ((size_t)(b*OUTCHTOT + OUTCH0 + ocr)*HH + y)*WW;
            op[px]   = v0;
            op[px+1] = v1;
        }
    }
}

// ---------------- fused LayerNorm + l1 (1x1) + qkv (1x1) ----------------
__global__ void k_ln_l1_qkv(const float* __restrict__ x, const float* __restrict__ ln_g,
                            const float* __restrict__ ln_b, const float* __restrict__ w_lp1,
                            const float* __restrict__ w_qkv) {
    __shared__ float s_w1[32*32];
    __shared__ float s_wq[96*32];
    __shared__ float s_g[32], s_b[32];
    int tid = threadIdx.x;
    for (int i = tid; i < 32*32; i += 256) s_w1[i] = w_lp1[i];
    for (int i = tid; i < 96*32; i += 256) s_wq[i] = w_qkv[i];
    if (tid < 32) { s_g[tid] = ln_g[tid]; s_b[tid] = ln_b[tid]; }
    __syncthreads();
    int gid = blockIdx.x*256 + tid;
    int b = gid / NN, p = gid % NN;
    float xv[32];
#pragma unroll
    for (int c = 0; c < 32; c++) xv[c] = x[(b*32 + c)*NN + p];
    float mu = 0.f;
#pragma unroll
    for (int c = 0; c < 32; c++) mu += xv[c];
    mu *= (1.f/32.f);
    float var = 0.f;
#pragma unroll
    for (int c = 0; c < 32; c++) { float d = xv[c]-mu; var += d*d; }
    var *= (1.f/32.f);
    float inv = rsqrtf(var + 1e-5f);
    float xn[32];
#pragma unroll
    for (int c = 0; c < 32; c++) xn[c] = (xv[c]-mu)*inv*s_g[c] + s_b[c];
    for (int o = 0; o < 32; o++) {
        float a = 0.f;
#pragma unroll
        for (int c = 0; c < 32; c++) a += s_w1[o*32+c]*xv[c];
        g_cat96p[(b*96 + o)*NN + p] = a;
    }
    for (int o = 0; o < 96; o++) {
        float a = 0.f;
#pragma unroll
        for (int c = 0; c < 32; c++) a += s_wq[o*32+c]*xn[c];
        g_qkv[(b*96 + o)*NN + p] = a;
    }
}

// ---------------- direct tiled conv3x3 (kept for the small 64x64 k2 conv) ----------------
// EPI: 0 plain, 1 sigmoid
template<int OCPB, int PAD, int EPI, int SRC, int DST>
__global__ void k_conv3x3(const float* __restrict__ in, const float* __restrict__ w,
                          int Cin, int Cout, int Hin, int Win, int Hout, int Wout,
                          int inChTot, int outChTot, int outCh0) {
    const float* src = (SRC == 0) ? in : gbuf<(SRC == 0) ? 1 : SRC>();
    float* dst = gbuf<DST>();
    __shared__ float st[2][10][34];
    __shared__ float ws[2][OCPB][9];
    int tilesX = (Wout + 31) / 32;
    int tx0 = (blockIdx.x % tilesX) * 32;
    int ty0 = (blockIdx.x / tilesX) * 8;
    int oc0 = blockIdx.y * OCPB;
    int b = blockIdx.z;
    int tid = threadIdx.x;
    int lx = tid & 31, ly = tid >> 5;
    float acc[OCPB];
#pragma unroll
    for (int i = 0; i < OCPB; i++) acc[i] = 0.f;
    for (int ci = 0; ci < Cin; ci += 2) {
        for (int i = tid; i < 2*OCPB*9; i += 256) {
            int cc = i/(OCPB*9), r = i%(OCPB*9), oc = r/9, kk = r%9;
            ws[cc][oc][kk] = (oc0+oc < Cout) ? w[((oc0+oc)*Cin + ci+cc)*9 + kk] : 0.f;
        }
        for (int i = tid; i < 680; i += 256) {
            int cc = i/340, r = i%340, iy = r/34, ix = r%34;
            int gy = ty0 - PAD + iy, gx = tx0 - PAD + ix;
            float v = 0.f;
            if (gy >= 0 && gy < Hin && gx >= 0 && gx < Win)
                v = src[((size_t)(b*inChTot + ci+cc)*Hin + gy)*Win + gx];
            st[cc][iy][ix] = v;
        }
        __syncthreads();
#pragma unroll
        for (int cc = 0; cc < 2; cc++) {
            float v0 = st[cc][ly  ][lx], v1 = st[cc][ly  ][lx+1], v2 = st[cc][ly  ][lx+2];
            float v3 = st[cc][ly+1][lx], v4 = st[cc][ly+1][lx+1], v5 = st[cc][ly+1][lx+2];
            float v6 = st[cc][ly+2][lx], v7 = st[cc][ly+2][lx+1], v8 = st[cc][ly+2][lx+2];
#pragma unroll
            for (int oc = 0; oc < OCPB; oc++) {
                acc[oc] += ws[cc][oc][0]*v0 + ws[cc][oc][1]*v1 + ws[cc][oc][2]*v2
                         + ws[cc][oc][3]*v3 + ws[cc][oc][4]*v4 + ws[cc][oc][5]*v5
                         + ws[cc][oc][6]*v6 + ws[cc][oc][7]*v7 + ws[cc][oc][8]*v8;
            }
        }
        __syncthreads();
    }
    int oy = ty0 + ly, ox = tx0 + lx;
    if (oy < Hout && ox < Wout) {
#pragma unroll
        for (int oc = 0; oc < OCPB; oc++) {
            if (oc0 + oc >= Cout) break;
            float v = acc[oc];
            if (EPI == 1) v = 1.f / (1.f + expf(-v));
            dst[((size_t)(b*outChTot + outCh0 + oc0+oc)*Hout + oy)*Wout + ox] = v;
        }
    }
}

// ---------------- grouped 3x3 conv (96 ch, groups=32, in/out 3 per group) ----------------
__global__ void k_qkvd(const float* __restrict__ w) {
    __shared__ float ws[96*27];
    int tid = threadIdx.x;
    for (int i = tid; i < 96*27; i += 256) ws[i] = w[i];
    __syncthreads();
    int gid = blockIdx.x*256 + tid;
    int p = gid % NN;
    int g = (gid / NN) % 32;
    int b = gid / (32*NN);
    int y = p >> 7, xx = p & 127;
    float a0 = 0.f, a1 = 0.f, a2 = 0.f;
    const float* inb = g_qkv + (size_t)(b*96 + 3*g)*NN;
#pragma unroll
    for (int ky = 0; ky < 3; ky++) {
        int gy = y - 1 + ky;
        if (gy < 0 || gy >= HH) continue;
#pragma unroll
        for (int kx = 0; kx < 3; kx++) {
            int gx = xx - 1 + kx;
            if (gx < 0 || gx >= WW) continue;
            int kk = ky*3 + kx;
#pragma unroll
            for (int ci = 0; ci < 3; ci++) {
                float v = inb[ci*NN + gy*WW + gx];
                a0 += ws[(3*g+0)*27 + ci*9 + kk]*v;
                a1 += ws[(3*g+1)*27 + ci*9 + kk]*v;
                a2 += ws[(3*g+2)*27 + ci*9 + kk]*v;
            }
        }
    }
    g_qkvd[(size_t)(b*96 + 3*g+0)*NN + p] = a0;
    g_qkvd[(size_t)(b*96 + 3*g+1)*NN + p] = a1;
    g_qkvd[(size_t)(b*96 + 3*g+2)*NN + p] = a2;
}

// ---------------- L2 norms of channel rows ----------------
template<int MODE>
__global__ void k_norms(const float* __restrict__ xin) {
    int numCh = (MODE == 0) ? 64 : 32;
    int b = blockIdx.x / numCh;
    int c = blockIdx.x % numCh;
    const float* pl;
    if (MODE == 0) pl = g_qkvd + (size_t)(b*96 + c)*NN;
    else if (MODE == 1) pl = xin + (size_t)(b*32 + c)*NN;
    else if (MODE == 2) pl = g_prompt + (size_t)(b*32 + c)*NN;
    else pl = g_kfeat + (size_t)(b*32 + c)*NN;
    float s = 0.f;
    for (int i = threadIdx.x; i < NN; i += 256) { float v = pl[i]; s += v*v; }
    __shared__ float red[8];
    int lane = threadIdx.x & 31, wid = threadIdx.x >> 5;
#pragma unroll
    for (int o = 16; o > 0; o >>= 1) s += __shfl_down_sync(0xffffffffu, s, o);
    if (lane == 0) red[wid] = s;
    __syncthreads();
    if (threadIdx.x == 0) {
        float t = 0.f;
        for (int i = 0; i < 8; i++) t += red[i];
        float r = sqrtf(t);
        if (MODE == 0)      g_norms_in[b*64 + c] = r;
        else if (MODE == 1) g_nf[b*64 + c] = r;
        else if (MODE == 2) g_nf[b*64 + 32 + c] = r;
        else                g_nk[b*32 + c] = r;
    }
}

// ---------------- gram matrix + per-head softmax ----------------
template<int MODE, int D, int E>
__global__ void k_gram(const float* __restrict__ xin, const float* __restrict__ tempv) {
    int b = blockIdx.x / NHEADS, h = blockIdx.x % NHEADS;
    const float* qrow[D];
    const float* krow[E];
#pragma unroll
    for (int d = 0; d < D; d++) {
        int ch = h*D + d;
        if (MODE == 0) qrow[d] = g_qkvd + (size_t)(b*96 + ch)*NN;
        else qrow[d] = (ch < 32) ? xin + (size_t)(b*32 + ch)*NN
                                 : g_prompt + (size_t)(b*32 + (ch-32))*NN;
    }
#pragma unroll
    for (int e = 0; e < E; e++) {
        if (MODE == 0) krow[e] = g_qkvd + (size_t)(b*96 + 32 + h*E + e)*NN;
        else           krow[e] = g_kfeat + (size_t)(b*32 + h*E + e)*NN;
    }
    float s[D*E];
#pragma unroll
    for (int i = 0; i < D*E; i++) s[i] = 0.f;
    for (int n = threadIdx.x; n < NN; n += 256) {
        float qv[D], kv[E];
#pragma unroll
        for (int d = 0; d < D; d++) qv[d] = qrow[d][n];
#pragma unroll
        for (int e = 0; e < E; e++) kv[e] = krow[e][n];
#pragma unroll
        for (int d = 0; d < D; d++)
#pragma unroll
            for (int e = 0; e < E; e++) s[d*E+e] += qv[d]*kv[e];
    }
    __shared__ float sh[D*E];
    if (threadIdx.x < D*E) sh[threadIdx.x] = 0.f;
    __syncthreads();
    int lane = threadIdx.x & 31;
#pragma unroll
    for (int i = 0; i < D*E; i++) {
        float v = s[i];
#pragma unroll
        for (int o = 16; o > 0; o >>= 1) v += __shfl_down_sync(0xffffffffu, v, o);
        if (lane == 0) atomicAdd(&sh[i], v);
    }
    __syncthreads();
    if (threadIdx.x < D) {
        int d = threadIdx.x;
        float t = tempv[h];
        float qq, kk0;
        if (MODE == 0) qq = fmaxf(g_norms_in[b*64 + h*D + d], 1e-12f);
        else           qq = fmaxf(g_nf[b*64 + h*D + d], 1e-12f);
        float row[E];
        float mx = -1e30f;
#pragma unroll
        for (int e = 0; e < E; e++) {
            if (MODE == 0) kk0 = fmaxf(g_norms_in[b*64 + 32 + h*E + e], 1e-12f);
            else           kk0 = fmaxf(g_nk[b*32 + h*E + e], 1e-12f);
            row[e] = sh[d*E+e] / (qq*kk0) * t;
            mx = fmaxf(mx, row[e]);
        }
        float sum = 0.f;
#pragma unroll
        for (int e = 0; e < E; e++) { row[e] = expf(row[e]-mx); sum += row[e]; }
        float isum = 1.f/sum;
#pragma unroll
        for (int e = 0; e < E; e++) {
            float v = row[e]*isum;
            if (MODE == 0) g_A_in[((b*NHEADS + h)*D + d)*E + e] = v;
            else           g_A_f[((b*NHEADS + h)*D + d)*E + e] = v;
        }
    }
}

// ---------------- fold attention matrix with 1x1 conv weights ----------------
template<int MODE, int D>
__global__ void k_meff(const float* __restrict__ wmat) {
    int b = blockIdx.x;
    int t = threadIdx.x;
    int o = t >> 5, vc = t & 31, h = vc >> 2, e = vc & 3;
    const float* A = (MODE == 0) ? g_A_in : g_A_f;
    float s = 0.f;
#pragma unroll
    for (int d = 0; d < D; d++)
        s += wmat[o*(8*D) + h*D + d] * A[((b*NHEADS + h)*D + d)*4 + e];
    float* M = (MODE == 0) ? g_Meff_in : g_Meff_f;
    M[b*1024 + o*32 + vc] = s;
}

// ---------------- per-pixel 32x32 matmul apply ----------------
template<int MODE>
__global__ void k_apply(const float* __restrict__ xin, float* __restrict__ outp) {
    __shared__ float sm[1024];
    int tid = threadIdx.x;
    int gid = blockIdx.x*256 + tid;
    int b = gid / NN, p = gid % NN;
    const float* M = (MODE == 0) ? g_Meff_in : g_Meff_f;
    for (int i = tid; i < 1024; i += 256) sm[i] = M[b*1024 + i];
    __syncthreads();
    float vv[32];
#pragma unroll
    for (int c = 0; c < 32; c++) {
        if (MODE == 0) vv[c] = g_qkvd[(size_t)(b*96 + 64 + c)*NN + p];
        else           vv[c] = xin[(size_t)(b*32 + c)*NN + p];
    }
    for (int o = 0; o < 32; o++) {
        float a = (MODE == 0) ? xin[(size_t)(b*32 + o)*NN + p] : 0.f;
#pragma unroll
        for (int c = 0; c < 32; c++) a += sm[o*32+c]*vv[c];
        if (MODE == 0) g_cat96p[(size_t)(b*96 + 64 + o)*NN + p] = a;
        else           outp[(size_t)(b*32 + o)*NN + p] = a;
    }
}

// ---------------- concat x,y ----------------
__global__ void k_catxy(const float* __restrict__ x, const float* __restrict__ y) {
    int gid = blockIdx.x*256 + threadIdx.x;
    int p = gid % NN;
    int c = (gid / NN) % 64;
    int b = gid / (64*NN);
    float v = (c < 32) ? x[(size_t)(b*32 + c)*NN + p] : y[(size_t)(b*32 + (c-32))*NN + p];
    g_catxy[gid] = v;
}

// ---------------- 2x2 avgpool of concat(x,y) ----------------
__global__ void k_pool(const float* __restrict__ x, const float* __restrict__ y) {
    int gid = blockIdx.x*256 + threadIdx.x;
    int xx = gid & 63;
    int yy = (gid >> 6) & 63;
    int c  = (gid >> 12) & 63;
    int b  = gid >> 18;
    const float* src = (c < 32) ? x + (size_t)(b*32 + c)*NN : y + (size_t)(b*32 + (c-32))*NN;
    int iy = yy*2, ix = xx*2;
    float v = 0.25f*(src[iy*WW+ix] + src[iy*WW+ix+1] + src[(iy+1)*WW+ix] + src[(iy+1)*WW+ix+1]);
    g_pool[((size_t)(b*64 + c)*64 + yy)*64 + xx] = v;
}

// ---------------- deformable conv (groups=8, Cout=32) ----------------
template<int K, int PAD, int OFF0, int OUT0>
__global__ void k_deform(const float* __restrict__ x, const float* __restrict__ w,
                         const float* __restrict__ bias) {
    constexpr int K2 = K*K;
    __shared__ float ws[16*K2];
    __shared__ float bsh[4];
    int tid = threadIdx.x;
    int gid = blockIdx.x*256 + tid;
    int p = gid % NN;
    int g = (gid / NN) & 7;
    int b = gid / (8*NN);
    for (int i = tid; i < 16*K2; i += 256) ws[i] = w[(g*4)*(4*K2) + i];
    if (tid < 4) bsh[tid] = bias[g*4 + tid];
    __syncthreads();
    int yy = p >> 7, xx = p & 127;
    float acc0 = 0.f, acc1 = 0.f, acc2 = 0.f, acc3 = 0.f;
    const float* offb = g_offs + (size_t)(b*166 + OFF0)*NN + p;
    const float* xb = x + (size_t)(b*32 + g*4)*NN;
    for (int k2 = 0; k2 < K2; k2++) {
        float dy = offb[(size_t)(2*k2)*NN];
        float dx = offb[(size_t)(2*k2+1)*NN];
        float py = (float)(yy - PAD + k2 / K) + dy;
        float px = (float)(xx - PAD + k2 % K) + dx;
        float y0f = floorf(py), x0f = floorf(px);
        float wy = py - y0f, wx = px - x0f;
        int y0 = (int)y0f, x0 = (int)x0f;
        float w00 = (1.f-wy)*(1.f-wx), w01 = (1.f-wy)*wx, w10 = wy*(1.f-wx), w11 = wy*wx;
        bool iy0 = (y0 >= 0 && y0 < HH), iy1 = (y0+1 >= 0 && y0+1 < HH);
        bool ix0 = (x0 >= 0 && x0 < WW), ix1 = (x0+1 >= 0 && x0+1 < WW);
        bool v00 = iy0 && ix0, v01 = iy0 && ix1, v10 = iy1 && ix0, v11 = iy1 && ix1;
#pragma unroll
        for (int c = 0; c < 4; c++) {
            const float* pl = xb + c*NN;
            float s = 0.f;
            if (v00) s += w00*pl[y0*WW + x0];
            if (v01) s += w01*pl[y0*WW + x0 + 1];
            if (v10) s += w10*pl[(y0+1)*WW + x0];
            if (v11) s += w11*pl[(y0+1)*WW + x0 + 1];
            acc0 += ws[(0*4+c)*K2 + k2]*s;
            acc1 += ws[(1*4+c)*K2 + k2]*s;
            acc2 += ws[(2*4+c)*K2 + k2]*s;
            acc3 += ws[(3*4+c)*K2 + k2]*s;
        }
    }
    g_catf[(size_t)(b*96 + OUT0 + g*4 + 0)*NN + p] = fmaxf(acc0 + bsh[0], 0.f);
    g_catf[(size_t)(b*96 + OUT0 + g*4 + 1)*NN + p] = fmaxf(acc1 + bsh[1], 0.f);
    g_catf[(size_t)(b*96 + OUT0 + g*4 + 2)*NN + p] = fmaxf(acc2 + bsh[2], 0.f);
    g_catf[(size_t)(b*96 + OUT0 + g*4 + 3)*NN + p] = fmaxf(acc3 + bsh[3], 0.f);
}

// ---------------- pointwise conv 96->32 with bias ----------------
__global__ void k_pw(const float* __restrict__ w, const float* __restrict__ bias) {
    __shared__ float ws[32*96];
    __shared__ float bs[32];
    int tid = threadIdx.x;
    for (int i = tid; i < 32*96; i += 256) ws[i] = w[i];
    if (tid < 32) bs[tid] = bias[tid];
    __syncthreads();
    int gid = blockIdx.x*256 + tid;
    int b = gid / NN, p = gid % NN;
    float acc[32];
#pragma unroll
    for (int o = 0; o < 32; o++) acc[o] = bs[o];
    for (int c = 0; c < 96; c++) {
        float v = g_catf[(size_t)(b*96 + c)*NN + p];
#pragma unroll
        for (int o = 0; o < 32; o++) acc[o] += ws[o*96 + c]*v;
    }
#pragma unroll
    for (int o = 0; o < 32; o++) g_kfeat[(size_t)(b*32 + o)*NN + p] = acc[o];
}

// ---------------- launch (kernel launches ONLY) ----------------
extern "C" void kernel_launch(void* const* d_in, const int* in_sizes, int n_in,
                              void* d_out, int out_size) {
    const float* x       = (const float*)d_in[0];
    const float* y       = (const float*)d_in[1];
    const float* temp    = (const float*)d_in[2];
    const float* w_po    = (const float*)d_in[3];
    const float* w_lp1   = (const float*)d_in[4];
    const float* w_lp2   = (const float*)d_in[5];
    const float* ln_g    = (const float*)d_in[6];
    const float* ln_b    = (const float*)d_in[7];
    const float* temp_in = (const float*)d_in[8];
    const float* w_qkv   = (const float*)d_in[9];
    const float* w_qkvd  = (const float*)d_in[10];
    const float* w_mproj = (const float*)d_in[11];
    const float* w_c3    = (const float*)d_in[12];
    const float* w_k2    = (const float*)d_in[13];
    const float* w_k3    = (const float*)d_in[14];
    const float* w_k4    = (const float*)d_in[15];
    const float* w_d3    = (const float*)d_in[16];
    const float* b_d3    = (const float*)d_in[17];
    const float* w_d5    = (const float*)d_in[18];
    const float* b_d5    = (const float*)d_in[19];
    const float* w_d7    = (const float*)d_in[20];
    const float* b_d7    = (const float*)d_in[21];
    const float* w_pw    = (const float*)d_in[22];
    const float* b_pw    = (const float*)d_in[23];

    // ---- prompt branch ----
    k_ln_l1_qkv<<<(BB*NN)/256, 256>>>(x, ln_g, ln_b, w_lp1, w_qkv);
    // l2 = conv3x3(x, w_lp2) -> g_cat96p channels 32..63  (tensor-core)
    k_conv3x3_tc<32,32,0,0,1,32,96><<<dim3(HH, 1, BB), 256>>>(x, w_lp2);
    k_qkvd<<<(BB*32*NN)/256, 256>>>(w_qkvd);
    k_norms<0><<<BB*64, 256>>>(nullptr);
    k_gram<0,4,4><<<BB*NHEADS, 256>>>(nullptr, temp_in);
    k_meff<0,4><<<BB, 1024>>>(w_mproj);
    // xg = x + Meff_in @ v  -> g_cat96p channels 64..95
    k_apply<0><<<(BB*NN)/256, 256>>>(x, nullptr);
    // prompt = conv3x3(g_cat96p, w_c3)  (tensor-core)
    k_conv3x3_tc<96,32,0,1,11,0,32><<<dim3(HH, 1, BB), 256>>>(nullptr, w_c3);

    // ---- alignment branch ----
    k_catxy<<<(BB*64*NN)/256, 256>>>(x, y);
    k_pool<<<(BB*64*64*64)/256, 256>>>(x, y);
    // a = sigmoid(conv3x3(pool, w_k2, pad=0)) at 62x62  (direct, small)
    k_conv3x3<16,0,1,5,6><<<dim3(16, 11, BB), 256>>>(nullptr, w_k2,
        64, 166, 64, 64, 62, 62, 64, 166, 0);
    // bmid = conv3x3(catxy, w_k3) * nearest_up(a)  (tensor-core, EPI=2)
    k_conv3x3_tc<64,166,2,4,7,0,166><<<dim3(HH, 6, BB), 256>>>(nullptr, w_k3);
    // offs = conv3x3(bmid, w_k4)  (tensor-core)
    k_conv3x3_tc<166,166,0,7,8,0,166><<<dim3(HH, 6, BB), 256>>>(nullptr, w_k4);
    // deformable convs -> g_catf
    k_deform<3,1,0,0><<<(BB*8*NN)/256, 256>>>(x, w_d3, b_d3);
    k_deform<5,2,18,32><<<(BB*8*NN)/256, 256>>>(x, w_d5, b_d5);
    k_deform<7,3,68,64><<<(BB*8*NN)/256, 256>>>(x, w_d7, b_d7);
    k_pw<<<(BB*NN)/256, 256>>>(w_pw, b_pw);

    // ---- final prompted channel attention ----
    k_norms<1><<<BB*32, 256>>>(x);
    k_norms<2><<<BB*32, 256>>>(nullptr);
    k_norms<3><<<BB*32, 256>>>(nullptr);
    k_gram<1,8,4><<<BB*NHEADS, 256>>>(x, temp);
    k_meff<1,8><<<BB, 1024>>>(w_po);
    // out = Meff_f @ x
    k_apply<1><<<(BB*NN)/256, 256>>>(x, (float*)d_out);
}

// round 4
// speedup vs baseline: 1.4095x; 1.0044x over previous
#include <cuda_runtime.h>
#include <math.h>
#include <stdint.h>

#define BB 2
#define CCH 32
#define HH 128
#define WW 128
#define NN (HH*WW)
#define NHEADS 8

// ---------------- scratch (static device globals; no allocation) ----------------
__device__ float g_cat96p[BB*96*NN];   // [l1 | l2 | xg]
__device__ float g_qkv[BB*96*NN];
__device__ float g_qkvd[BB*96*NN];     // q|k|v after grouped dwconv
__device__ float g_pool[BB*64*64*64];
__device__ float g_asmall[BB*166*62*62];
__device__ float g_bmid[BB*166*NN];
__device__ float g_offs[BB*166*NN];
__device__ float g_catf[BB*96*NN];     // [f3 | f5 | f7]
__device__ float g_kfeat[BB*CCH*NN];
__device__ float g_prompt[BB*CCH*NN];
__device__ float4 g_xnhwc4[BB*NN*8];   // x in NHWC, float4-grouped (16B aligned)
__device__ float g_stage_in[BB*8*24];  // dots[16] | q2[4] | k2[4]
__device__ float g_stage_f[BB*8*44];   // dots[32] | q2[8] | k2[4]
__device__ float g_Meff_in[BB*32*32];
__device__ float g_Meff_f[BB*32*32];

// compile-time scratch-buffer resolution
template<int ID> __device__ __forceinline__ float* gbuf();
template<> __device__ __forceinline__ float* gbuf<1>()  { return g_cat96p; }
template<> __device__ __forceinline__ float* gbuf<5>()  { return g_pool; }
template<> __device__ __forceinline__ float* gbuf<6>()  { return g_asmall; }
template<> __device__ __forceinline__ float* gbuf<7>()  { return g_bmid; }
template<> __device__ __forceinline__ float* gbuf<8>()  { return g_offs; }
template<> __device__ __forceinline__ float* gbuf<11>() { return g_prompt; }

// ---------------- tf32 helpers ----------------
__device__ __forceinline__ uint32_t f2tf32(float x) {
    uint32_t r;
    asm("cvt.rna.tf32.f32 %0, %1;" : "=r"(r) : "f"(x));
    return r;
}
__device__ __forceinline__ void mma_tf32(float* d, uint32_t a0, uint32_t a1,
                                         uint32_t a2, uint32_t a3,
                                         uint32_t b0, uint32_t b1) {
    asm volatile("mma.sync.aligned.m16n8k8.row.col.f32.tf32.tf32.f32 "
        "{%0,%1,%2,%3}, {%4,%5,%6,%7}, {%8,%9}, {%0,%1,%2,%3};\n"
        : "+f"(d[0]), "+f"(d[1]), "+f"(d[2]), "+f"(d[3])
        : "r"(a0), "r"(a1), "r"(a2), "r"(a3), "r"(b0), "r"(b1));
}

// ---------------- zero staging ----------------
__global__ void k_zero() {
    int t = threadIdx.x;
    for (int i = t; i < BB*8*24; i += 256) g_stage_in[i] = 0.f;
    for (int i = t; i < BB*8*44; i += 256) g_stage_f[i] = 0.f;
}

// ---------------- tensor-core conv3x3 (generalized geometry) ----------------
// EPI: 0 plain, 1 sigmoid, 2 multiply by nearest-upsampled sigmoid aux (g_asmall)
// SRCID: 0 -> inp param; else scratch id. CONCAT: channels 0..31 inp, 32..63 inp2.
template<int CIN, int COUT, int EPI, int SRCID, int CONCAT, int DST,
         int OUTCH0, int OUTCHTOT, int HIN, int WIN, int HOUT, int WOUT, int PAD>
__global__ void k_conv3x3_tc(const float* __restrict__ inp, const float* __restrict__ inp2,
                             const float* __restrict__ w) {
    const float* src = (SRCID == 0) ? inp : gbuf<(SRCID == 0) ? 1 : SRCID>();
    float* dst = gbuf<DST>();
    __shared__ float sIn[8*3*132];           // [ci][row(3)][px' 0..131 -> gx = px'-PAD]
    __shared__ float sW[8*9*33];             // [(ci*9+k)*33 + oc]
    const int y   = blockIdx.x;              // output row (< HOUT)
    const int oc0 = blockIdx.y * 32;
    const int b   = blockIdx.z;
    const int tid = threadIdx.x;
    const int lane = tid & 31, wid5 = tid >> 5;
    const int wm = wid5 >> 2, wn = wid5 & 3;
    const int g = lane >> 2, tg = lane & 3;

    float acc[4][4];
#pragma unroll
    for (int t = 0; t < 4; t++)
#pragma unroll
        for (int r = 0; r < 4; r++) acc[t][r] = 0.f;

    const int NCHUNK = (CIN + 7) / 8;
    for (int ch = 0; ch < NCHUNK; ch++) {
        const int cibase = ch * 8;
        for (int i = tid; i < 8*3*132; i += 256) {
            int ci = i / 396; int r = i % 396; int row = r / 132; int px = r % 132;
            int gy = y - PAD + row, gx = px - PAD;
            int c = cibase + ci;
            float v = 0.f;
            if (c < CIN && gy >= 0 && gy < HIN && gx >= 0 && gx < WIN) {
                if (CONCAT) {
                    const float* sp = (c < 32) ? inp + ((size_t)(b*32 + c)*HIN + gy)*WIN
                                               : inp2 + ((size_t)(b*32 + (c-32))*HIN + gy)*WIN;
                    v = sp[gx];
                } else {
                    v = src[((size_t)(b*CIN + c)*HIN + gy)*WIN + gx];
                }
            }
            sIn[i] = v;
        }
        for (int i = tid; i < 8*9*32; i += 256) {
            int ci = i / 288; int r = i % 288; int k = r >> 5; int oc = r & 31;
            int ocg = oc0 + oc, c = cibase + ci;
            float v = 0.f;
            if (ocg < COUT && c < CIN) v = w[((size_t)ocg*CIN + c)*9 + k];
            sW[(ci*9 + k)*33 + oc] = v;
        }
        __syncthreads();
#pragma unroll
        for (int kpos = 0; kpos < 9; kpos++) {
            const int ky = kpos / 3, kx = kpos % 3;
            const int aoc = wm*16 + g;
            uint32_t a0 = f2tf32(sW[(tg*9 + kpos)*33 + aoc]);
            uint32_t a1 = f2tf32(sW[(tg*9 + kpos)*33 + aoc + 8]);
            uint32_t a2 = f2tf32(sW[((tg+4)*9 + kpos)*33 + aoc]);
            uint32_t a3 = f2tf32(sW[((tg+4)*9 + kpos)*33 + aoc + 8]);
#pragma unroll
            for (int t = 0; t < 4; t++) {
                int px = wn*32 + t*8 + g;
                uint32_t b0 = f2tf32(sIn[(tg*3 + ky)*132 + px + kx]);
                uint32_t b1 = f2tf32(sIn[((tg+4)*3 + ky)*132 + px + kx]);
                mma_tf32(acc[t], a0, a1, a2, a3, b0, b1);
            }
        }
        __syncthreads();
    }
    const int ocr0 = oc0 + wm*16 + g;
    const int ay = (y * 62) >> 7;
#pragma unroll
    for (int t = 0; t < 4; t++) {
        int px = wn*32 + t*8 + 2*tg;
#pragma unroll
        for (int half = 0; half < 2; half++) {
            int ocr = ocr0 + half*8;
            if (ocr >= COUT) continue;
            float v0 = acc[t][half*2 + 0];
            float v1 = acc[t][half*2 + 1];
            if (EPI == 1) {
                v0 = 1.f / (1.f + expf(-v0));
                v1 = 1.f / (1.f + expf(-v1));
            }
            if (EPI == 2) {
                int ax0 = (px * 62) >> 7, ax1 = ((px+1) * 62) >> 7;
                const float* ap = g_asmall + ((size_t)(b*166 + ocr)*62 + ay)*62;
                v0 *= ap[ax0];
                v1 *= ap[ax1];
            }
            float* op = dst + ((size_t)(b*OUTCHTOT + OUTCH0 + ocr)*HOUT + y)*WOUT;
            if (px   < WOUT) op[px]   = v0;
            if (px+1 < WOUT) op[px+1] = v1;
        }
    }
}

// ---------------- fused LayerNorm + l1 + qkv (4-way channel split) ----------------
// q=0: l1 = w_lp1 @ x -> g_cat96p ch0..31 ; q=1..3: qkv rows (q-1)*32.. -> g_qkv
__global__ void k_ln_l1_qkv(const float* __restrict__ x, const float* __restrict__ ln_g,
                            const float* __restrict__ ln_b, const float* __restrict__ w_lp1,
                            const float* __restrict__ w_qkv) {
    __shared__ float sw[32*32];
    __shared__ float s_g[32], s_b[32];
    int tid = threadIdx.x;
    int gid = blockIdx.x*256 + tid;          // B*4*N
    int p = gid % NN;
    int q = (gid / NN) & 3;
    int b = gid / (4*NN);
    const float* wsrc = (q == 0) ? w_lp1 : w_qkv + (size_t)(q-1)*1024;
    for (int i = tid; i < 1024; i += 256) sw[i] = wsrc[i];
    if (tid < 32) { s_g[tid] = ln_g[tid]; s_b[tid] = ln_b[tid]; }
    __syncthreads();
    float xv[32];
#pragma unroll
    for (int c = 0; c < 32; c++) xv[c] = x[(size_t)(b*32 + c)*NN + p];
    float vin[32];
    if (q == 0) {
#pragma unroll
        for (int c = 0; c < 32; c++) vin[c] = xv[c];
    } else {
        float mu = 0.f;
#pragma unroll
        for (int c = 0; c < 32; c++) mu += xv[c];
        mu *= (1.f/32.f);
        float var = 0.f;
#pragma unroll
        for (int c = 0; c < 32; c++) { float d = xv[c]-mu; var += d*d; }
        var *= (1.f/32.f);
        float inv = rsqrtf(var + 1e-5f);
#pragma unroll
        for (int c = 0; c < 32; c++) vin[c] = (xv[c]-mu)*inv*s_g[c] + s_b[c];
    }
    float* outbase = (q == 0) ? g_cat96p + (size_t)(b*96)*NN
                              : g_qkv + (size_t)(b*96 + (q-1)*32)*NN;
    for (int o = 0; o < 32; o++) {
        float a = 0.f;
#pragma unroll
        for (int c = 0; c < 32; c++) a += sw[o*32+c]*vin[c];
        outbase[(size_t)o*NN + p] = a;
    }
}

// ---------------- grouped 3x3 conv (96 ch, groups=32, in/out 3 per group) ----------------
__global__ void k_qkvd(const float* __restrict__ w) {
    __shared__ float ws[96*27];
    int tid = threadIdx.x;
    for (int i = tid; i < 96*27; i += 256) ws[i] = w[i];
    __syncthreads();
    int gid = blockIdx.x*256 + tid;
    int p = gid % NN;
    int g = (gid / NN) % 32;
    int b = gid / (32*NN);
    int y = p >> 7, xx = p & 127;
    float a0 = 0.f, a1 = 0.f, a2 = 0.f;
    const float* inb = g_qkv + (size_t)(b*96 + 3*g)*NN;
#pragma unroll
    for (int ky = 0; ky < 3; ky++) {
        int gy = y - 1 + ky;
        if (gy < 0 || gy >= HH) continue;
#pragma unroll
        for (int kx = 0; kx < 3; kx++) {
            int gx = xx - 1 + kx;
            if (gx < 0 || gx >= WW) continue;
            int kk = ky*3 + kx;
#pragma unroll
            for (int ci = 0; ci < 3; ci++) {
                float v = inb[ci*NN + gy*WW + gx];
                a0 += ws[(3*g+0)*27 + ci*9 + kk]*v;
                a1 += ws[(3*g+1)*27 + ci*9 + kk]*v;
                a2 += ws[(3*g+2)*27 + ci*9 + kk]*v;
            }
        }
    }
    g_qkvd[(size_t)(b*96 + 3*g+0)*NN + p] = a0;
    g_qkvd[(size_t)(b*96 + 3*g+1)*NN + p] = a1;
    g_qkvd[(size_t)(b*96 + 3*g+2)*NN + p] = a2;
}

// ---------------- sliced gram accumulate (dots + squared norms) ----------------
// MODE 0: q=g_qkvd ch0..31 (D=4), k=g_qkvd ch32..63 (E=4) -> g_stage_in
// MODE 1: q=concat(x,prompt) (D=8), k=g_kfeat (E=4)       -> g_stage_f
template<int MODE>
__global__ void k_gramacc(const float* __restrict__ xin) {
    constexpr int D = (MODE == 0) ? 4 : 8;
    constexpr int E = 4;
    constexpr int NS = D*E + D + E;          // 24 or 44
    constexpr int SL = 16;
    int bid = blockIdx.x;                    // BB*8*16
    int slice = bid & 15;
    int h = (bid >> 4) & 7;
    int b = bid >> 7;
    int tid = threadIdx.x;
    const float* qbase;
    if (MODE == 0) qbase = g_qkvd + (size_t)(b*96 + h*D)*NN;
    else qbase = (h < 4) ? xin + (size_t)(b*32 + h*8)*NN
                         : g_prompt + (size_t)(b*32 + (h-4)*8)*NN;
    const float* kbase = (MODE == 0) ? g_qkvd + (size_t)(b*96 + 32 + h*E)*NN
                                     : g_kfeat + (size_t)(b*32 + h*E)*NN;
    float acc[NS];
#pragma unroll
    for (int i = 0; i < NS; i++) acc[i] = 0.f;
    int n0 = slice * (NN/SL);
    for (int it = 0; it < (NN/SL)/256; it++) {
        int n = n0 + it*256 + tid;
        float qv[D], kv[E];
#pragma unroll
        for (int d = 0; d < D; d++) qv[d] = qbase[(size_t)d*NN + n];
#pragma unroll
        for (int e = 0; e < E; e++) kv[e] = kbase[(size_t)e*NN + n];
#pragma unroll
        for (int d = 0; d < D; d++)
#pragma unroll
            for (int e = 0; e < E; e++) acc[d*E+e] += qv[d]*kv[e];
#pragma unroll
        for (int d = 0; d < D; d++) acc[D*E + d] += qv[d]*qv[d];
#pragma unroll
        for (int e = 0; e < E; e++) acc[D*E + D + e] += kv[e]*kv[e];
    }
    __shared__ float red[NS];
    if (tid < NS) red[tid] = 0.f;
    __syncthreads();
    int lane = tid & 31;
#pragma unroll
    for (int i = 0; i < NS; i++) {
        float v = acc[i];
#pragma unroll
        for (int o = 16; o > 0; o >>= 1) v += __shfl_down_sync(0xffffffffu, v, o);
        if (lane == 0) atomicAdd(&red[i], v);
    }
    __syncthreads();
    float* st = (MODE == 0) ? g_stage_in + (b*8 + h)*24 : g_stage_f + (b*8 + h)*44;
    if (tid < NS) atomicAdd(&st[tid], red[tid]);
}

// ---------------- softmax + fold with 1x1 conv weights -> Meff ----------------
template<int MODE>
__global__ void k_meffsm(const float* __restrict__ wmat, const float* __restrict__ tempv) {
    constexpr int D = (MODE == 0) ? 4 : 8;
    int b = blockIdx.x;
    int t = threadIdx.x;                     // 1024 threads
    __shared__ float sA[8*D*4];
    if (t < 8*D) {
        int h = t / D, d = t % D;
        const float* st = (MODE == 0) ? g_stage_in + (b*8 + h)*24 : g_stage_f + (b*8 + h)*44;
        float qn = fmaxf(sqrtf(st[D*4 + d]), 1e-12f);
        float tp = tempv[h];
        float row[4];
        float mx = -1e30f;
#pragma unroll
        for (int e = 0; e < 4; e++) {
            float kn = fmaxf(sqrtf(st[D*4 + D + e]), 1e-12f);
            row[e] = st[d*4+e] / (qn*kn) * tp;
            mx = fmaxf(mx, row[e]);
        }
        float sum = 0.f;
#pragma unroll
        for (int e = 0; e < 4; e++) { row[e] = expf(row[e]-mx); sum += row[e]; }
        float isum = 1.f/sum;
#pragma unroll
        for (int e = 0; e < 4; e++) sA[(h*D + d)*4 + e] = row[e]*isum;
    }
    __syncthreads();
    int o = t >> 5, vc = t & 31, h = vc >> 2, e = vc & 3;
    float s = 0.f;
#pragma unroll
    for (int d = 0; d < D; d++)
        s += wmat[o*(8*D) + h*D + d] * sA[(h*D + d)*4 + e];
    float* M = (MODE == 0) ? g_Meff_in : g_Meff_f;
    M[b*1024 + o*32 + vc] = s;
}

// ---------------- per-pixel 32x32 matmul apply (4-way channel split) ----------------
// MODE 0: in=g_qkvd ch64..95, M=g_Meff_in, resid=x -> g_cat96p ch64..95
// MODE 1: in=x, M=g_Meff_f                          -> outp
template<int MODE>
__global__ void k_apply(const float* __restrict__ xin, float* __restrict__ outp) {
    __shared__ float sm[256];
    int tid = threadIdx.x;
    int gid = blockIdx.x*256 + tid;          // B*4*N
    int p = gid % NN;
    int q = (gid / NN) & 3;
    int b = gid / (4*NN);
    const float* M = (MODE == 0) ? g_Meff_in : g_Meff_f;
    if (tid < 256) sm[tid] = M[b*1024 + q*256 + tid];
    __syncthreads();
    float vv[32];
#pragma unroll
    for (int c = 0; c < 32; c++) {
        if (MODE == 0) vv[c] = g_qkvd[(size_t)(b*96 + 64 + c)*NN + p];
        else           vv[c] = xin[(size_t)(b*32 + c)*NN + p];
    }
#pragma unroll
    for (int j = 0; j < 8; j++) {
        int o = q*8 + j;
        float a = (MODE == 0) ? xin[(size_t)(b*32 + o)*NN + p] : 0.f;
#pragma unroll
        for (int c = 0; c < 32; c++) a += sm[j*32+c]*vv[c];
        if (MODE == 0) g_cat96p[(size_t)(b*96 + 64 + o)*NN + p] = a;
        else           outp[(size_t)(b*32 + o)*NN + p] = a;
    }
}

// ---------------- 2x2 avgpool of concat(x,y) ----------------
__global__ void k_pool(const float* __restrict__ x, const float* __restrict__ y) {
    int gid = blockIdx.x*256 + threadIdx.x;
    int xx = gid & 63;
    int yy = (gid >> 6) & 63;
    int c  = (gid >> 12) & 63;
    int b  = gid >> 18;
    const float* src = (c < 32) ? x + (size_t)(b*32 + c)*NN : y + (size_t)(b*32 + (c-32))*NN;
    int iy = yy*2, ix = xx*2;
    float v = 0.25f*(src[iy*WW+ix] + src[iy*WW+ix+1] + src[(iy+1)*WW+ix] + src[(iy+1)*WW+ix+1]);
    g_pool[((size_t)(b*64 + c)*64 + yy)*64 + xx] = v;
}

// ---------------- NCHW -> NHWC(float4 groups) transpose of x ----------------
__global__ void k_nhwc(const float* __restrict__ x) {
    __shared__ float s[32][65];
    int tid = threadIdx.x;
    int blk = blockIdx.x;                    // B*NN/64
    int b = blk / (NN/64);
    int px0 = (blk % (NN/64)) * 64;
#pragma unroll
    for (int k = 0; k < 8; k++) {
        int ch = k*4 + (tid >> 6);
        int px = tid & 63;
        s[ch][px] = x[(size_t)(b*32 + ch)*NN + px0 + px];
    }
    __syncthreads();
    float* xn = (float*)g_xnhwc4;
#pragma unroll
    for (int k = 0; k < 8; k++) {
        int px = k*8 + (tid >> 5);
        int ch = tid & 31;
        xn[(size_t)(b*NN + px0 + px)*32 + ch] = s[ch][px];
    }
}

// ---------------- fused deformable convs (k=3,5,7; groups=8) ----------------
template<int K, int PAD>
__device__ __forceinline__ void deform_one(const float* __restrict__ offp,
                                           const float* __restrict__ ws,
                                           const float* __restrict__ bsh,
                                           int yy, int xx, int b, int g, int p,
                                           int out0) {
    constexpr int K2 = K*K;
    float acc0 = 0.f, acc1 = 0.f, acc2 = 0.f, acc3 = 0.f;
    const float4* xb = g_xnhwc4 + (size_t)b*NN*8 + g;
    for (int k2 = 0; k2 < K2; k2++) {
        float dy = offp[(size_t)(2*k2)*NN];
        float dx = offp[(size_t)(2*k2+1)*NN];
        float py = (float)(yy - PAD + k2 / K) + dy;
        float px = (float)(xx - PAD + k2 % K) + dx;
        float y0f = floorf(py), x0f = floorf(px);
        float wy = py - y0f, wx = px - x0f;
        int y0 = (int)y0f, x0 = (int)x0f;
        float w00 = (1.f-wy)*(1.f-wx), w01 = (1.f-wy)*wx, w10 = wy*(1.f-wx), w11 = wy*wx;
        bool iy0 = (y0 >= 0 && y0 < HH), iy1 = (y0+1 >= 0 && y0+1 < HH);
        bool ix0 = (x0 >= 0 && x0 < WW), ix1 = (x0+1 >= 0 && x0+1 < WW);
        float4 s = make_float4(0.f, 0.f, 0.f, 0.f);
        if (iy0 && ix0) {
            float4 v = xb[(size_t)(y0*WW + x0)*8];
            s.x += w00*v.x; s.y += w00*v.y; s.z += w00*v.z; s.w += w00*v.w;
        }
        if (iy0 && ix1) {
            float4 v = xb[(size_t)(y0*WW + x0 + 1)*8];
            s.x += w01*v.x; s.y += w01*v.y; s.z += w01*v.z; s.w += w01*v.w;
        }
        if (iy1 && ix0) {
            float4 v = xb[(size_t)((y0+1)*WW + x0)*8];
            s.x += w10*v.x; s.y += w10*v.y; s.z += w10*v.z; s.w += w10*v.w;
        }
        if (iy1 && ix1) {
            float4 v = xb[(size_t)((y0+1)*WW + x0 + 1)*8];
            s.x += w11*v.x; s.y += w11*v.y; s.z += w11*v.z; s.w += w11*v.w;
        }
        acc0 += ws[(0*4+0)*K2+k2]*s.x + ws[(0*4+1)*K2+k2]*s.y + ws[(0*4+2)*K2+k2]*s.z + ws[(0*4+3)*K2+k2]*s.w;
        acc1 += ws[(1*4+0)*K2+k2]*s.x + ws[(1*4+1)*K2+k2]*s.y + ws[(1*4+2)*K2+k2]*s.z + ws[(1*4+3)*K2+k2]*s.w;
        acc2 += ws[(2*4+0)*K2+k2]*s.x + ws[(2*4+1)*K2+k2]*s.y + ws[(2*4+2)*K2+k2]*s.z + ws[(2*4+3)*K2+k2]*s.w;
        acc3 += ws[(3*4+0)*K2+k2]*s.x + ws[(3*4+1)*K2+k2]*s.y + ws[(3*4+2)*K2+k2]*s.z + ws[(3*4+3)*K2+k2]*s.w;
    }
    float* ob = g_catf + (size_t)(b*96 + out0 + g*4)*NN + p;
    ob[0*NN] = fmaxf(acc0 + bsh[0], 0.f);
    ob[1*NN] = fmaxf(acc1 + bsh[1], 0.f);
    ob[2*NN] = fmaxf(acc2 + bsh[2], 0.f);
    ob[3*NN] = fmaxf(acc3 + bsh[3], 0.f);
}

__global__ void k_deform_all(const float* __restrict__ w3, const float* __restrict__ b3,
                             const float* __restrict__ w5, const float* __restrict__ b5,
                             const float* __restrict__ w7, const float* __restrict__ b7) {
    __shared__ float ws[16*83];              // [w3 144 | w5 400 | w7 784]
    __shared__ float bsh[12];
    int tid = threadIdx.x;
    int gid = blockIdx.x*256 + tid;          // B*8*N
    int p = gid % NN;
    int g = (gid / NN) & 7;
    int b = gid / (8*NN);
    for (int i = tid; i < 144; i += 256) ws[i] = w3[g*144 + i];
    for (int i = tid; i < 400; i += 256) ws[144 + i] = w5[g*400 + i];
    for (int i = tid; i < 784; i += 256) ws[544 + i] = w7[g*784 + i];
    if (tid < 4)       bsh[tid]   = b3[g*4 + tid];
    else if (tid < 8)  bsh[tid]   = b5[g*4 + tid - 4];
    else if (tid < 12) bsh[tid]   = b7[g*4 + tid - 8];
    __syncthreads();
    int yy = p >> 7, xx = p & 127;
    const float* offbase = g_offs + (size_t)(b*166)*NN + p;
    deform_one<3,1>(offbase,              ws,       bsh,     yy, xx, b, g, p, 0);
    deform_one<5,2>(offbase + (size_t)18*NN, ws+144, bsh+4,  yy, xx, b, g, p, 32);
    deform_one<7,3>(offbase + (size_t)68*NN, ws+544, bsh+8,  yy, xx, b, g, p, 64);
}

// ---------------- pointwise conv 96->32 with bias (4-way split) ----------------
__global__ void k_pw(const float* __restrict__ w, const float* __restrict__ bias) {
    __shared__ float ws[8*96];
    __shared__ float bs[8];
    int tid = threadIdx.x;
    int gid = blockIdx.x*256 + tid;          // B*4*N
    int p = gid % NN;
    int q = (gid / NN) & 3;
    int b = gid / (4*NN);
    for (int i = tid; i < 768; i += 256) ws[i] = w[(size_t)(q*8 + i/96)*96 + i%96];
    if (tid < 8) bs[tid] = bias[q*8 + tid];
    __syncthreads();
    float acc[8];
#pragma unroll
    for (int j = 0; j < 8; j++) acc[j] = bs[j];
    for (int c = 0; c < 96; c++) {
        float v = g_catf[(size_t)(b*96 + c)*NN + p];
#pragma unroll
        for (int j = 0; j < 8; j++) acc[j] += ws[j*96 + c]*v;
    }
#pragma unroll
    for (int j = 0; j < 8; j++) g_kfeat[(size_t)(b*32 + q*8 + j)*NN + p] = acc[j];
}

// ---------------- launch (kernel launches ONLY) ----------------
extern "C" void kernel_launch(void* const* d_in, const int* in_sizes, int n_in,
                              void* d_out, int out_size) {
    const float* x       = (const float*)d_in[0];
    const float* y       = (const float*)d_in[1];
    const float* temp    = (const float*)d_in[2];
    const float* w_po    = (const float*)d_in[3];
    const float* w_lp1   = (const float*)d_in[4];
    const float* w_lp2   = (const float*)d_in[5];
    const float* ln_g    = (const float*)d_in[6];
    const float* ln_b    = (const float*)d_in[7];
    const float* temp_in = (const float*)d_in[8];
    const float* w_qkv   = (const float*)d_in[9];
    const float* w_qkvd  = (const float*)d_in[10];
    const float* w_mproj = (const float*)d_in[11];
    const float* w_c3    = (const float*)d_in[12];
    const float* w_k2    = (const float*)d_in[13];
    const float* w_k3    = (const float*)d_in[14];
    const float* w_k4    = (const float*)d_in[15];
    const float* w_d3    = (const float*)d_in[16];
    const float* b_d3    = (const float*)d_in[17];
    const float* w_d5    = (const float*)d_in[18];
    const float* b_d5    = (const float*)d_in[19];
    const float* w_d7    = (const float*)d_in[20];
    const float* b_d7    = (const float*)d_in[21];
    const float* w_pw    = (const float*)d_in[22];
    const float* b_pw    = (const float*)d_in[23];

    k_zero<<<1, 256>>>();
    // ---- prompt branch ----
    k_ln_l1_qkv<<<(BB*4*NN)/256, 256>>>(x, ln_g, ln_b, w_lp1, w_qkv);
    // l2 = conv3x3(x, w_lp2) -> g_cat96p ch32..63
    k_conv3x3_tc<32,32,0, 0,0, 1,32,96, 128,128,128,128, 1>
        <<<dim3(HH, 1, BB), 256>>>(x, nullptr, w_lp2);
    k_qkvd<<<(BB*32*NN)/256, 256>>>(w_qkvd);
    k_gramacc<0><<<BB*8*16, 256>>>(x);
    k_meffsm<0><<<BB, 1024>>>(w_mproj, temp_in);
    k_apply<0><<<(BB*4*NN)/256, 256>>>(x, nullptr);
    // prompt = conv3x3(g_cat96p, w_c3)
    k_conv3x3_tc<96,32,0, 1,0, 11,0,32, 128,128,128,128, 1>
        <<<dim3(HH, 1, BB), 256>>>(nullptr, nullptr, w_c3);

    // ---- alignment branch ----
    k_pool<<<(BB*64*64*64)/256, 256>>>(x, y);
    // a = sigmoid(conv3x3(pool, w_k2, pad=0)) at 62x62
    k_conv3x3_tc<64,166,1, 5,0, 6,0,166, 64,64,62,62, 0>
        <<<dim3(62, 6, BB), 256>>>(nullptr, nullptr, w_k2);
    // bmid = conv3x3(concat(x,y), w_k3) * nearest_up(a)
    k_conv3x3_tc<64,166,2, 0,1, 7,0,166, 128,128,128,128, 1>
        <<<dim3(HH, 6, BB), 256>>>(x, y, w_k3);
    // offs = conv3x3(bmid, w_k4)
    k_conv3x3_tc<166,166,0, 7,0, 8,0,166, 128,128,128,128, 1>
        <<<dim3(HH, 6, BB), 256>>>(nullptr, nullptr, w_k4);
    k_nhwc<<<(BB*NN)/64, 256>>>(x);
    k_deform_all<<<(BB*8*NN)/256, 256>>>(w_d3, b_d3, w_d5, b_d5, w_d7, b_d7);
    k_pw<<<(BB*4*NN)/256, 256>>>(w_pw, b_pw);

    // ---- final prompted channel attention ----
    k_gramacc<1><<<BB*8*16, 256>>>(x);
    k_meffsm<1><<<BB, 1024>>>(w_po, temp);
    k_apply<1><<<(BB*4*NN)/256, 256>>>(x, (float*)d_out);
}

// round 6
// speedup vs baseline: 1.7140x; 1.2161x over previous
#include <cuda_runtime.h>
#include <math.h>
#include <stdint.h>

#define BB 2
#define CCH 32
#define HH 128
#define WW 128
#define NN (HH*WW)
#define NHEADS 8

// ---------------- scratch (static device globals; no allocation) ----------------
__device__ float g_cat96p[BB*96*NN];   // [l1 | l2 | xg]
__device__ float g_qkv[BB*96*NN];
__device__ float g_qkvd[BB*96*NN];     // q|k|v after grouped dwconv
__device__ float g_pool[BB*64*64*64];
__device__ float g_asmall[BB*166*62*62];
__device__ float g_bmid[BB*166*NN];
__device__ float g_offs[BB*166*NN];
__device__ float g_catf[BB*96*NN];     // [f3 | f5 | f7]
__device__ float g_kfeat[BB*CCH*NN];
__device__ float g_prompt[BB*CCH*NN];
__device__ float4 g_xnhwc4[BB*NN*8];   // x in NHWC, float4-grouped (16B aligned)
__device__ float g_stage_in[BB*8*24];  // dots[16] | q2[4] | k2[4]
__device__ float g_stage_f[BB*8*44];   // dots[32] | q2[8] | k2[4]
__device__ float g_Meff_in[BB*32*32];
__device__ float g_Meff_f[BB*32*32];

// compile-time scratch-buffer resolution
template<int ID> __device__ __forceinline__ float* gbuf();
template<> __device__ __forceinline__ float* gbuf<1>()  { return g_cat96p; }
template<> __device__ __forceinline__ float* gbuf<5>()  { return g_pool; }
template<> __device__ __forceinline__ float* gbuf<6>()  { return g_asmall; }
template<> __device__ __forceinline__ float* gbuf<7>()  { return g_bmid; }
template<> __device__ __forceinline__ float* gbuf<8>()  { return g_offs; }
template<> __device__ __forceinline__ float* gbuf<11>() { return g_prompt; }

// ---------------- bf16 helpers ----------------
__device__ __forceinline__ uint32_t pack_bf16x2(float lo, float hi) {
    uint32_t r;
    asm("cvt.rn.bf16x2.f32 %0, %1, %2;" : "=r"(r) : "f"(hi), "f"(lo));
    return r;
}
__device__ __forceinline__ void mma_bf16(float* d, uint32_t a0, uint32_t a1,
                                         uint32_t a2, uint32_t a3,
                                         uint32_t b0, uint32_t b1) {
    asm volatile("mma.sync.aligned.m16n8k16.row.col.f32.bf16.bf16.f32 "
        "{%0,%1,%2,%3}, {%4,%5,%6,%7}, {%8,%9}, {%0,%1,%2,%3};\n"
        : "+f"(d[0]), "+f"(d[1]), "+f"(d[2]), "+f"(d[3])
        : "r"(a0), "r"(a1), "r"(a2), "r"(a3), "r"(b0), "r"(b1));
}

// ---------------- zero staging ----------------
__global__ void k_zero() {
    int t = threadIdx.x;
    for (int i = t; i < BB*8*24; i += 256) g_stage_in[i] = 0.f;
    for (int i = t; i < BB*8*44; i += 256) g_stage_f[i] = 0.f;
}

// ---------------- tensor-core conv3x3, bf16 m16n8k16 ----------------
// smem holds bf16x2 pairs along ci; inner loop = pure LDS + mma (no cvt).
// EPI: 0 plain, 1 sigmoid, 2 multiply by nearest-upsampled sigmoid aux (g_asmall)
// SRCID: 0 -> inp param; else scratch id. CONCAT: ch 0..31 inp, 32..63 inp2.
template<int CIN, int COUT, int EPI, int SRCID, int CONCAT, int DST,
         int OUTCH0, int OUTCHTOT, int HIN, int WIN, int HOUT, int WOUT, int PAD>
__global__ void k_conv3x3_tc(const float* __restrict__ inp, const float* __restrict__ inp2,
                             const float* __restrict__ w) {
    const float* src = (SRCID == 0) ? inp : gbuf<(SRCID == 0) ? 1 : SRCID>();
    float* dst = gbuf<DST>();
    __shared__ uint32_t sIn[8*3*132];        // [cp(8 ci-pairs)][row(3)][px 0..131 -> gx=px-PAD]
    __shared__ uint32_t sW[8*9*33];          // [(cp*9+k)*33 + oc], bf16x2 over ci pair
    const int y   = blockIdx.x;              // output row (< HOUT)
    const int oc0 = blockIdx.y * 32;
    const int b   = blockIdx.z;
    const int tid = threadIdx.x;
    const int lane = tid & 31, wid5 = tid >> 5;
    const int wm = wid5 >> 2, wn = wid5 & 3;
    const int g = lane >> 2, tg = lane & 3;

    float acc[4][4];
#pragma unroll
    for (int t = 0; t < 4; t++)
#pragma unroll
        for (int r = 0; r < 4; r++) acc[t][r] = 0.f;

    const int NCHUNK = (CIN + 15) / 16;
    for (int ch = 0; ch < NCHUNK; ch++) {
        const int cibase = ch * 16;
        // ---- fill input tile as bf16x2 pairs ----
        for (int i = tid; i < 8*3*132; i += 256) {
            int cp = i / 396; int r = i % 396; int row = r / 132; int px = r % 132;
            int gy = y - PAD + row, gx = px - PAD;
            int c0 = cibase + 2*cp;
            float v0 = 0.f, v1 = 0.f;
            if (gy >= 0 && gy < HIN && gx >= 0 && gx < WIN) {
                if (CONCAT) {
                    if (c0 < CIN) {
                        const float* sp = (c0 < 32) ? inp + ((size_t)(b*32 + c0)*HIN + gy)*WIN
                                                    : inp2 + ((size_t)(b*32 + (c0-32))*HIN + gy)*WIN;
                        v0 = sp[gx];
                    }
                    if (c0+1 < CIN) {
                        int c1 = c0+1;
                        const float* sp = (c1 < 32) ? inp + ((size_t)(b*32 + c1)*HIN + gy)*WIN
                                                    : inp2 + ((size_t)(b*32 + (c1-32))*HIN + gy)*WIN;
                        v1 = sp[gx];
                    }
                } else {
                    if (c0 < CIN)   v0 = src[((size_t)(b*CIN + c0)*HIN + gy)*WIN + gx];
                    if (c0+1 < CIN) v1 = src[((size_t)(b*CIN + c0+1)*HIN + gy)*WIN + gx];
                }
            }
            sIn[i] = pack_bf16x2(v0, v1);
        }
        // ---- fill weights as bf16x2 pairs ----
        for (int i = tid; i < 8*9*32; i += 256) {
            int cp = i / 288; int r = i % 288; int k = r >> 5; int oc = r & 31;
            int ocg = oc0 + oc, c0 = cibase + 2*cp;
            float v0 = 0.f, v1 = 0.f;
            if (ocg < COUT) {
                if (c0 < CIN)   v0 = w[((size_t)ocg*CIN + c0)*9 + k];
                if (c0+1 < CIN) v1 = w[((size_t)ocg*CIN + c0+1)*9 + k];
            }
            sW[(cp*9 + k)*33 + oc] = pack_bf16x2(v0, v1);
        }
        __syncthreads();
        // ---- 9 shifted GEMMs, K=16 each ----
#pragma unroll
        for (int kpos = 0; kpos < 9; kpos++) {
            const int ky = kpos / 3, kx = kpos % 3;
            const int aoc = wm*16 + g;
            uint32_t a0 = sW[(tg*9 + kpos)*33 + aoc];
            uint32_t a1 = sW[(tg*9 + kpos)*33 + aoc + 8];
            uint32_t a2 = sW[((tg+4)*9 + kpos)*33 + aoc];
            uint32_t a3 = sW[((tg+4)*9 + kpos)*33 + aoc + 8];
#pragma unroll
            for (int t = 0; t < 4; t++) {
                int px = wn*32 + t*8 + g;
                uint32_t b0 = sIn[(tg*3 + ky)*132 + px + kx];
                uint32_t b1 = sIn[((tg+4)*3 + ky)*132 + px + kx];
                mma_bf16(acc[t], a0, a1, a2, a3, b0, b1);
            }
        }
        __syncthreads();
    }
    const int ocr0 = oc0 + wm*16 + g;
    const int ay = (y * 62) >> 7;
#pragma unroll
    for (int t = 0; t < 4; t++) {
        int px = wn*32 + t*8 + 2*tg;
#pragma unroll
        for (int half = 0; half < 2; half++) {
            int ocr = ocr0 + half*8;
            if (ocr >= COUT) continue;
            float v0 = acc[t][half*2 + 0];
            float v1 = acc[t][half*2 + 1];
            if (EPI == 1) {
                v0 = 1.f / (1.f + expf(-v0));
                v1 = 1.f / (1.f + expf(-v1));
            }
            if (EPI == 2) {
                int ax0 = (px * 62) >> 7, ax1 = ((px+1) * 62) >> 7;
                const float* ap = g_asmall + ((size_t)(b*166 + ocr)*62 + ay)*62;
                v0 *= ap[ax0];
                v1 *= ap[ax1];
            }
            float* op = dst + ((size_t)(b*OUTCHTOT + OUTCH0 + ocr)*HOUT + y)*WOUT;
            if (px   < WOUT) op[px]   = v0;
            if (px+1 < WOUT) op[px+1] = v1;
        }
    }
}

// ---------------- fused LayerNorm + l1 + qkv (4-way channel split) ----------------
__global__ void k_ln_l1_qkv(const float* __restrict__ x, const float* __restrict__ ln_g,
                            const float* __restrict__ ln_b, const float* __restrict__ w_lp1,
                            const float* __restrict__ w_qkv) {
    __shared__ float sw[32*32];
    __shared__ float s_g[32], s_b[32];
    int tid = threadIdx.x;
    int gid = blockIdx.x*256 + tid;          // B*4*N
    int p = gid % NN;
    int q = (gid / NN) & 3;
    int b = gid / (4*NN);
    const float* wsrc = (q == 0) ? w_lp1 : w_qkv + (size_t)(q-1)*1024;
    for (int i = tid; i < 1024; i += 256) sw[i] = wsrc[i];
    if (tid < 32) { s_g[tid] = ln_g[tid]; s_b[tid] = ln_b[tid]; }
    __syncthreads();
    float xv[32];
#pragma unroll
    for (int c = 0; c < 32; c++) xv[c] = x[(size_t)(b*32 + c)*NN + p];
    float vin[32];
    if (q == 0) {
#pragma unroll
        for (int c = 0; c < 32; c++) vin[c] = xv[c];
    } else {
        float mu = 0.f;
#pragma unroll
        for (int c = 0; c < 32; c++) mu += xv[c];
        mu *= (1.f/32.f);
        float var = 0.f;
#pragma unroll
        for (int c = 0; c < 32; c++) { float d = xv[c]-mu; var += d*d; }
        var *= (1.f/32.f);
        float inv = rsqrtf(var + 1e-5f);
#pragma unroll
        for (int c = 0; c < 32; c++) vin[c] = (xv[c]-mu)*inv*s_g[c] + s_b[c];
    }
    float* outbase = (q == 0) ? g_cat96p + (size_t)(b*96)*NN
                              : g_qkv + (size_t)(b*96 + (q-1)*32)*NN;
    for (int o = 0; o < 32; o++) {
        float a = 0.f;
#pragma unroll
        for (int c = 0; c < 32; c++) a += sw[o*32+c]*vin[c];
        outbase[(size_t)o*NN + p] = a;
    }
}

// ---------------- grouped 3x3 conv (96 ch, groups=32, in/out 3 per group) ----------------
__global__ void k_qkvd(const float* __restrict__ w) {
    __shared__ float ws[96*27];
    int tid = threadIdx.x;
    for (int i = tid; i < 96*27; i += 256) ws[i] = w[i];
    __syncthreads();
    int gid = blockIdx.x*256 + tid;
    int p = gid % NN;
    int g = (gid / NN) % 32;
    int b = gid / (32*NN);
    int y = p >> 7, xx = p & 127;
    float a0 = 0.f, a1 = 0.f, a2 = 0.f;
    const float* inb = g_qkv + (size_t)(b*96 + 3*g)*NN;
#pragma unroll
    for (int ky = 0; ky < 3; ky++) {
        int gy = y - 1 + ky;
        if (gy < 0 || gy >= HH) continue;
#pragma unroll
        for (int kx = 0; kx < 3; kx++) {
            int gx = xx - 1 + kx;
            if (gx < 0 || gx >= WW) continue;
            int kk = ky*3 + kx;
#pragma unroll
            for (int ci = 0; ci < 3; ci++) {
                float v = inb[ci*NN + gy*WW + gx];
                a0 += ws[(3*g+0)*27 + ci*9 + kk]*v;
                a1 += ws[(3*g+1)*27 + ci*9 + kk]*v;
                a2 += ws[(3*g+2)*27 + ci*9 + kk]*v;
            }
        }
    }
    g_qkvd[(size_t)(b*96 + 3*g+0)*NN + p] = a0;
    g_qkvd[(size_t)(b*96 + 3*g+1)*NN + p] = a1;
    g_qkvd[(size_t)(b*96 + 3*g+2)*NN + p] = a2;
}

// ---------------- sliced gram accumulate (dots + squared norms) ----------------
template<int MODE>
__global__ void k_gramacc(const float* __restrict__ xin) {
    constexpr int D = (MODE == 0) ? 4 : 8;
    constexpr int E = 4;
    constexpr int NS = D*E + D + E;          // 24 or 44
    constexpr int SL = 16;
    int bid = blockIdx.x;                    // BB*8*16
    int slice = bid & 15;
    int h = (bid >> 4) & 7;
    int b = bid >> 7;
    int tid = threadIdx.x;
    const float* qbase;
    if (MODE == 0) qbase = g_qkvd + (size_t)(b*96 + h*D)*NN;
    else qbase = (h < 4) ? xin + (size_t)(b*32 + h*8)*NN
                         : g_prompt + (size_t)(b*32 + (h-4)*8)*NN;
    const float* kbase = (MODE == 0) ? g_qkvd + (size_t)(b*96 + 32 + h*E)*NN
                                     : g_kfeat + (size_t)(b*32 + h*E)*NN;
    float acc[NS];
#pragma unroll
    for (int i = 0; i < NS; i++) acc[i] = 0.f;
    int n0 = slice * (NN/SL);
    for (int it = 0; it < (NN/SL)/256; it++) {
        int n = n0 + it*256 + tid;
        float qv[D], kv[E];
#pragma unroll
        for (int d = 0; d < D; d++) qv[d] = qbase[(size_t)d*NN + n];
#pragma unroll
        for (int e = 0; e < E; e++) kv[e] = kbase[(size_t)e*NN + n];
#pragma unroll
        for (int d = 0; d < D; d++)
#pragma unroll
            for (int e = 0; e < E; e++) acc[d*E+e] += qv[d]*kv[e];
#pragma unroll
        for (int d = 0; d < D; d++) acc[D*E + d] += qv[d]*qv[d];
#pragma unroll
        for (int e = 0; e < E; e++) acc[D*E + D + e] += kv[e]*kv[e];
    }
    __shared__ float red[NS];
    if (tid < NS) red[tid] = 0.f;
    __syncthreads();
    int lane = tid & 31;
#pragma unroll
    for (int i = 0; i < NS; i++) {
        float v = acc[i];
#pragma unroll
        for (int o = 16; o > 0; o >>= 1) v += __shfl_down_sync(0xffffffffu, v, o);
        if (lane == 0) atomicAdd(&red[i], v);
    }
    __syncthreads();
    float* st = (MODE == 0) ? g_stage_in + (b*8 + h)*24 : g_stage_f + (b*8 + h)*44;
    if (tid < NS) atomicAdd(&st[tid], red[tid]);
}

// ---------------- softmax + fold with 1x1 conv weights -> Meff ----------------
template<int MODE>
__global__ void k_meffsm(const float* __restrict__ wmat, const float* __restrict__ tempv) {
    constexpr int D = (MODE == 0) ? 4 : 8;
    int b = blockIdx.x;
    int t = threadIdx.x;                     // 1024 threads
    __shared__ float sA[8*D*4];
    if (t < 8*D) {
        int h = t / D, d = t % D;
        const float* st = (MODE == 0) ? g_stage_in + (b*8 + h)*24 : g_stage_f + (b*8 + h)*44;
        float qn = fmaxf(sqrtf(st[D*4 + d]), 1e-12f);
        float tp = tempv[h];
        float row[4];
        float mx = -1e30f;
#pragma unroll
        for (int e = 0; e < 4; e++) {
            float kn = fmaxf(sqrtf(st[D*4 + D + e]), 1e-12f);
            row[e] = st[d*4+e] / (qn*kn) * tp;
            mx = fmaxf(mx, row[e]);
        }
        float sum = 0.f;
#pragma unroll
        for (int e = 0; e < 4; e++) { row[e] = expf(row[e]-mx); sum += row[e]; }
        float isum = 1.f/sum;
#pragma unroll
        for (int e = 0; e < 4; e++) sA[(h*D + d)*4 + e] = row[e]*isum;
    }
    __syncthreads();
    int o = t >> 5, vc = t & 31, h = vc >> 2, e = vc & 3;
    float s = 0.f;
#pragma unroll
    for (int d = 0; d < D; d++)
        s += wmat[o*(8*D) + h*D + d] * sA[(h*D + d)*4 + e];
    float* M = (MODE == 0) ? g_Meff_in : g_Meff_f;
    M[b*1024 + o*32 + vc] = s;
}

// ---------------- per-pixel 32x32 matmul apply (4-way channel split) ----------------
template<int MODE>
__global__ void k_apply(const float* __restrict__ xin, float* __restrict__ outp) {
    __shared__ float sm[256];
    int tid = threadIdx.x;
    int gid = blockIdx.x*256 + tid;          // B*4*N
    int p = gid % NN;
    int q = (gid / NN) & 3;
    int b = gid / (4*NN);
    const float* M = (MODE == 0) ? g_Meff_in : g_Meff_f;
    if (tid < 256) sm[tid] = M[b*1024 + q*256 + tid];
    __syncthreads();
    float vv[32];
#pragma unroll
    for (int c = 0; c < 32; c++) {
        if (MODE == 0) vv[c] = g_qkvd[(size_t)(b*96 + 64 + c)*NN + p];
        else           vv[c] = xin[(size_t)(b*32 + c)*NN + p];
    }
#pragma unroll
    for (int j = 0; j < 8; j++) {
        int o = q*8 + j;
        float a = (MODE == 0) ? xin[(size_t)(b*32 + o)*NN + p] : 0.f;
#pragma unroll
        for (int c = 0; c < 32; c++) a += sm[j*32+c]*vv[c];
        if (MODE == 0) g_cat96p[(size_t)(b*96 + 64 + o)*NN + p] = a;
        else           outp[(size_t)(b*32 + o)*NN + p] = a;
    }
}

// ---------------- 2x2 avgpool of concat(x,y) ----------------
__global__ void k_pool(const float* __restrict__ x, const float* __restrict__ y) {
    int gid = blockIdx.x*256 + threadIdx.x;
    int xx = gid & 63;
    int yy = (gid >> 6) & 63;
    int c  = (gid >> 12) & 63;
    int b  = gid >> 18;
    const float* src = (c < 32) ? x + (size_t)(b*32 + c)*NN : y + (size_t)(b*32 + (c-32))*NN;
    int iy = yy*2, ix = xx*2;
    float v = 0.25f*(src[iy*WW+ix] + src[iy*WW+ix+1] + src[(iy+1)*WW+ix] + src[(iy+1)*WW+ix+1]);
    g_pool[((size_t)(b*64 + c)*64 + yy)*64 + xx] = v;
}

// ---------------- NCHW -> NHWC(float4 groups) transpose of x ----------------
__global__ void k_nhwc(const float* __restrict__ x) {
    __shared__ float s[32][65];
    int tid = threadIdx.x;
    int blk = blockIdx.x;                    // B*NN/64
    int b = blk / (NN/64);
    int px0 = (blk % (NN/64)) * 64;
#pragma unroll
    for (int k = 0; k < 8; k++) {
        int ch = k*4 + (tid >> 6);
        int px = tid & 63;
        s[ch][px] = x[(size_t)(b*32 + ch)*NN + px0 + px];
    }
    __syncthreads();
    float* xn = (float*)g_xnhwc4;
#pragma unroll
    for (int k = 0; k < 8; k++) {
        int px = k*8 + (tid >> 5);
        int ch = tid & 31;
        xn[(size_t)(b*NN + px0 + px)*32 + ch] = s[ch][px];
    }
}

// ---------------- fused deformable convs (k=3,5,7; groups=8) ----------------
template<int K, int PAD>
__device__ __forceinline__ void deform_one(const float* __restrict__ offp,
                                           const float* __restrict__ ws,
                                           const float* __restrict__ bsh,
                                           int yy, int xx, int b, int g, int p,
                                           int out0) {
    constexpr int K2 = K*K;
    float acc0 = 0.f, acc1 = 0.f, acc2 = 0.f, acc3 = 0.f;
    const float4* xb = g_xnhwc4 + (size_t)b*NN*8 + g;
    for (int k2 = 0; k2 < K2; k2++) {
        float dy = offp[(size_t)(2*k2)*NN];
        float dx = offp[(size_t)(2*k2+1)*NN];
        float py = (float)(yy - PAD + k2 / K) + dy;
        float px = (float)(xx - PAD + k2 % K) + dx;
        float y0f = floorf(py), x0f = floorf(px);
        float wy = py - y0f, wx = px - x0f;
        int y0 = (int)y0f, x0 = (int)x0f;
        float w00 = (1.f-wy)*(1.f-wx), w01 = (1.f-wy)*wx, w10 = wy*(1.f-wx), w11 = wy*wx;
        bool iy0 = (y0 >= 0 && y0 < HH), iy1 = (y0+1 >= 0 && y0+1 < HH);
        bool ix0 = (x0 >= 0 && x0 < WW), ix1 = (x0+1 >= 0 && x0+1 < WW);
        float4 s = make_float4(0.f, 0.f, 0.f, 0.f);
        if (iy0 && ix0) {
            float4 v = xb[(size_t)(y0*WW + x0)*8];
            s.x += w00*v.x; s.y += w00*v.y; s.z += w00*v.z; s.w += w00*v.w;
        }
        if (iy0 && ix1) {
            float4 v = xb[(size_t)(y0*WW + x0 + 1)*8];
            s.x += w01*v.x; s.y += w01*v.y; s.z += w01*v.z; s.w += w01*v.w;
        }
        if (iy1 && ix0) {
            float4 v = xb[(size_t)((y0+1)*WW + x0)*8];
            s.x += w10*v.x; s.y += w10*v.y; s.z += w10*v.z; s.w += w10*v.w;
        }
        if (iy1 && ix1) {
            float4 v = xb[(size_t)((y0+1)*WW + x0 + 1)*8];
            s.x += w11*v.x; s.y += w11*v.y; s.z += w11*v.z; s.w += w11*v.w;
        }
        acc0 += ws[(0*4+0)*K2+k2]*s.x + ws[(0*4+1)*K2+k2]*s.y + ws[(0*4+2)*K2+k2]*s.z + ws[(0*4+3)*K2+k2]*s.w;
        acc1 += ws[(1*4+0)*K2+k2]*s.x + ws[(1*4+1)*K2+k2]*s.y + ws[(1*4+2)*K2+k2]*s.z + ws[(1*4+3)*K2+k2]*s.w;
        acc2 += ws[(2*4+0)*K2+k2]*s.x + ws[(2*4+1)*K2+k2]*s.y + ws[(2*4+2)*K2+k2]*s.z + ws[(2*4+3)*K2+k2]*s.w;
        acc3 += ws[(3*4+0)*K2+k2]*s.x + ws[(3*4+1)*K2+k2]*s.y + ws[(3*4+2)*K2+k2]*s.z + ws[(3*4+3)*K2+k2]*s.w;
    }
    float* ob = g_catf + (size_t)(b*96 + out0 + g*4)*NN + p;
    ob[0*NN] = fmaxf(acc0 + bsh[0], 0.f);
    ob[1*NN] = fmaxf(acc1 + bsh[1], 0.f);
    ob[2*NN] = fmaxf(acc2 + bsh[2], 0.f);
    ob[3*NN] = fmaxf(acc3 + bsh[3], 0.f);
}

__global__ void k_deform_all(const float* __restrict__ w3, const float* __restrict__ b3,
                             const float* __restrict__ w5, const float* __restrict__ b5,
                             const float* __restrict__ w7, const float* __restrict__ b7) {
    __shared__ float ws[16*83];              // [w3 144 | w5 400 | w7 784]
    __shared__ float bsh[12];
    int tid = threadIdx.x;
    int gid = blockIdx.x*256 + tid;          // B*8*N
    int p = gid % NN;
    int g = (gid / NN) & 7;
    int b = gid / (8*NN);
    for (int i = tid; i < 144; i += 256) ws[i] = w3[g*144 + i];
    for (int i = tid; i < 400; i += 256) ws[144 + i] = w5[g*400 + i];
    for (int i = tid; i < 784; i += 256) ws[544 + i] = w7[g*784 + i];
    if (tid < 4)       bsh[tid]   = b3[g*4 + tid];
    else if (tid < 8)  bsh[tid]   = b5[g*4 + tid - 4];
    else if (tid < 12) bsh[tid]   = b7[g*4 + tid - 8];
    __syncthreads();
    int yy = p >> 7, xx = p & 127;
    const float* offbase = g_offs + (size_t)(b*166)*NN + p;
    deform_one<3,1>(offbase,              ws,       bsh,     yy, xx, b, g, p, 0);
    deform_one<5,2>(offbase + (size_t)18*NN, ws+144, bsh+4,  yy, xx, b, g, p, 32);
    deform_one<7,3>(offbase + (size_t)68*NN, ws+544, bsh+8,  yy, xx, b, g, p, 64);
}

// ---------------- pointwise conv 96->32 with bias (4-way split) ----------------
__global__ void k_pw(const float* __restrict__ w, const float* __restrict__ bias) {
    __shared__ float ws[8*96];
    __shared__ float bs[8];
    int tid = threadIdx.x;
    int gid = blockIdx.x*256 + tid;          // B*4*N
    int p = gid % NN;
    int q = (gid / NN) & 3;
    int b = gid / (4*NN);
    for (int i = tid; i < 768; i += 256) ws[i] = w[(size_t)(q*8 + i/96)*96 + i%96];
    if (tid < 8) bs[tid] = bias[q*8 + tid];
    __syncthreads();
    float acc[8];
#pragma unroll
    for (int j = 0; j < 8; j++) acc[j] = bs[j];
    for (int c = 0; c < 96; c++) {
        float v = g_catf[(size_t)(b*96 + c)*NN + p];
#pragma unroll
        for (int j = 0; j < 8; j++) acc[j] += ws[j*96 + c]*v;
    }
#pragma unroll
    for (int j = 0; j < 8; j++) g_kfeat[(size_t)(b*32 + q*8 + j)*NN + p] = acc[j];
}

// ---------------- launch (kernel launches ONLY) ----------------
extern "C" void kernel_launch(void* const* d_in, const int* in_sizes, int n_in,
                              void* d_out, int out_size) {
    const float* x       = (const float*)d_in[0];
    const float* y       = (const float*)d_in[1];
    const float* temp    = (const float*)d_in[2];
    const float* w_po    = (const float*)d_in[3];
    const float* w_lp1   = (const float*)d_in[4];
    const float* w_lp2   = (const float*)d_in[5];
    const float* ln_g    = (const float*)d_in[6];
    const float* ln_b    = (const float*)d_in[7];
    const float* temp_in = (const float*)d_in[8];
    const float* w_qkv   = (const float*)d_in[9];
    const float* w_qkvd  = (const float*)d_in[10];
    const float* w_mproj = (const float*)d_in[11];
    const float* w_c3    = (const float*)d_in[12];
    const float* w_k2    = (const float*)d_in[13];
    const float* w_k3    = (const float*)d_in[14];
    const float* w_k4    = (const float*)d_in[15];
    const float* w_d3    = (const float*)d_in[16];
    const float* b_d3    = (const float*)d_in[17];
    const float* w_d5    = (const float*)d_in[18];
    const float* b_d5    = (const float*)d_in[19];
    const float* w_d7    = (const float*)d_in[20];
    const float* b_d7    = (const float*)d_in[21];
    const float* w_pw    = (const float*)d_in[22];
    const float* b_pw    = (const float*)d_in[23];

    // ---- alignment branch first (puts the heavy k4 conv at launch index 3 for ncu) ----
    k_pool<<<(BB*64*64*64)/256, 256>>>(x, y);                         // 0
    // a = sigmoid(conv3x3(pool, w_k2, pad=0)) at 62x62
    k_conv3x3_tc<64,166,1, 5,0, 6,0,166, 64,64,62,62, 0>
        <<<dim3(62, 6, BB), 256>>>(nullptr, nullptr, w_k2);           // 1
    // bmid = conv3x3(concat(x,y), w_k3) * nearest_up(a)
    k_conv3x3_tc<64,166,2, 0,1, 7,0,166, 128,128,128,128, 1>
        <<<dim3(HH, 6, BB), 256>>>(x, y, w_k3);                       // 2
    // offs = conv3x3(bmid, w_k4)
    k_conv3x3_tc<166,166,0, 7,0, 8,0,166, 128,128,128,128, 1>
        <<<dim3(HH, 6, BB), 256>>>(nullptr, nullptr, w_k4);           // 3  <- profiled
    k_nhwc<<<(BB*NN)/64, 256>>>(x);                                   // 4
    k_deform_all<<<(BB*8*NN)/256, 256>>>(w_d3, b_d3, w_d5, b_d5, w_d7, b_d7); // 5
    k_pw<<<(BB*4*NN)/256, 256>>>(w_pw, b_pw);                         // 6

    // ---- prompt branch ----
    k_zero<<<1, 256>>>();                                             // 7
    k_ln_l1_qkv<<<(BB*4*NN)/256, 256>>>(x, ln_g, ln_b, w_lp1, w_qkv); // 8
    // l2 = conv3x3(x, w_lp2) -> g_cat96p ch32..63
    k_conv3x3_tc<32,32,0, 0,0, 1,32,96, 128,128,128,128, 1>
        <<<dim3(HH, 1, BB), 256>>>(x, nullptr, w_lp2);                // 9
    k_qkvd<<<(BB*32*NN)/256, 256>>>(w_qkvd);                          // 10
    k_gramacc<0><<<BB*8*16, 256>>>(x);                                // 11
    k_meffsm<0><<<BB, 1024>>>(w_mproj, temp_in);                      // 12
    k_apply<0><<<(BB*4*NN)/256, 256>>>(x, nullptr);                   // 13
    // prompt = conv3x3(g_cat96p, w_c3)
    k_conv3x3_tc<96,32,0, 1,0, 11,0,32, 128,128,128,128, 1>
        <<<dim3(HH, 1, BB), 256>>>(nullptr, nullptr, w_c3);           // 14

    // ---- final prompted channel attention ----
    k_gramacc<1><<<BB*8*16, 256>>>(x);                                // 15
    k_meffsm<1><<<BB, 1024>>>(w_po, temp);                            // 16
    k_apply<1><<<(BB*4*NN)/256, 256>>>(x, (float*)d_out);             // 17
}

// round 7
// speedup vs baseline: 2.4854x; 1.4500x over previous
#include <cuda_runtime.h>
#include <math.h>
#include <stdint.h>

#define BB 2
#define CCH 32
#define HH 128
#define WW 128
#define NN (HH*WW)
#define NHEADS 8

// ---------------- scratch (static device globals; no allocation) ----------------
__device__ float g_qkv[BB*96*NN];
__device__ float g_qkvd[BB*96*NN];     // q|k|v after grouped dwconv
__device__ float g_asmall[BB*166*62*62];
__device__ float g_offs[BB*166*NN];
__device__ float g_catf[BB*96*NN];     // [f3 | f5 | f7]
__device__ float g_kfeat[BB*CCH*NN];
__device__ float g_prompt[BB*CCH*NN];
__device__ float4 g_xnhwc4[BB*NN*8];   // x in NHWC, float4-grouped (16B aligned)
__device__ float g_stage_in[BB*8*24];  // dots[16] | q2[4] | k2[4]
__device__ float g_stage_f[BB*8*44];   // dots[32] | q2[8] | k2[4]
__device__ float g_Meff_in[BB*32*32];
__device__ float g_Meff_f[BB*32*32];

// bf16x2 pair-interleaved staging (u32 = channels (2c, 2c+1))
__device__ uint32_t g_xy16[BB*32*NN];      // cp 0..15 = x, 16..31 = y
__device__ uint32_t g_pool16[BB*32*64*64]; // pooled concat(x,y)
__device__ uint32_t g_bmid16[BB*83*NN];    // k3 output (166 ch -> 83 cp)
__device__ uint32_t g_cat96p16[BB*48*NN];  // [l1 cp0-15 | l2 cp16-31 | xg cp32-47]
__device__ uint32_t g_w16[289872];         // prepacked conv weights (sW image)

// compile-time scratch-buffer resolution
template<int ID> __device__ __forceinline__ float* gbuf();
template<> __device__ __forceinline__ float* gbuf<6>()  { return g_asmall; }
template<> __device__ __forceinline__ float* gbuf<8>()  { return g_offs; }
template<> __device__ __forceinline__ float* gbuf<11>() { return g_prompt; }
template<int ID> __device__ __forceinline__ uint32_t* gbufu();
template<> __device__ __forceinline__ uint32_t* gbufu<1>() { return g_xy16; }
template<> __device__ __forceinline__ uint32_t* gbufu<2>() { return g_pool16; }
template<> __device__ __forceinline__ uint32_t* gbufu<3>() { return g_bmid16; }
template<> __device__ __forceinline__ uint32_t* gbufu<4>() { return g_cat96p16; }

// ---------------- bf16 helpers ----------------
__device__ __forceinline__ uint32_t pack_bf16x2(float lo, float hi) {
    uint32_t r;
    asm("cvt.rn.bf16x2.f32 %0, %1, %2;" : "=r"(r) : "f"(hi), "f"(lo));
    return r;
}
__device__ __forceinline__ void mma_bf16(float* d, uint32_t a0, uint32_t a1,
                                         uint32_t a2, uint32_t a3,
                                         uint32_t b0, uint32_t b1) {
    asm volatile("mma.sync.aligned.m16n8k16.row.col.f32.bf16.bf16.f32 "
        "{%0,%1,%2,%3}, {%4,%5,%6,%7}, {%8,%9}, {%0,%1,%2,%3};\n"
        : "+f"(d[0]), "+f"(d[1]), "+f"(d[2]), "+f"(d[3])
        : "r"(a0), "r"(a1), "r"(a2), "r"(a3), "r"(b0), "r"(b1));
}

// ---------------- weight prepack: write sW shared-memory images ----------------
// layout per (octile, chunk): [(cp*9 + k)*33 + oc], oc permuted for bf16-out convs
__global__ void k_prepack(const float* __restrict__ w_lp2, const float* __restrict__ w_c3,
                          const float* __restrict__ w_k2, const float* __restrict__ w_k3,
                          const float* __restrict__ w_k4) {
    const int conv = blockIdx.y;
    const int CINs[5]  = {32, 96, 64, 64, 166};
    const int COUTs[5] = {32, 32, 166, 166, 166};
    const int NCHs[5]  = {2, 6, 4, 4, 11};
    const int OCTs[5]  = {1, 1, 6, 6, 6};
    const int PERMs[5] = {1, 0, 0, 1, 0};
    const int OFFs[5]  = {0, 4752, 19008, 76032, 133056};
    const float* wsv[5] = {w_lp2, w_c3, w_k2, w_k3, w_k4};
    const int CIN = CINs[conv], COUT = COUTs[conv], NCH = NCHs[conv], PERM = PERMs[conv];
    const float* w = wsv[conv];
    const int total = OCTs[conv]*NCH*2376;
    for (int i = blockIdx.x*256 + threadIdx.x; i < total; i += gridDim.x*256) {
        int within = i % 2376;
        int tile   = i / 2376;
        int oc = within % 33;
        int ck = within / 33;
        int k  = ck % 9;
        int cp = ck / 9;
        int chunk  = tile % NCH;
        int octile = tile / NCH;
        uint32_t val = 0;
        if (oc < 32) {
            int pc = PERM ? ((oc & 16) + 2*(oc & 7) + ((oc >> 3) & 1)) : oc;
            int chn = octile*32 + pc;
            int c0 = chunk*16 + 2*cp;
            float v0 = 0.f, v1 = 0.f;
            if (chn < COUT && c0 < CIN) {
                v0 = w[((size_t)chn*CIN + c0)*9 + k];
                v1 = w[((size_t)chn*CIN + c0 + 1)*9 + k];
            }
            val = pack_bf16x2(v0, v1);
        }
        g_w16[OFFs[conv] + i] = val;
    }
}

// ---------------- pack x|y into bf16x2 pair planes ----------------
__global__ void k_pack_xy(const float* __restrict__ x, const float* __restrict__ y) {
    int gid = blockIdx.x*256 + threadIdx.x;     // BB*32*NN
    int p = gid % NN;
    int cp = (gid / NN) % 32;
    int b = gid / (32*NN);
    const float* s = (cp < 16) ? x + (size_t)(b*32 + 2*cp)*NN
                               : y + (size_t)(b*32 + 2*(cp-16))*NN;
    g_xy16[(size_t)(b*32 + cp)*NN + p] = pack_bf16x2(s[p], s[NN + p]);
}

// ---------------- 2x2 avgpool of concat(x,y) -> packed ----------------
__global__ void k_pool16(const float* __restrict__ x, const float* __restrict__ y) {
    int gid = blockIdx.x*256 + threadIdx.x;     // BB*32*4096
    int px = gid & 63;
    int py = (gid >> 6) & 63;
    int cp = (gid >> 12) & 31;
    int b  = gid >> 17;
    const float* s = (cp < 16) ? x + (size_t)(b*32 + 2*cp)*NN
                               : y + (size_t)(b*32 + 2*(cp-16))*NN;
    int iy = 2*py, ix = 2*px;
    float v0 = 0.25f*(s[iy*WW+ix] + s[iy*WW+ix+1] + s[(iy+1)*WW+ix] + s[(iy+1)*WW+ix+1]);
    const float* s1 = s + NN;
    float v1 = 0.25f*(s1[iy*WW+ix] + s1[iy*WW+ix+1] + s1[(iy+1)*WW+ix] + s1[(iy+1)*WW+ix+1]);
    g_pool16[(size_t)(b*32 + cp)*4096 + py*64 + px] = pack_bf16x2(v0, v1);
}

// ---------------- zero staging ----------------
__global__ void k_zero() {
    int t = threadIdx.x;
    for (int i = t; i < BB*8*24; i += 256) g_stage_in[i] = 0.f;
    for (int i = t; i < BB*8*44; i += 256) g_stage_f[i] = 0.f;
}

// ---------------- tensor-core conv3x3, bf16 m16n8k16, packed I/O ----------------
// EPI: 0 plain, 1 sigmoid, 2 multiply by nearest-upsampled sigmoid aux (g_asmall)
// OUT16=1: write bf16x2 pairs (channel-permuted weights); else fp32 NCHW.
template<int CIN, int COUT, int EPI, int SRCU, int CPTOT, int OUT16, int DSTID,
         int OUTC0, int OUTCTOT, int W16OFF,
         int HIN, int WIN, int HOUT, int WOUT, int PAD>
__global__ void k_conv3x3_tc() {
    constexpr int CP = CIN/2;
    constexpr int NCHUNK = (CP + 7) / 8;
    const uint32_t* src16 = gbufu<SRCU>();
    __shared__ uint32_t sIn[8*3*132];        // [cp][row][px], px 0..131 -> gx = px-PAD
    __shared__ uint32_t sW[2376];            // [(cp*9+k)*33 + oc]
    const int y   = blockIdx.x;
    const int oc0 = blockIdx.y * 32;
    const int b   = blockIdx.z;
    const int tid = threadIdx.x;
    const int lane = tid & 31, wid5 = tid >> 5;
    const int wm = wid5 >> 2, wn = wid5 & 3;
    const int g = lane >> 2, tg = lane & 3;

    float acc[4][4];
#pragma unroll
    for (int t = 0; t < 4; t++)
#pragma unroll
        for (int r = 0; r < 4; r++) acc[t][r] = 0.f;

    const uint32_t* wbase = g_w16 + W16OFF + (size_t)(oc0 >> 5)*NCHUNK*2376;
    for (int ch = 0; ch < NCHUNK; ch++) {
        // ---- input fill: warp = one cp plane, lanes sweep px (div-free) ----
        {
            int cpg = ch*8 + wid5;
            bool cpv = cpg < CP;
            const uint32_t* sp = src16 + (size_t)(b*CPTOT + cpg)*(HIN*WIN);
#pragma unroll
            for (int row = 0; row < 3; row++) {
                int gy = y - PAD + row;
                bool yv = cpv && ((unsigned)gy < (unsigned)HIN);
                const uint32_t* rp = sp + gy*WIN;
                uint32_t* sd = sIn + (wid5*3 + row)*132;
#pragma unroll
                for (int kk = 0; kk < 5; kk++) {
                    int px = lane + 32*kk;
                    if (px < 132) {
                        int gx = px - PAD;
                        uint32_t v = 0;
                        if (yv && (unsigned)gx < (unsigned)WIN) v = rp[gx];
                        sd[px] = v;
                    }
                }
            }
        }
        // ---- weight fill: straight copy of prepacked image ----
        {
            const uint32_t* wp = wbase + ch*2376;
            for (int i = tid; i < 2376; i += 256) sW[i] = wp[i];
        }
        __syncthreads();
        // ---- 9 shifted GEMMs, K=16 each ----
#pragma unroll
        for (int kpos = 0; kpos < 9; kpos++) {
            const int ky = kpos / 3, kx = kpos % 3;
            const int aoc = wm*16 + g;
            uint32_t a0 = sW[(tg*9 + kpos)*33 + aoc];
            uint32_t a1 = sW[(tg*9 + kpos)*33 + aoc + 8];
            uint32_t a2 = sW[((tg+4)*9 + kpos)*33 + aoc];
            uint32_t a3 = sW[((tg+4)*9 + kpos)*33 + aoc + 8];
#pragma unroll
            for (int t = 0; t < 4; t++) {
                int px = wn*32 + t*8 + g;
                uint32_t b0 = sIn[(tg*3 + ky)*132 + px + kx];
                uint32_t b1 = sIn[((tg+4)*3 + ky)*132 + px + kx];
                mma_bf16(acc[t], a0, a1, a2, a3, b0, b1);
            }
        }
        __syncthreads();
    }
    // ---- epilogue ----
    if (OUT16) {
        // weights were permuted: acc rows (g, g+8) = adjacent channels (2g, 2g+1)
        int chan0 = oc0 + wm*16 + 2*g;
        if (chan0 < COUT) {
            uint32_t* op = gbufu<OUT16 ? DSTID : 1>()
                + (size_t)(b*OUTCTOT + (OUTC0 + chan0)/2)*(HOUT*WOUT) + (size_t)y*WOUT;
#pragma unroll
            for (int t = 0; t < 4; t++) {
                int px = wn*32 + t*8 + 2*tg;
                float v00 = acc[t][0], v01 = acc[t][1];   // chan0,   px / px+1
                float v10 = acc[t][2], v11 = acc[t][3];   // chan0+1, px / px+1
                if (EPI == 2) {
                    int ay = (y * 62) >> 7;
                    int ax0 = (px * 62) >> 7, ax1 = ((px+1) * 62) >> 7;
                    const float* a0p = g_asmall + ((size_t)(b*166 + chan0)*62 + ay)*62;
                    const float* a1p = a0p + 62*62;
                    v00 *= a0p[ax0]; v01 *= a0p[ax1];
                    v10 *= a1p[ax0]; v11 *= a1p[ax1];
                }
                op[px]   = pack_bf16x2(v00, v10);
                op[px+1] = pack_bf16x2(v01, v11);
            }
        }
    } else {
        float* dst = gbuf<OUT16 ? 11 : DSTID>();
        const int ocr0 = oc0 + wm*16 + g;
#pragma unroll
        for (int t = 0; t < 4; t++) {
            int px = wn*32 + t*8 + 2*tg;
#pragma unroll
            for (int half = 0; half < 2; half++) {
                int ocr = ocr0 + half*8;
                if (ocr >= COUT) continue;
                float v0 = acc[t][half*2 + 0];
                float v1 = acc[t][half*2 + 1];
                if (EPI == 1) {
                    v0 = 1.f / (1.f + expf(-v0));
                    v1 = 1.f / (1.f + expf(-v1));
                }
                float* opf = dst + (size_t)(b*OUTCTOT + OUTC0 + ocr)*(HOUT*WOUT) + (size_t)y*WOUT;
                if (px   < WOUT) opf[px]   = v0;
                if (px+1 < WOUT) opf[px+1] = v1;
            }
        }
    }
}

// ---------------- fused LayerNorm + l1 + qkv (4-way channel split) ----------------
// q=0: l1 -> g_cat96p16 cp0..15 (packed); q=1..3: qkv rows -> g_qkv fp32
__global__ void k_ln_l1_qkv(const float* __restrict__ x, const float* __restrict__ ln_g,
                            const float* __restrict__ ln_b, const float* __restrict__ w_lp1,
                            const float* __restrict__ w_qkv) {
    __shared__ float sw[32*32];
    __shared__ float s_g[32], s_b[32];
    int tid = threadIdx.x;
    int gid = blockIdx.x*256 + tid;          // B*4*N
    int p = gid % NN;
    int q = (gid / NN) & 3;
    int b = gid / (4*NN);
    const float* wsrc = (q == 0) ? w_lp1 : w_qkv + (size_t)(q-1)*1024;
    for (int i = tid; i < 1024; i += 256) sw[i] = wsrc[i];
    if (tid < 32) { s_g[tid] = ln_g[tid]; s_b[tid] = ln_b[tid]; }
    __syncthreads();
    float xv[32];
#pragma unroll
    for (int c = 0; c < 32; c++) xv[c] = x[(size_t)(b*32 + c)*NN + p];
    if (q == 0) {
#pragma unroll
        for (int m = 0; m < 16; m++) {
            float a0 = 0.f, a1 = 0.f;
#pragma unroll
            for (int c = 0; c < 32; c++) {
                a0 += sw[(2*m)*32 + c]*xv[c];
                a1 += sw[(2*m+1)*32 + c]*xv[c];
            }
            g_cat96p16[(size_t)(b*48 + m)*NN + p] = pack_bf16x2(a0, a1);
        }
    } else {
        float mu = 0.f;
#pragma unroll
        for (int c = 0; c < 32; c++) mu += xv[c];
        mu *= (1.f/32.f);
        float var = 0.f;
#pragma unroll
        for (int c = 0; c < 32; c++) { float d = xv[c]-mu; var += d*d; }
        var *= (1.f/32.f);
        float inv = rsqrtf(var + 1e-5f);
        float vin[32];
#pragma unroll
        for (int c = 0; c < 32; c++) vin[c] = (xv[c]-mu)*inv*s_g[c] + s_b[c];
        float* outbase = g_qkv + (size_t)(b*96 + (q-1)*32)*NN;
        for (int o = 0; o < 32; o++) {
            float a = 0.f;
#pragma unroll
            for (int c = 0; c < 32; c++) a += sw[o*32+c]*vin[c];
            outbase[(size_t)o*NN + p] = a;
        }
    }
}

// ---------------- grouped 3x3 conv (96 ch, groups=32, in/out 3 per group) ----------------
__global__ void k_qkvd(const float* __restrict__ w) {
    __shared__ float ws[96*27];
    int tid = threadIdx.x;
    for (int i = tid; i < 96*27; i += 256) ws[i] = w[i];
    __syncthreads();
    int gid = blockIdx.x*256 + tid;
    int p = gid % NN;
    int g = (gid / NN) % 32;
    int b = gid / (32*NN);
    int y = p >> 7, xx = p & 127;
    float a0 = 0.f, a1 = 0.f, a2 = 0.f;
    const float* inb = g_qkv + (size_t)(b*96 + 3*g)*NN;
#pragma unroll
    for (int ky = 0; ky < 3; ky++) {
        int gy = y - 1 + ky;
        if (gy < 0 || gy >= HH) continue;
#pragma unroll
        for (int kx = 0; kx < 3; kx++) {
            int gx = xx - 1 + kx;
            if (gx < 0 || gx >= WW) continue;
            int kk = ky*3 + kx;
#pragma unroll
            for (int ci = 0; ci < 3; ci++) {
                float v = inb[ci*NN + gy*WW + gx];
                a0 += ws[(3*g+0)*27 + ci*9 + kk]*v;
                a1 += ws[(3*g+1)*27 + ci*9 + kk]*v;
                a2 += ws[(3*g+2)*27 + ci*9 + kk]*v;
            }
        }
    }
    g_qkvd[(size_t)(b*96 + 3*g+0)*NN + p] = a0;
    g_qkvd[(size_t)(b*96 + 3*g+1)*NN + p] = a1;
    g_qkvd[(size_t)(b*96 + 3*g+2)*NN + p] = a2;
}

// ---------------- sliced gram accumulate (dots + squared norms) ----------------
template<int MODE>
__global__ void k_gramacc(const float* __restrict__ xin) {
    constexpr int D = (MODE == 0) ? 4 : 8;
    constexpr int E = 4;
    constexpr int NS = D*E + D + E;          // 24 or 44
    constexpr int SL = 16;
    int bid = blockIdx.x;                    // BB*8*16
    int slice = bid & 15;
    int h = (bid >> 4) & 7;
    int b = bid >> 7;
    int tid = threadIdx.x;
    const float* qbase;
    if (MODE == 0) qbase = g_qkvd + (size_t)(b*96 + h*D)*NN;
    else qbase = (h < 4) ? xin + (size_t)(b*32 + h*8)*NN
                         : g_prompt + (size_t)(b*32 + (h-4)*8)*NN;
    const float* kbase = (MODE == 0) ? g_qkvd + (size_t)(b*96 + 32 + h*E)*NN
                                     : g_kfeat + (size_t)(b*32 + h*E)*NN;
    float acc[NS];
#pragma unroll
    for (int i = 0; i < NS; i++) acc[i] = 0.f;
    int n0 = slice * (NN/SL);
    for (int it = 0; it < (NN/SL)/256; it++) {
        int n = n0 + it*256 + tid;
        float qv[D], kv[E];
#pragma unroll
        for (int d = 0; d < D; d++) qv[d] = qbase[(size_t)d*NN + n];
#pragma unroll
        for (int e = 0; e < E; e++) kv[e] = kbase[(size_t)e*NN + n];
#pragma unroll
        for (int d = 0; d < D; d++)
#pragma unroll
            for (int e = 0; e < E; e++) acc[d*E+e] += qv[d]*kv[e];
#pragma unroll
        for (int d = 0; d < D; d++) acc[D*E + d] += qv[d]*qv[d];
#pragma unroll
        for (int e = 0; e < E; e++) acc[D*E + D + e] += kv[e]*kv[e];
    }
    __shared__ float red[NS];
    if (tid < NS) red[tid] = 0.f;
    __syncthreads();
    int lane = tid & 31;
#pragma unroll
    for (int i = 0; i < NS; i++) {
        float v = acc[i];
#pragma unroll
        for (int o = 16; o > 0; o >>= 1) v += __shfl_down_sync(0xffffffffu, v, o);
        if (lane == 0) atomicAdd(&red[i], v);
    }
    __syncthreads();
    float* st = (MODE == 0) ? g_stage_in + (b*8 + h)*24 : g_stage_f + (b*8 + h)*44;
    if (tid < NS) atomicAdd(&st[tid], red[tid]);
}

// ---------------- softmax + fold with 1x1 conv weights -> Meff ----------------
template<int MODE>
__global__ void k_meffsm(const float* __restrict__ wmat, const float* __restrict__ tempv) {
    constexpr int D = (MODE == 0) ? 4 : 8;
    int b = blockIdx.x;
    int t = threadIdx.x;                     // 1024 threads
    __shared__ float sA[8*D*4];
    if (t < 8*D) {
        int h = t / D, d = t % D;
        const float* st = (MODE == 0) ? g_stage_in + (b*8 + h)*24 : g_stage_f + (b*8 + h)*44;
        float qn = fmaxf(sqrtf(st[D*4 + d]), 1e-12f);
        float tp = tempv[h];
        float row[4];
        float mx = -1e30f;
#pragma unroll
        for (int e = 0; e < 4; e++) {
            float kn = fmaxf(sqrtf(st[D*4 + D + e]), 1e-12f);
            row[e] = st[d*4+e] / (qn*kn) * tp;
            mx = fmaxf(mx, row[e]);
        }
        float sum = 0.f;
#pragma unroll
        for (int e = 0; e < 4; e++) { row[e] = expf(row[e]-mx); sum += row[e]; }
        float isum = 1.f/sum;
#pragma unroll
        for (int e = 0; e < 4; e++) sA[(h*D + d)*4 + e] = row[e]*isum;
    }
    __syncthreads();
    int o = t >> 5, vc = t & 31, h = vc >> 2, e = vc & 3;
    float s = 0.f;
#pragma unroll
    for (int d = 0; d < D; d++)
        s += wmat[o*(8*D) + h*D + d] * sA[(h*D + d)*4 + e];
    float* M = (MODE == 0) ? g_Meff_in : g_Meff_f;
    M[b*1024 + o*32 + vc] = s;
}

// ---------------- per-pixel 32x32 matmul apply (4-way channel split) ----------------
// MODE 0: in=g_qkvd ch64..95, M=g_Meff_in, resid=x -> g_cat96p16 cp32..47 (packed)
// MODE 1: in=x, M=g_Meff_f -> outp fp32
template<int MODE>
__global__ void k_apply(const float* __restrict__ xin, float* __restrict__ outp) {
    __shared__ float sm[256];
    int tid = threadIdx.x;
    int gid = blockIdx.x*256 + tid;          // B*4*N
    int p = gid % NN;
    int q = (gid / NN) & 3;
    int b = gid / (4*NN);
    const float* M = (MODE == 0) ? g_Meff_in : g_Meff_f;
    if (tid < 256) sm[tid] = M[b*1024 + q*256 + tid];
    __syncthreads();
    float vv[32];
#pragma unroll
    for (int c = 0; c < 32; c++) {
        if (MODE == 0) vv[c] = g_qkvd[(size_t)(b*96 + 64 + c)*NN + p];
        else           vv[c] = xin[(size_t)(b*32 + c)*NN + p];
    }
    float av[8];
#pragma unroll
    for (int j = 0; j < 8; j++) {
        int o = q*8 + j;
        float a = (MODE == 0) ? xin[(size_t)(b*32 + o)*NN + p] : 0.f;
#pragma unroll
        for (int c = 0; c < 32; c++) a += sm[j*32+c]*vv[c];
        av[j] = a;
    }
    if (MODE == 0) {
#pragma unroll
        for (int m = 0; m < 4; m++)
            g_cat96p16[(size_t)(b*48 + 32 + q*4 + m)*NN + p] = pack_bf16x2(av[2*m], av[2*m+1]);
    } else {
#pragma unroll
        for (int j = 0; j < 8; j++)
            outp[(size_t)(b*32 + q*8 + j)*NN + p] = av[j];
    }
}

// ---------------- NCHW -> NHWC(float4 groups) transpose of x ----------------
__global__ void k_nhwc(const float* __restrict__ x) {
    __shared__ float s[32][65];
    int tid = threadIdx.x;
    int blk = blockIdx.x;                    // B*NN/64
    int b = blk / (NN/64);
    int px0 = (blk % (NN/64)) * 64;
#pragma unroll
    for (int k = 0; k < 8; k++) {
        int ch = k*4 + (tid >> 6);
        int px = tid & 63;
        s[ch][px] = x[(size_t)(b*32 + ch)*NN + px0 + px];
    }
    __syncthreads();
    float* xn = (float*)g_xnhwc4;
#pragma unroll
    for (int k = 0; k < 8; k++) {
        int px = k*8 + (tid >> 5);
        int ch = tid & 31;
        xn[(size_t)(b*NN + px0 + px)*32 + ch] = s[ch][px];
    }
}

// ---------------- fused deformable convs (k=3,5,7; groups=8) ----------------
template<int K, int PAD>
__device__ __forceinline__ void deform_one(const float* __restrict__ offp,
                                           const float* __restrict__ ws,
                                           const float* __restrict__ bsh,
                                           int yy, int xx, int b, int g, int p,
                                           int out0) {
    constexpr int K2 = K*K;
    float acc0 = 0.f, acc1 = 0.f, acc2 = 0.f, acc3 = 0.f;
    const float4* xb = g_xnhwc4 + (size_t)b*NN*8 + g;
    for (int k2 = 0; k2 < K2; k2++) {
        float dy = offp[(size_t)(2*k2)*NN];
        float dx = offp[(size_t)(2*k2+1)*NN];
        float py = (float)(yy - PAD + k2 / K) + dy;
        float px = (float)(xx - PAD + k2 % K) + dx;
        float y0f = floorf(py), x0f = floorf(px);
        float wy = py - y0f, wx = px - x0f;
        int y0 = (int)y0f, x0 = (int)x0f;
        float w00 = (1.f-wy)*(1.f-wx), w01 = (1.f-wy)*wx, w10 = wy*(1.f-wx), w11 = wy*wx;
        bool iy0 = (y0 >= 0 && y0 < HH), iy1 = (y0+1 >= 0 && y0+1 < HH);
        bool ix0 = (x0 >= 0 && x0 < WW), ix1 = (x0+1 >= 0 && x0+1 < WW);
        float4 s = make_float4(0.f, 0.f, 0.f, 0.f);
        if (iy0 && ix0) {
            float4 v = xb[(size_t)(y0*WW + x0)*8];
            s.x += w00*v.x; s.y += w00*v.y; s.z += w00*v.z; s.w += w00*v.w;
        }
        if (iy0 && ix1) {
            float4 v = xb[(size_t)(y0*WW + x0 + 1)*8];
            s.x += w01*v.x; s.y += w01*v.y; s.z += w01*v.z; s.w += w01*v.w;
        }
        if (iy1 && ix0) {
            float4 v = xb[(size_t)((y0+1)*WW + x0)*8];
            s.x += w10*v.x; s.y += w10*v.y; s.z += w10*v.z; s.w += w10*v.w;
        }
        if (iy1 && ix1) {
            float4 v = xb[(size_t)((y0+1)*WW + x0 + 1)*8];
            s.x += w11*v.x; s.y += w11*v.y; s.z += w11*v.z; s.w += w11*v.w;
        }
        acc0 += ws[(0*4+0)*K2+k2]*s.x + ws[(0*4+1)*K2+k2]*s.y + ws[(0*4+2)*K2+k2]*s.z + ws[(0*4+3)*K2+k2]*s.w;
        acc1 += ws[(1*4+0)*K2+k2]*s.x + ws[(1*4+1)*K2+k2]*s.y + ws[(1*4+2)*K2+k2]*s.z + ws[(1*4+3)*K2+k2]*s.w;
        acc2 += ws[(2*4+0)*K2+k2]*s.x + ws[(2*4+1)*K2+k2]*s.y + ws[(2*4+2)*K2+k2]*s.z + ws[(2*4+3)*K2+k2]*s.w;
        acc3 += ws[(3*4+0)*K2+k2]*s.x + ws[(3*4+1)*K2+k2]*s.y + ws[(3*4+2)*K2+k2]*s.z + ws[(3*4+3)*K2+k2]*s.w;
    }
    float* ob = g_catf + (size_t)(b*96 + out0 + g*4)*NN + p;
    ob[0*NN] = fmaxf(acc0 + bsh[0], 0.f);
    ob[1*NN] = fmaxf(acc1 + bsh[1], 0.f);
    ob[2*NN] = fmaxf(acc2 + bsh[2], 0.f);
    ob[3*NN] = fmaxf(acc3 + bsh[3], 0.f);
}

__global__ void k_deform_all(const float* __restrict__ w3, const float* __restrict__ b3,
                             const float* __restrict__ w5, const float* __restrict__ b5,
                             const float* __restrict__ w7, const float* __restrict__ b7) {
    __shared__ float ws[16*83];              // [w3 144 | w5 400 | w7 784]
    __shared__ float bsh[12];
    int tid = threadIdx.x;
    int gid = blockIdx.x*256 + tid;          // B*8*N
    int p = gid % NN;
    int g = (gid / NN) & 7;
    int b = gid / (8*NN);
    for (int i = tid; i < 144; i += 256) ws[i] = w3[g*144 + i];
    for (int i = tid; i < 400; i += 256) ws[144 + i] = w5[g*400 + i];
    for (int i = tid; i < 784; i += 256) ws[544 + i] = w7[g*784 + i];
    if (tid < 4)       bsh[tid]   = b3[g*4 + tid];
    else if (tid < 8)  bsh[tid]   = b5[g*4 + tid - 4];
    else if (tid < 12) bsh[tid]   = b7[g*4 + tid - 8];
    __syncthreads();
    int yy = p >> 7, xx = p & 127;
    const float* offbase = g_offs + (size_t)(b*166)*NN + p;
    deform_one<3,1>(offbase,                 ws,     bsh,    yy, xx, b, g, p, 0);
    deform_one<5,2>(offbase + (size_t)18*NN, ws+144, bsh+4,  yy, xx, b, g, p, 32);
    deform_one<7,3>(offbase + (size_t)68*NN, ws+544, bsh+8,  yy, xx, b, g, p, 64);
}

// ---------------- pointwise conv 96->32 with bias (4-way split) ----------------
__global__ void k_pw(const float* __restrict__ w, const float* __restrict__ bias) {
    __shared__ float ws[8*96];
    __shared__ float bs[8];
    int tid = threadIdx.x;
    int gid = blockIdx.x*256 + tid;          // B*4*N
    int p = gid % NN;
    int q = (gid / NN) & 3;
    int b = gid / (4*NN);
    for (int i = tid; i < 768; i += 256) ws[i] = w[(size_t)(q*8 + i/96)*96 + i%96];
    if (tid < 8) bs[tid] = bias[q*8 + tid];
    __syncthreads();
    float acc[8];
#pragma unroll
    for (int j = 0; j < 8; j++) acc[j] = bs[j];
    for (int c = 0; c < 96; c++) {
        float v = g_catf[(size_t)(b*96 + c)*NN + p];
#pragma unroll
        for (int j = 0; j < 8; j++) acc[j] += ws[j*96 + c]*v;
    }
#pragma unroll
    for (int j = 0; j < 8; j++) g_kfeat[(size_t)(b*32 + q*8 + j)*NN + p] = acc[j];
}

// ---------------- launch (kernel launches ONLY) ----------------
extern "C" void kernel_launch(void* const* d_in, const int* in_sizes, int n_in,
                              void* d_out, int out_size) {
    const float* x       = (const float*)d_in[0];
    const float* y       = (const float*)d_in[1];
    const float* temp    = (const float*)d_in[2];
    const float* w_po    = (const float*)d_in[3];
    const float* w_lp1   = (const float*)d_in[4];
    const float* w_lp2   = (const float*)d_in[5];
    const float* ln_g    = (const float*)d_in[6];
    const float* ln_b    = (const float*)d_in[7];
    const float* temp_in = (const float*)d_in[8];
    const float* w_qkv   = (const float*)d_in[9];
    const float* w_qkvd  = (const float*)d_in[10];
    const float* w_mproj = (const float*)d_in[11];
    const float* w_c3    = (const float*)d_in[12];
    const float* w_k2    = (const float*)d_in[13];
    const float* w_k3    = (const float*)d_in[14];
    const float* w_k4    = (const float*)d_in[15];
    const float* w_d3    = (const float*)d_in[16];
    const float* b_d3    = (const float*)d_in[17];
    const float* w_d5    = (const float*)d_in[18];
    const float* b_d5    = (const float*)d_in[19];
    const float* w_d7    = (const float*)d_in[20];
    const float* b_d7    = (const float*)d_in[21];
    const float* w_pw    = (const float*)d_in[22];
    const float* b_pw    = (const float*)d_in[23];

    // ---- staging / prepack ----
    k_prepack<<<dim3(128, 5), 256>>>(w_lp2, w_c3, w_k2, w_k3, w_k4);      // 0
    k_pool16<<<(BB*32*4096)/256, 256>>>(x, y);                             // 1
    k_pack_xy<<<(BB*32*NN)/256, 256>>>(x, y);                              // 2

    // ---- alignment branch ----
    // a = sigmoid(conv3x3(pool, w_k2, pad=0)) at 62x62
    k_conv3x3_tc<64,166,1, 2,32, 0,6, 0,166, 19008, 64,64,62,62, 0>
        <<<dim3(62, 6, BB), 256>>>();                                      // 3 <- profiled
    // bmid16 = conv3x3(concat(x,y), w_k3) * nearest_up(a)  (bf16 packed out)
    k_conv3x3_tc<64,166,2, 1,32, 1,3, 0,83, 76032, 128,128,128,128, 1>
        <<<dim3(HH, 6, BB), 256>>>();                                      // 4
    // offs = conv3x3(bmid16, w_k4)
    k_conv3x3_tc<166,166,0, 3,83, 0,8, 0,166, 133056, 128,128,128,128, 1>
        <<<dim3(HH, 6, BB), 256>>>();                                      // 5
    k_nhwc<<<(BB*NN)/64, 256>>>(x);                                        // 6
    k_deform_all<<<(BB*8*NN)/256, 256>>>(w_d3, b_d3, w_d5, b_d5, w_d7, b_d7); // 7
    k_pw<<<(BB*4*NN)/256, 256>>>(w_pw, b_pw);                              // 8

    // ---- prompt branch ----
    k_zero<<<1, 256>>>();                                                  // 9
    k_ln_l1_qkv<<<(BB*4*NN)/256, 256>>>(x, ln_g, ln_b, w_lp1, w_qkv);      // 10
    // l2 = conv3x3(x, w_lp2) -> cat96p16 cp16..31 (bf16 packed out)
    k_conv3x3_tc<32,32,0, 1,32, 1,4, 32,48, 0, 128,128,128,128, 1>
        <<<dim3(HH, 1, BB), 256>>>();                                      // 11
    k_qkvd<<<(BB*32*NN)/256, 256>>>(w_qkvd);                               // 12
    k_gramacc<0><<<BB*8*16, 256>>>(x);                                     // 13
    k_meffsm<0><<<BB, 1024>>>(w_mproj, temp_in);                           // 14
    k_apply<0><<<(BB*4*NN)/256, 256>>>(x, nullptr);                        // 15
    // prompt = conv3x3(cat96p16, w_c3)
    k_conv3x3_tc<96,32,0, 4,48, 0,11, 0,32, 4752, 128,128,128,128, 1>
        <<<dim3(HH, 1, BB), 256>>>();                                      // 16

    // ---- final prompted channel attention ----
    k_gramacc<1><<<BB*8*16, 256>>>(x);                                     // 17
    k_meffsm<1><<<BB, 1024>>>(w_po, temp);                                 // 18
    k_apply<1><<<(BB*4*NN)/256, 256>>>(x, (float*)d_out);                  // 19
}

// round 8
// speedup vs baseline: 2.7507x; 1.1068x over previous
#include <cuda_runtime.h>
#include <math.h>
#include <stdint.h>

#define BB 2
#define CCH 32
#define HH 128
#define WW 128
#define NN (HH*WW)
#define NHEADS 8

// ---------------- scratch (static device globals; no allocation) ----------------
__device__ float g_qkv[BB*96*NN];
__device__ float g_qkvd[BB*96*NN];     // q|k|v after grouped dwconv
__device__ float g_asmall[BB*166*62*62];
__device__ float g_offs[BB*166*NN];
__device__ float g_catf[BB*96*NN];     // [f3 | f5 | f7]
__device__ float g_kfeat[BB*CCH*NN];
__device__ float g_prompt[BB*CCH*NN];
__device__ float4 g_xnhwc4[BB*NN*8];   // x in NHWC, float4-grouped (16B aligned)
__device__ float g_stage_in[BB*8*24];  // dots[16] | q2[4] | k2[4]
__device__ float g_stage_f[BB*8*44];   // dots[32] | q2[8] | k2[4]
__device__ float g_Meff_in[BB*32*32];
__device__ float g_Meff_f[BB*32*32];

// bf16x2 pair-interleaved staging (u32 = channels (2c, 2c+1))
__device__ uint32_t g_xy16[BB*32*NN];      // cp 0..15 = x, 16..31 = y
__device__ uint32_t g_pool16[BB*32*64*64]; // pooled concat(x,y)
__device__ uint32_t g_bmid16[BB*83*NN];    // k3 output (166 ch -> 83 cp)
__device__ uint32_t g_cat96p16[BB*48*NN];  // [l1 cp0-15 | l2 cp16-31 | xg cp32-47]
__device__ uint32_t g_w16[289872];         // prepacked conv weights (sW image)

// compile-time scratch-buffer resolution
template<int ID> __device__ __forceinline__ float* gbuf();
template<> __device__ __forceinline__ float* gbuf<6>()  { return g_asmall; }
template<> __device__ __forceinline__ float* gbuf<8>()  { return g_offs; }
template<> __device__ __forceinline__ float* gbuf<11>() { return g_prompt; }
template<int ID> __device__ __forceinline__ uint32_t* gbufu();
template<> __device__ __forceinline__ uint32_t* gbufu<1>() { return g_xy16; }
template<> __device__ __forceinline__ uint32_t* gbufu<2>() { return g_pool16; }
template<> __device__ __forceinline__ uint32_t* gbufu<3>() { return g_bmid16; }
template<> __device__ __forceinline__ uint32_t* gbufu<4>() { return g_cat96p16; }

// ---------------- bf16 helpers ----------------
__device__ __forceinline__ uint32_t pack_bf16x2(float lo, float hi) {
    uint32_t r;
    asm("cvt.rn.bf16x2.f32 %0, %1, %2;" : "=r"(r) : "f"(hi), "f"(lo));
    return r;
}
__device__ __forceinline__ void mma_bf16(float* d, uint32_t a0, uint32_t a1,
                                         uint32_t a2, uint32_t a3,
                                         uint32_t b0, uint32_t b1) {
    asm volatile("mma.sync.aligned.m16n8k16.row.col.f32.bf16.bf16.f32 "
        "{%0,%1,%2,%3}, {%4,%5,%6,%7}, {%8,%9}, {%0,%1,%2,%3};\n"
        : "+f"(d[0]), "+f"(d[1]), "+f"(d[2]), "+f"(d[3])
        : "r"(a0), "r"(a1), "r"(a2), "r"(a3), "r"(b0), "r"(b1));
}

// ---------------- merged setup: prepack weights + pool16 + pack_xy + zero ----------------
// blockIdx.y: 0..4 = prepack conv, 5 = pool16 (+stage zero), 6 = pack_xy
__global__ void k_setup(const float* __restrict__ x, const float* __restrict__ y,
                        const float* __restrict__ w_lp2, const float* __restrict__ w_c3,
                        const float* __restrict__ w_k2, const float* __restrict__ w_k3,
                        const float* __restrict__ w_k4) {
    const int cy = blockIdx.y;
    const int tid0 = blockIdx.x*256 + threadIdx.x;
    const int stride = gridDim.x*256;
    if (cy < 5) {
        const int CINs[5]  = {32, 96, 64, 64, 166};
        const int COUTs[5] = {32, 32, 166, 166, 166};
        const int NCHs[5]  = {2, 6, 4, 4, 11};
        const int OCTs[5]  = {1, 1, 6, 6, 6};
        const int PERMs[5] = {1, 0, 0, 1, 0};
        const int OFFs[5]  = {0, 4752, 19008, 76032, 133056};
        const float* wsv[5] = {w_lp2, w_c3, w_k2, w_k3, w_k4};
        const int CIN = CINs[cy], COUT = COUTs[cy], NCH = NCHs[cy], PERM = PERMs[cy];
        const float* w = wsv[cy];
        const int total = OCTs[cy]*NCH*2376;
        for (int i = tid0; i < total; i += stride) {
            int within = i % 2376;
            int tile   = i / 2376;
            int oc = within % 33;
            int ck = within / 33;
            int k  = ck % 9;
            int cp = ck / 9;
            int chunk  = tile % NCH;
            int octile = tile / NCH;
            uint32_t val = 0;
            if (oc < 32) {
                int pc = PERM ? ((oc & 16) + 2*(oc & 7) + ((oc >> 3) & 1)) : oc;
                int chn = octile*32 + pc;
                int c0 = chunk*16 + 2*cp;
                float v0 = 0.f, v1 = 0.f;
                if (chn < COUT && c0 < CIN) {
                    v0 = w[((size_t)chn*CIN + c0)*9 + k];
                    v1 = w[((size_t)chn*CIN + c0 + 1)*9 + k];
                }
                val = pack_bf16x2(v0, v1);
            }
            g_w16[OFFs[cy] + i] = val;
        }
    } else if (cy == 5) {
        if (blockIdx.x == 0) {
            for (int i = threadIdx.x; i < BB*8*24; i += 256) g_stage_in[i] = 0.f;
            for (int i = threadIdx.x; i < BB*8*44; i += 256) g_stage_f[i] = 0.f;
        }
        for (int gid = tid0; gid < BB*32*4096; gid += stride) {
            int px = gid & 63;
            int py = (gid >> 6) & 63;
            int cp = (gid >> 12) & 31;
            int b  = gid >> 17;
            const float* s = (cp < 16) ? x + (size_t)(b*32 + 2*cp)*NN
                                       : y + (size_t)(b*32 + 2*(cp-16))*NN;
            int iy = 2*py, ix = 2*px;
            float v0 = 0.25f*(s[iy*WW+ix] + s[iy*WW+ix+1] + s[(iy+1)*WW+ix] + s[(iy+1)*WW+ix+1]);
            const float* s1 = s + NN;
            float v1 = 0.25f*(s1[iy*WW+ix] + s1[iy*WW+ix+1] + s1[(iy+1)*WW+ix] + s1[(iy+1)*WW+ix+1]);
            g_pool16[(size_t)(b*32 + cp)*4096 + py*64 + px] = pack_bf16x2(v0, v1);
        }
    } else {
        for (int gid = tid0; gid < BB*32*NN; gid += stride) {
            int p = gid % NN;
            int cp = (gid / NN) % 32;
            int b = gid / (32*NN);
            const float* s = (cp < 16) ? x + (size_t)(b*32 + 2*cp)*NN
                                       : y + (size_t)(b*32 + 2*(cp-16))*NN;
            g_xy16[(size_t)(b*32 + cp)*NN + p] = pack_bf16x2(s[p], s[NN + p]);
        }
    }
}

// ---------------- tensor-core conv3x3, bf16 m16n8k16, packed I/O, 2-row tile ----------------
// EPI: 0 plain, 1 sigmoid, 2 multiply by nearest-upsampled sigmoid aux (g_asmall)
// OUT16=1: write bf16x2 pairs (channel-permuted weights); else fp32 NCHW.
template<int CIN, int COUT, int EPI, int SRCU, int CPTOT, int OUT16, int DSTID,
         int OUTC0, int OUTCTOT, int W16OFF,
         int HIN, int WIN, int HOUT, int WOUT, int PAD>
__global__ void k_conv3x3_tc() {
    constexpr int CP = CIN/2;
    constexpr int NCHUNK = (CP + 7) / 8;
    const uint32_t* src16 = gbufu<SRCU>();
    __shared__ uint32_t sIn[8*4*132];        // [cp][row(4)][px], px 0..131 -> gx = px-PAD
    __shared__ uint32_t sW[2376];            // [(cp*9+k)*33 + oc]
    const int y0  = blockIdx.x * 2;          // first output row of this block
    const int oc0 = blockIdx.y * 32;
    const int b   = blockIdx.z;
    const int tid = threadIdx.x;
    const int lane = tid & 31, wid5 = tid >> 5;
    const int wm = wid5 >> 2, wn = wid5 & 3;
    const int g = lane >> 2, tg = lane & 3;

    float acc[2][4][4];
#pragma unroll
    for (int yo = 0; yo < 2; yo++)
#pragma unroll
        for (int t = 0; t < 4; t++)
#pragma unroll
            for (int r = 0; r < 4; r++) acc[yo][t][r] = 0.f;

    const uint32_t* wbase = g_w16 + W16OFF + (size_t)(oc0 >> 5)*NCHUNK*2376;
    for (int ch = 0; ch < NCHUNK; ch++) {
        // ---- input fill: warp = one cp plane, rows y0-PAD .. y0-PAD+3 ----
        {
            int cpg = ch*8 + wid5;
            bool cpv = cpg < CP;
            const uint32_t* sp = src16 + (size_t)(b*CPTOT + cpg)*(HIN*WIN);
#pragma unroll
            for (int row = 0; row < 4; row++) {
                int gy = y0 - PAD + row;
                bool yv = cpv && ((unsigned)gy < (unsigned)HIN);
                const uint32_t* rp = sp + gy*WIN;
                uint32_t* sd = sIn + (wid5*4 + row)*132;
#pragma unroll
                for (int kk = 0; kk < 4; kk++) {
                    int px = lane + 32*kk;
                    int gx = px - PAD;
                    uint32_t v = 0;
                    if (yv && (unsigned)gx < (unsigned)WIN) v = rp[gx];
                    sd[px] = v;
                }
                if (lane < 4) {
                    int px = 128 + lane;
                    int gx = px - PAD;
                    uint32_t v = 0;
                    if (yv && (unsigned)gx < (unsigned)WIN) v = rp[gx];
                    sd[px] = v;
                }
            }
        }
        // ---- weight fill: straight copy of prepacked image ----
        {
            const uint32_t* wp = wbase + ch*2376;
            for (int i = tid; i < 2376; i += 256) sW[i] = wp[i];
        }
        __syncthreads();
        // ---- 9 shifted GEMMs x 2 output rows, K=16 each ----
#pragma unroll
        for (int kpos = 0; kpos < 9; kpos++) {
            const int ky = kpos / 3, kx = kpos % 3;
            const int aoc = wm*16 + g;
            uint32_t a0 = sW[(tg*9 + kpos)*33 + aoc];
            uint32_t a1 = sW[(tg*9 + kpos)*33 + aoc + 8];
            uint32_t a2 = sW[((tg+4)*9 + kpos)*33 + aoc];
            uint32_t a3 = sW[((tg+4)*9 + kpos)*33 + aoc + 8];
#pragma unroll
            for (int yo = 0; yo < 2; yo++) {
                const int r0 = (tg*4 + yo + ky)*132 + kx;
                const int r1 = ((tg+4)*4 + yo + ky)*132 + kx;
#pragma unroll
                for (int t = 0; t < 4; t++) {
                    int px = wn*32 + t*8 + g;
                    mma_bf16(acc[yo][t], a0, a1, a2, a3, sIn[r0 + px], sIn[r1 + px]);
                }
            }
        }
        __syncthreads();
    }
    // ---- epilogue (2 rows) ----
#pragma unroll
    for (int yo = 0; yo < 2; yo++) {
        const int y = y0 + yo;
        if (OUT16) {
            // weights were permuted: acc rows (g, g+8) = adjacent channels (2g, 2g+1)
            int chan0 = oc0 + wm*16 + 2*g;
            if (chan0 < COUT) {
                uint32_t* op = gbufu<OUT16 ? DSTID : 1>()
                    + (size_t)(b*OUTCTOT + (OUTC0 + chan0)/2)*(HOUT*WOUT) + (size_t)y*WOUT;
#pragma unroll
                for (int t = 0; t < 4; t++) {
                    int px = wn*32 + t*8 + 2*tg;
                    float v00 = acc[yo][t][0], v01 = acc[yo][t][1];
                    float v10 = acc[yo][t][2], v11 = acc[yo][t][3];
                    if (EPI == 2) {
                        int ay = (y * 62) >> 7;
                        int ax0 = (px * 62) >> 7, ax1 = ((px+1) * 62) >> 7;
                        const float* a0p = g_asmall + ((size_t)(b*166 + chan0)*62 + ay)*62;
                        const float* a1p = a0p + 62*62;
                        v00 *= a0p[ax0]; v01 *= a0p[ax1];
                        v10 *= a1p[ax0]; v11 *= a1p[ax1];
                    }
                    op[px]   = pack_bf16x2(v00, v10);
                    op[px+1] = pack_bf16x2(v01, v11);
                }
            }
        } else {
            float* dst = gbuf<OUT16 ? 11 : DSTID>();
            const int ocr0 = oc0 + wm*16 + g;
#pragma unroll
            for (int t = 0; t < 4; t++) {
                int px = wn*32 + t*8 + 2*tg;
#pragma unroll
                for (int half = 0; half < 2; half++) {
                    int ocr = ocr0 + half*8;
                    if (ocr >= COUT) continue;
                    float v0 = acc[yo][t][half*2 + 0];
                    float v1 = acc[yo][t][half*2 + 1];
                    if (EPI == 1) {
                        v0 = 1.f / (1.f + expf(-v0));
                        v1 = 1.f / (1.f + expf(-v1));
                    }
                    float* opf = dst + (size_t)(b*OUTCTOT + OUTC0 + ocr)*(HOUT*WOUT) + (size_t)y*WOUT;
                    if (px   < WOUT) opf[px]   = v0;
                    if (px+1 < WOUT) opf[px+1] = v1;
                }
            }
        }
    }
}

// ---------------- fused LayerNorm + l1 + qkv (4-way channel split) ----------------
// q=0: l1 -> g_cat96p16 cp0..15 (packed); q=1..3: qkv rows -> g_qkv fp32
__global__ void k_ln_l1_qkv(const float* __restrict__ x, const float* __restrict__ ln_g,
                            const float* __restrict__ ln_b, const float* __restrict__ w_lp1,
                            const float* __restrict__ w_qkv) {
    __shared__ float sw[32*32];
    __shared__ float s_g[32], s_b[32];
    int tid = threadIdx.x;
    int gid = blockIdx.x*256 + tid;          // B*4*N
    int p = gid % NN;
    int q = (gid / NN) & 3;
    int b = gid / (4*NN);
    const float* wsrc = (q == 0) ? w_lp1 : w_qkv + (size_t)(q-1)*1024;
    for (int i = tid; i < 1024; i += 256) sw[i] = wsrc[i];
    if (tid < 32) { s_g[tid] = ln_g[tid]; s_b[tid] = ln_b[tid]; }
    __syncthreads();
    float xv[32];
#pragma unroll
    for (int c = 0; c < 32; c++) xv[c] = x[(size_t)(b*32 + c)*NN + p];
    if (q == 0) {
#pragma unroll
        for (int m = 0; m < 16; m++) {
            float a0 = 0.f, a1 = 0.f;
#pragma unroll
            for (int c = 0; c < 32; c++) {
                a0 += sw[(2*m)*32 + c]*xv[c];
                a1 += sw[(2*m+1)*32 + c]*xv[c];
            }
            g_cat96p16[(size_t)(b*48 + m)*NN + p] = pack_bf16x2(a0, a1);
        }
    } else {
        float mu = 0.f;
#pragma unroll
        for (int c = 0; c < 32; c++) mu += xv[c];
        mu *= (1.f/32.f);
        float var = 0.f;
#pragma unroll
        for (int c = 0; c < 32; c++) { float d = xv[c]-mu; var += d*d; }
        var *= (1.f/32.f);
        float inv = rsqrtf(var + 1e-5f);
        float vin[32];
#pragma unroll
        for (int c = 0; c < 32; c++) vin[c] = (xv[c]-mu)*inv*s_g[c] + s_b[c];
        float* outbase = g_qkv + (size_t)(b*96 + (q-1)*32)*NN;
        for (int o = 0; o < 32; o++) {
            float a = 0.f;
#pragma unroll
            for (int c = 0; c < 32; c++) a += sw[o*32+c]*vin[c];
            outbase[(size_t)o*NN + p] = a;
        }
    }
}

// ---------------- grouped 3x3 conv (96 ch, groups=32, in/out 3 per group) ----------------
__global__ void k_qkvd(const float* __restrict__ w) {
    __shared__ float ws[96*27];
    int tid = threadIdx.x;
    for (int i = tid; i < 96*27; i += 256) ws[i] = w[i];
    __syncthreads();
    int gid = blockIdx.x*256 + tid;
    int p = gid % NN;
    int g = (gid / NN) % 32;
    int b = gid / (32*NN);
    int y = p >> 7, xx = p & 127;
    float a0 = 0.f, a1 = 0.f, a2 = 0.f;
    const float* inb = g_qkv + (size_t)(b*96 + 3*g)*NN;
#pragma unroll
    for (int ky = 0; ky < 3; ky++) {
        int gy = y - 1 + ky;
        if (gy < 0 || gy >= HH) continue;
#pragma unroll
        for (int kx = 0; kx < 3; kx++) {
            int gx = xx - 1 + kx;
            if (gx < 0 || gx >= WW) continue;
            int kk = ky*3 + kx;
#pragma unroll
            for (int ci = 0; ci < 3; ci++) {
                float v = inb[ci*NN + gy*WW + gx];
                a0 += ws[(3*g+0)*27 + ci*9 + kk]*v;
                a1 += ws[(3*g+1)*27 + ci*9 + kk]*v;
                a2 += ws[(3*g+2)*27 + ci*9 + kk]*v;
            }
        }
    }
    g_qkvd[(size_t)(b*96 + 3*g+0)*NN + p] = a0;
    g_qkvd[(size_t)(b*96 + 3*g+1)*NN + p] = a1;
    g_qkvd[(size_t)(b*96 + 3*g+2)*NN + p] = a2;
}

// ---------------- sliced gram accumulate (dots + squared norms) ----------------
template<int MODE>
__global__ void k_gramacc(const float* __restrict__ xin) {
    constexpr int D = (MODE == 0) ? 4 : 8;
    constexpr int E = 4;
    constexpr int NS = D*E + D + E;          // 24 or 44
    constexpr int SL = 16;
    int bid = blockIdx.x;                    // BB*8*16
    int slice = bid & 15;
    int h = (bid >> 4) & 7;
    int b = bid >> 7;
    int tid = threadIdx.x;
    const float* qbase;
    if (MODE == 0) qbase = g_qkvd + (size_t)(b*96 + h*D)*NN;
    else qbase = (h < 4) ? xin + (size_t)(b*32 + h*8)*NN
                         : g_prompt + (size_t)(b*32 + (h-4)*8)*NN;
    const float* kbase = (MODE == 0) ? g_qkvd + (size_t)(b*96 + 32 + h*E)*NN
                                     : g_kfeat + (size_t)(b*32 + h*E)*NN;
    float acc[NS];
#pragma unroll
    for (int i = 0; i < NS; i++) acc[i] = 0.f;
    int n0 = slice * (NN/SL);
    for (int it = 0; it < (NN/SL)/256; it++) {
        int n = n0 + it*256 + tid;
        float qv[D], kv[E];
#pragma unroll
        for (int d = 0; d < D; d++) qv[d] = qbase[(size_t)d*NN + n];
#pragma unroll
        for (int e = 0; e < E; e++) kv[e] = kbase[(size_t)e*NN + n];
#pragma unroll
        for (int d = 0; d < D; d++)
#pragma unroll
            for (int e = 0; e < E; e++) acc[d*E+e] += qv[d]*kv[e];
#pragma unroll
        for (int d = 0; d < D; d++) acc[D*E + d] += qv[d]*qv[d];
#pragma unroll
        for (int e = 0; e < E; e++) acc[D*E + D + e] += kv[e]*kv[e];
    }
    __shared__ float red[NS];
    if (tid < NS) red[tid] = 0.f;
    __syncthreads();
    int lane = tid & 31;
#pragma unroll
    for (int i = 0; i < NS; i++) {
        float v = acc[i];
#pragma unroll
        for (int o = 16; o > 0; o >>= 1) v += __shfl_down_sync(0xffffffffu, v, o);
        if (lane == 0) atomicAdd(&red[i], v);
    }
    __syncthreads();
    float* st = (MODE == 0) ? g_stage_in + (b*8 + h)*24 : g_stage_f + (b*8 + h)*44;
    if (tid < NS) atomicAdd(&st[tid], red[tid]);
}

// ---------------- softmax + fold with 1x1 conv weights -> Meff ----------------
template<int MODE>
__global__ void k_meffsm(const float* __restrict__ wmat, const float* __restrict__ tempv) {
    constexpr int D = (MODE == 0) ? 4 : 8;
    int b = blockIdx.x;
    int t = threadIdx.x;                     // 1024 threads
    __shared__ float sA[8*D*4];
    if (t < 8*D) {
        int h = t / D, d = t % D;
        const float* st = (MODE == 0) ? g_stage_in + (b*8 + h)*24 : g_stage_f + (b*8 + h)*44;
        float qn = fmaxf(sqrtf(st[D*4 + d]), 1e-12f);
        float tp = tempv[h];
        float row[4];
        float mx = -1e30f;
#pragma unroll
        for (int e = 0; e < 4; e++) {
            float kn = fmaxf(sqrtf(st[D*4 + D + e]), 1e-12f);
            row[e] = st[d*4+e] / (qn*kn) * tp;
            mx = fmaxf(mx, row[e]);
        }
        float sum = 0.f;
#pragma unroll
        for (int e = 0; e < 4; e++) { row[e] = expf(row[e]-mx); sum += row[e]; }
        float isum = 1.f/sum;
#pragma unroll
        for (int e = 0; e < 4; e++) sA[(h*D + d)*4 + e] = row[e]*isum;
    }
    __syncthreads();
    int o = t >> 5, vc = t & 31, h = vc >> 2, e = vc & 3;
    float s = 0.f;
#pragma unroll
    for (int d = 0; d < D; d++)
        s += wmat[o*(8*D) + h*D + d] * sA[(h*D + d)*4 + e];
    float* M = (MODE == 0) ? g_Meff_in : g_Meff_f;
    M[b*1024 + o*32 + vc] = s;
}

// ---------------- per-pixel 32x32 matmul apply (4-way channel split) ----------------
// MODE 0: in=g_qkvd ch64..95, M=g_Meff_in, resid=x -> g_cat96p16 cp32..47 (packed)
// MODE 1: in=x, M=g_Meff_f -> outp fp32
template<int MODE>
__global__ void k_apply(const float* __restrict__ xin, float* __restrict__ outp) {
    __shared__ float sm[256];
    int tid = threadIdx.x;
    int gid = blockIdx.x*256 + tid;          // B*4*N
    int p = gid % NN;
    int q = (gid / NN) & 3;
    int b = gid / (4*NN);
    const float* M = (MODE == 0) ? g_Meff_in : g_Meff_f;
    if (tid < 256) sm[tid] = M[b*1024 + q*256 + tid];
    __syncthreads();
    float vv[32];
#pragma unroll
    for (int c = 0; c < 32; c++) {
        if (MODE == 0) vv[c] = g_qkvd[(size_t)(b*96 + 64 + c)*NN + p];
        else           vv[c] = xin[(size_t)(b*32 + c)*NN + p];
    }
    float av[8];
#pragma unroll
    for (int j = 0; j < 8; j++) {
        int o = q*8 + j;
        float a = (MODE == 0) ? xin[(size_t)(b*32 + o)*NN + p] : 0.f;
#pragma unroll
        for (int c = 0; c < 32; c++) a += sm[j*32+c]*vv[c];
        av[j] = a;
    }
    if (MODE == 0) {
#pragma unroll
        for (int m = 0; m < 4; m++)
            g_cat96p16[(size_t)(b*48 + 32 + q*4 + m)*NN + p] = pack_bf16x2(av[2*m], av[2*m+1]);
    } else {
#pragma unroll
        for (int j = 0; j < 8; j++)
            outp[(size_t)(b*32 + q*8 + j)*NN + p] = av[j];
    }
}

// ---------------- NCHW -> NHWC(float4 groups) transpose of x ----------------
__global__ void k_nhwc(const float* __restrict__ x) {
    __shared__ float s[32][65];
    int tid = threadIdx.x;
    int blk = blockIdx.x;                    // B*NN/64
    int b = blk / (NN/64);
    int px0 = (blk % (NN/64)) * 64;
#pragma unroll
    for (int k = 0; k < 8; k++) {
        int ch = k*4 + (tid >> 6);
        int px = tid & 63;
        s[ch][px] = x[(size_t)(b*32 + ch)*NN + px0 + px];
    }
    __syncthreads();
    float* xn = (float*)g_xnhwc4;
#pragma unroll
    for (int k = 0; k < 8; k++) {
        int px = k*8 + (tid >> 5);
        int ch = tid & 31;
        xn[(size_t)(b*NN + px0 + px)*32 + ch] = s[ch][px];
    }
}

// ---------------- fused deformable convs (k=3,5,7; groups=8) ----------------
template<int K, int PAD>
__device__ __forceinline__ void deform_one(const float* __restrict__ offp,
                                           const float* __restrict__ ws,
                                           const float* __restrict__ bsh,
                                           int yy, int xx, int b, int g, int p,
                                           int out0) {
    constexpr int K2 = K*K;
    float acc0 = 0.f, acc1 = 0.f, acc2 = 0.f, acc3 = 0.f;
    const float4* xb = g_xnhwc4 + (size_t)b*NN*8 + g;
    for (int k2 = 0; k2 < K2; k2++) {
        float dy = offp[(size_t)(2*k2)*NN];
        float dx = offp[(size_t)(2*k2+1)*NN];
        float py = (float)(yy - PAD + k2 / K) + dy;
        float px = (float)(xx - PAD + k2 % K) + dx;
        float y0f = floorf(py), x0f = floorf(px);
        float wy = py - y0f, wx = px - x0f;
        int y0 = (int)y0f, x0 = (int)x0f;
        float w00 = (1.f-wy)*(1.f-wx), w01 = (1.f-wy)*wx, w10 = wy*(1.f-wx), w11 = wy*wx;
        bool iy0 = (y0 >= 0 && y0 < HH), iy1 = (y0+1 >= 0 && y0+1 < HH);
        bool ix0 = (x0 >= 0 && x0 < WW), ix1 = (x0+1 >= 0 && x0+1 < WW);
        float4 s = make_float4(0.f, 0.f, 0.f, 0.f);
        if (iy0 && ix0) {
            float4 v = xb[(size_t)(y0*WW + x0)*8];
            s.x += w00*v.x; s.y += w00*v.y; s.z += w00*v.z; s.w += w00*v.w;
        }
        if (iy0 && ix1) {
            float4 v = xb[(size_t)(y0*WW + x0 + 1)*8];
            s.x += w01*v.x; s.y += w01*v.y; s.z += w01*v.z; s.w += w01*v.w;
        }
        if (iy1 && ix0) {
            float4 v = xb[(size_t)((y0+1)*WW + x0)*8];
            s.x += w10*v.x; s.y += w10*v.y; s.z += w10*v.z; s.w += w10*v.w;
        }
        if (iy1 && ix1) {
            float4 v = xb[(size_t)((y0+1)*WW + x0 + 1)*8];
            s.x += w11*v.x; s.y += w11*v.y; s.z += w11*v.z; s.w += w11*v.w;
        }
        acc0 += ws[(0*4+0)*K2+k2]*s.x + ws[(0*4+1)*K2+k2]*s.y + ws[(0*4+2)*K2+k2]*s.z + ws[(0*4+3)*K2+k2]*s.w;
        acc1 += ws[(1*4+0)*K2+k2]*s.x + ws[(1*4+1)*K2+k2]*s.y + ws[(1*4+2)*K2+k2]*s.z + ws[(1*4+3)*K2+k2]*s.w;
        acc2 += ws[(2*4+0)*K2+k2]*s.x + ws[(2*4+1)*K2+k2]*s.y + ws[(2*4+2)*K2+k2]*s.z + ws[(2*4+3)*K2+k2]*s.w;
        acc3 += ws[(3*4+0)*K2+k2]*s.x + ws[(3*4+1)*K2+k2]*s.y + ws[(3*4+2)*K2+k2]*s.z + ws[(3*4+3)*K2+k2]*s.w;
    }
    float* ob = g_catf + (size_t)(b*96 + out0 + g*4)*NN + p;
    ob[0*NN] = fmaxf(acc0 + bsh[0], 0.f);
    ob[1*NN] = fmaxf(acc1 + bsh[1], 0.f);
    ob[2*NN] = fmaxf(acc2 + bsh[2], 0.f);
    ob[3*NN] = fmaxf(acc3 + bsh[3], 0.f);
}

__global__ void k_deform_all(const float* __restrict__ w3, const float* __restrict__ b3,
                             const float* __restrict__ w5, const float* __restrict__ b5,
                             const float* __restrict__ w7, const float* __restrict__ b7) {
    __shared__ float ws[16*83];              // [w3 144 | w5 400 | w7 784]
    __shared__ float bsh[12];
    int tid = threadIdx.x;
    int gid = blockIdx.x*256 + tid;          // B*8*N
    int p = gid % NN;
    int g = (gid / NN) & 7;
    int b = gid / (8*NN);
    for (int i = tid; i < 144; i += 256) ws[i] = w3[g*144 + i];
    for (int i = tid; i < 400; i += 256) ws[144 + i] = w5[g*400 + i];
    for (int i = tid; i < 784; i += 256) ws[544 + i] = w7[g*784 + i];
    if (tid < 4)       bsh[tid]   = b3[g*4 + tid];
    else if (tid < 8)  bsh[tid]   = b5[g*4 + tid - 4];
    else if (tid < 12) bsh[tid]   = b7[g*4 + tid - 8];
    __syncthreads();
    int yy = p >> 7, xx = p & 127;
    const float* offbase = g_offs + (size_t)(b*166)*NN + p;
    deform_one<3,1>(offbase,                 ws,     bsh,    yy, xx, b, g, p, 0);
    deform_one<5,2>(offbase + (size_t)18*NN, ws+144, bsh+4,  yy, xx, b, g, p, 32);
    deform_one<7,3>(offbase + (size_t)68*NN, ws+544, bsh+8,  yy, xx, b, g, p, 64);
}

// ---------------- pointwise conv 96->32 with bias (4-way split) ----------------
__global__ void k_pw(const float* __restrict__ w, const float* __restrict__ bias) {
    __shared__ float ws[8*96];
    __shared__ float bs[8];
    int tid = threadIdx.x;
    int gid = blockIdx.x*256 + tid;          // B*4*N
    int p = gid % NN;
    int q = (gid / NN) & 3;
    int b = gid / (4*NN);
    for (int i = tid; i < 768; i += 256) ws[i] = w[(size_t)(q*8 + i/96)*96 + i%96];
    if (tid < 8) bs[tid] = bias[q*8 + tid];
    __syncthreads();
    float acc[8];
#pragma unroll
    for (int j = 0; j < 8; j++) acc[j] = bs[j];
    for (int c = 0; c < 96; c++) {
        float v = g_catf[(size_t)(b*96 + c)*NN + p];
#pragma unroll
        for (int j = 0; j < 8; j++) acc[j] += ws[j*96 + c]*v;
    }
#pragma unroll
    for (int j = 0; j < 8; j++) g_kfeat[(size_t)(b*32 + q*8 + j)*NN + p] = acc[j];
}

// ---------------- launch (kernel launches ONLY) ----------------
extern "C" void kernel_launch(void* const* d_in, const int* in_sizes, int n_in,
                              void* d_out, int out_size) {
    const float* x       = (const float*)d_in[0];
    const float* y       = (const float*)d_in[1];
    const float* temp    = (const float*)d_in[2];
    const float* w_po    = (const float*)d_in[3];
    const float* w_lp1   = (const float*)d_in[4];
    const float* w_lp2   = (const float*)d_in[5];
    const float* ln_g    = (const float*)d_in[6];
    const float* ln_b    = (const float*)d_in[7];
    const float* temp_in = (const float*)d_in[8];
    const float* w_qkv   = (const float*)d_in[9];
    const float* w_qkvd  = (const float*)d_in[10];
    const float* w_mproj = (const float*)d_in[11];
    const float* w_c3    = (const float*)d_in[12];
    const float* w_k2    = (const float*)d_in[13];
    const float* w_k3    = (const float*)d_in[14];
    const float* w_k4    = (const float*)d_in[15];
    const float* w_d3    = (const float*)d_in[16];
    const float* b_d3    = (const float*)d_in[17];
    const float* w_d5    = (const float*)d_in[18];
    const float* b_d5    = (const float*)d_in[19];
    const float* w_d7    = (const float*)d_in[20];
    const float* b_d7    = (const float*)d_in[21];
    const float* w_pw    = (const float*)d_in[22];
    const float* b_pw    = (const float*)d_in[23];

    // ---- merged setup (prepack + pool16 + pack_xy + stage zero) ----
    k_setup<<<dim3(256, 7), 256>>>(x, y, w_lp2, w_c3, w_k2, w_k3, w_k4);   // 0

    // ---- alignment branch ----
    // a = sigmoid(conv3x3(pool, w_k2, pad=0)) at 62x62
    k_conv3x3_tc<64,166,1, 2,32, 0,6, 0,166, 19008, 64,64,62,62, 0>
        <<<dim3(31, 6, BB), 256>>>();                                      // 1
    // bmid16 = conv3x3(concat(x,y), w_k3) * nearest_up(a)  (bf16 packed out)
    k_conv3x3_tc<64,166,2, 1,32, 1,3, 0,83, 76032, 128,128,128,128, 1>
        <<<dim3(64, 6, BB), 256>>>();                                      // 2
    // offs = conv3x3(bmid16, w_k4)
    k_conv3x3_tc<166,166,0, 3,83, 0,8, 0,166, 133056, 128,128,128,128, 1>
        <<<dim3(64, 6, BB), 256>>>();                                      // 3 <- profiled
    k_nhwc<<<(BB*NN)/64, 256>>>(x);                                        // 4
    k_deform_all<<<(BB*8*NN)/256, 256>>>(w_d3, b_d3, w_d5, b_d5, w_d7, b_d7); // 5
    k_pw<<<(BB*4*NN)/256, 256>>>(w_pw, b_pw);                              // 6

    // ---- prompt branch ----
    k_ln_l1_qkv<<<(BB*4*NN)/256, 256>>>(x, ln_g, ln_b, w_lp1, w_qkv);      // 7
    // l2 = conv3x3(x, w_lp2) -> cat96p16 cp16..31 (bf16 packed out)
    k_conv3x3_tc<32,32,0, 1,32, 1,4, 32,48, 0, 128,128,128,128, 1>
        <<<dim3(64, 1, BB), 256>>>();                                      // 8
    k_qkvd<<<(BB*32*NN)/256, 256>>>(w_qkvd);                               // 9
    k_gramacc<0><<<BB*8*16, 256>>>(x);                                     // 10
    k_meffsm<0><<<BB, 1024>>>(w_mproj, temp_in);                           // 11
    k_apply<0><<<(BB*4*NN)/256, 256>>>(x, nullptr);                        // 12
    // prompt = conv3x3(cat96p16, w_c3)
    k_conv3x3_tc<96,32,0, 4,48, 0,11, 0,32, 4752, 128,128,128,128, 1>
        <<<dim3(64, 1, BB), 256>>>();                                      // 13

    // ---- final prompted channel attention ----
    k_gramacc<1><<<BB*8*16, 256>>>(x);                                     // 14
    k_meffsm<1><<<BB, 1024>>>(w_po, temp);                                 // 15
    k_apply<1><<<(BB*4*NN)/256, 256>>>(x, (float*)d_out);                  // 16
}

// round 10
// speedup vs baseline: 2.7632x; 1.0045x over previous
#include <cuda_runtime.h>
#include <math.h>
#include <stdint.h>

#define BB 2
#define CCH 32
#define HH 128
#define WW 128
#define NN (HH*WW)
#define NHEADS 8

// ---------------- scratch (static device globals; no allocation) ----------------
__device__ float g_qkv[BB*96*NN];
__device__ float g_qkvd[BB*96*NN];     // q|k|v after grouped dwconv
__device__ float g_asmall[BB*166*62*62];
__device__ float2 g_offs2[BB*83*NN];   // k4 output: (dy,dx) float2 planes
__device__ float g_catf[BB*96*NN];     // [f3 | f5 | f7]
__device__ float g_kfeat[BB*CCH*NN];
__device__ float g_prompt[BB*CCH*NN];
__device__ float4 g_xnhwc4[BB*NN*8];   // x in NHWC, float4-grouped (16B aligned)
__device__ float g_stage_in[BB*8*24];  // dots[16] | q2[4] | k2[4]
__device__ float g_stage_f[BB*8*44];   // dots[32] | q2[8] | k2[4]
__device__ float g_Meff_in[BB*32*32];
__device__ float g_Meff_f[BB*32*32];

// bf16x2 pair-interleaved staging (u32 = channels (2c, 2c+1))
__device__ uint32_t g_xy16[BB*32*NN];      // cp 0..15 = x, 16..31 = y
__device__ uint32_t g_pool16[BB*32*64*64]; // pooled concat(x,y)
__device__ uint32_t g_bmid16[BB*83*NN];    // k3 output (166 ch -> 83 cp)
__device__ uint32_t g_cat96p16[BB*48*NN];  // [l1 cp0-15 | l2 cp16-31 | xg cp32-47]
__device__ uint32_t g_w16[351360];         // prepacked conv weights (sW image, pitch 40)

// compile-time scratch-buffer resolution
template<int ID> __device__ __forceinline__ float* gbuf();
template<> __device__ __forceinline__ float* gbuf<6>()  { return g_asmall; }
template<> __device__ __forceinline__ float* gbuf<11>() { return g_prompt; }
template<int ID> __device__ __forceinline__ uint32_t* gbufu();
template<> __device__ __forceinline__ uint32_t* gbufu<1>() { return g_xy16; }
template<> __device__ __forceinline__ uint32_t* gbufu<2>() { return g_pool16; }
template<> __device__ __forceinline__ uint32_t* gbufu<3>() { return g_bmid16; }
template<> __device__ __forceinline__ uint32_t* gbufu<4>() { return g_cat96p16; }

// ---------------- bf16 helpers ----------------
__device__ __forceinline__ uint32_t pack_bf16x2(float lo, float hi) {
    uint32_t r;
    asm("cvt.rn.bf16x2.f32 %0, %1, %2;" : "=r"(r) : "f"(hi), "f"(lo));
    return r;
}
__device__ __forceinline__ void mma_bf16(float* d, uint32_t a0, uint32_t a1,
                                         uint32_t a2, uint32_t a3,
                                         uint32_t b0, uint32_t b1) {
    asm volatile("mma.sync.aligned.m16n8k16.row.col.f32.bf16.bf16.f32 "
        "{%0,%1,%2,%3}, {%4,%5,%6,%7}, {%8,%9}, {%0,%1,%2,%3};\n"
        : "+f"(d[0]), "+f"(d[1]), "+f"(d[2]), "+f"(d[3])
        : "r"(a0), "r"(a1), "r"(a2), "r"(a3), "r"(b0), "r"(b1));
}

// ---------------- merged setup ----------------
// blockIdx.y: 0..4 = prepack conv, 5 = pool16 (+stage zero), 6 = pack_xy, 7 = nhwc
__global__ void k_setup(const float* __restrict__ x, const float* __restrict__ y,
                        const float* __restrict__ w_lp2, const float* __restrict__ w_c3,
                        const float* __restrict__ w_k2, const float* __restrict__ w_k3,
                        const float* __restrict__ w_k4) {
    __shared__ float s[32][65];
    const int cy = blockIdx.y;
    const int tid0 = blockIdx.x*256 + threadIdx.x;
    const int stride = gridDim.x*256;
    if (cy < 5) {
        const int CINs[5]  = {32, 96, 64, 64, 166};
        const int COUTs[5] = {32, 32, 166, 166, 166};
        const int NCHs[5]  = {2, 6, 4, 4, 11};
        const int OCTs[5]  = {1, 1, 6, 6, 6};
        const int PERMs[5] = {1, 0, 0, 1, 1};
        const int OFFs[5]  = {0, 5760, 23040, 92160, 161280};
        const float* wsv[5] = {w_lp2, w_c3, w_k2, w_k3, w_k4};
        const int CIN = CINs[cy], COUT = COUTs[cy], NCH = NCHs[cy], PERM = PERMs[cy];
        const float* w = wsv[cy];
        const int total = OCTs[cy]*NCH*2880;
        for (int i = tid0; i < total; i += stride) {
            int within = i % 2880;
            int tile   = i / 2880;
            int oc = within % 40;
            int ck = within / 40;
            int k  = ck % 9;
            int cp = ck / 9;
            int chunk  = tile % NCH;
            int octile = tile / NCH;
            uint32_t val = 0;
            if (oc < 32) {
                int pc = PERM ? ((oc & 16) + 2*(oc & 7) + ((oc >> 3) & 1)) : oc;
                int chn = octile*32 + pc;
                int c0 = chunk*16 + 2*cp;
                float v0 = 0.f, v1 = 0.f;
                if (chn < COUT && c0 < CIN) {
                    v0 = w[((size_t)chn*CIN + c0)*9 + k];
                    v1 = w[((size_t)chn*CIN + c0 + 1)*9 + k];
                }
                val = pack_bf16x2(v0, v1);
            }
            g_w16[OFFs[cy] + i] = val;
        }
    } else if (cy == 5) {
        if (blockIdx.x == 0) {
            for (int i = threadIdx.x; i < BB*8*24; i += 256) g_stage_in[i] = 0.f;
            for (int i = threadIdx.x; i < BB*8*44; i += 256) g_stage_f[i] = 0.f;
        }
        for (int gid = tid0; gid < BB*32*4096; gid += stride) {
            int px = gid & 63;
            int py = (gid >> 6) & 63;
            int cp = (gid >> 12) & 31;
            int b  = gid >> 17;
            const float* sp = (cp < 16) ? x + (size_t)(b*32 + 2*cp)*NN
                                        : y + (size_t)(b*32 + 2*(cp-16))*NN;
            int iy = 2*py, ix = 2*px;
            float v0 = 0.25f*(sp[iy*WW+ix] + sp[iy*WW+ix+1] + sp[(iy+1)*WW+ix] + sp[(iy+1)*WW+ix+1]);
            const float* s1 = sp + NN;
            float v1 = 0.25f*(s1[iy*WW+ix] + s1[iy*WW+ix+1] + s1[(iy+1)*WW+ix] + s1[(iy+1)*WW+ix+1]);
            g_pool16[(size_t)(b*32 + cp)*4096 + py*64 + px] = pack_bf16x2(v0, v1);
        }
    } else if (cy == 6) {
        for (int gid = tid0; gid < BB*32*NN; gid += stride) {
            int p = gid % NN;
            int cp = (gid / NN) % 32;
            int b = gid / (32*NN);
            const float* sp = (cp < 16) ? x + (size_t)(b*32 + 2*cp)*NN
                                        : y + (size_t)(b*32 + 2*(cp-16))*NN;
            g_xy16[(size_t)(b*32 + cp)*NN + p] = pack_bf16x2(sp[p], sp[NN + p]);
        }
    } else {
        // NHWC transpose of x via smem tiles
        const int tid = threadIdx.x;
        for (int blk = blockIdx.x; blk < BB*(NN/64); blk += gridDim.x) {
            int b = blk / (NN/64);
            int px0 = (blk % (NN/64)) * 64;
#pragma unroll
            for (int k = 0; k < 8; k++) {
                int ch = k*4 + (tid >> 6);
                int px = tid & 63;
                s[ch][px] = x[(size_t)(b*32 + ch)*NN + px0 + px];
            }
            __syncthreads();
            float* xn = (float*)g_xnhwc4;
#pragma unroll
            for (int k = 0; k < 8; k++) {
                int px = k*8 + (tid >> 5);
                int ch = tid & 31;
                xn[(size_t)(b*NN + px0 + px)*32 + ch] = s[ch][px];
            }
            __syncthreads();
        }
    }
}

// ---------------- tensor-core conv3x3, bf16 m16n8k16, 2-row tile, bank-clean ----------------
// EPI: 0 plain, 1 sigmoid, 2 multiply by nearest-upsampled sigmoid aux (g_asmall)
// OUTM: 0 = fp32 NCHW, 1 = bf16x2 pairs (permuted weights), 2 = float2 offs (permuted)
template<int CIN, int COUT, int EPI, int SRCU, int CPTOT, int OUTM, int DSTID,
         int OUTC0, int OUTCTOT, int W16OFF,
         int HIN, int WIN, int HOUT, int WOUT, int PAD>
__global__ void k_conv3x3_tc() {
    constexpr int CP = CIN/2;
    constexpr int NCHUNK = (CP + 7) / 8;
    constexpr int PITCH = 134;               // tg row-group stride 4*134 % 32 = 24 -> conflict-free
    const uint32_t* src16 = gbufu<SRCU>();
    __shared__ uint32_t sIn[8*4*PITCH];
    __shared__ uint32_t sW[2880];            // pitch 40: 9*40 % 32 = 8 -> conflict-free
    const int y0  = blockIdx.x * 2;
    const int oc0 = blockIdx.y * 32;
    const int b   = blockIdx.z;
    const int tid = threadIdx.x;
    const int lane = tid & 31, wid5 = tid >> 5;
    const int wy = wid5 >> 2, wn = wid5 & 3; // warp = (output row, pixel quarter)
    const int g = lane >> 2, tg = lane & 3;

    float acc[2][4][4];
#pragma unroll
    for (int m = 0; m < 2; m++)
#pragma unroll
        for (int t = 0; t < 4; t++)
#pragma unroll
            for (int r = 0; r < 4; r++) acc[m][t][r] = 0.f;

    const uint32_t* wbase = g_w16 + W16OFF + (size_t)(oc0 >> 5)*NCHUNK*2880;
    for (int ch = 0; ch < NCHUNK; ch++) {
        // ---- input fill: warp = one cp plane, rows y0-PAD .. y0-PAD+3 ----
        {
            int cpg = ch*8 + wid5;
            bool cpv = cpg < CP;
            const uint32_t* sp = src16 + (size_t)(b*CPTOT + cpg)*(HIN*WIN);
#pragma unroll
            for (int row = 0; row < 4; row++) {
                int gy = y0 - PAD + row;
                bool yv = cpv && ((unsigned)gy < (unsigned)HIN);
                const uint32_t* rp = sp + gy*WIN;
                uint32_t* sd = sIn + (wid5*4 + row)*PITCH;
#pragma unroll
                for (int kk = 0; kk < 5; kk++) {
                    int px = lane + 32*kk;
                    if (px < PITCH) {
                        int gx = px - PAD;
                        uint32_t v = 0;
                        if (yv && (unsigned)gx < (unsigned)WIN) v = rp[gx];
                        sd[px] = v;
                    }
                }
            }
        }
        // ---- weight fill: straight copy ----
        {
            const uint32_t* wp = wbase + ch*2880;
            for (int i = tid; i < 2880; i += 256) sW[i] = wp[i];
        }
        __syncthreads();
        // ---- 9 shifted GEMMs; B fragment shared across the 2 oc-tiles ----
#pragma unroll
        for (int kpos = 0; kpos < 9; kpos++) {
            const int ky = kpos / 3, kx = kpos % 3;
            uint32_t a[2][4];
#pragma unroll
            for (int m = 0; m < 2; m++) {
                const int aoc = m*16 + g;
                a[m][0] = sW[(tg*9 + kpos)*40 + aoc];
                a[m][1] = sW[(tg*9 + kpos)*40 + aoc + 8];
                a[m][2] = sW[((tg+4)*9 + kpos)*40 + aoc];
                a[m][3] = sW[((tg+4)*9 + kpos)*40 + aoc + 8];
            }
            const int r0 = (tg*4 + wy + ky)*PITCH + kx;
            const int r1 = ((tg+4)*4 + wy + ky)*PITCH + kx;
#pragma unroll
            for (int t = 0; t < 4; t++) {
                int px = wn*32 + t*8 + g;
                uint32_t b0 = sIn[r0 + px], b1 = sIn[r1 + px];
                mma_bf16(acc[0][t], a[0][0], a[0][1], a[0][2], a[0][3], b0, b1);
                mma_bf16(acc[1][t], a[1][0], a[1][1], a[1][2], a[1][3], b0, b1);
            }
        }
        __syncthreads();
    }
    // ---- epilogue: this warp owns row y0+wy, oc tiles m=0,1 ----
    const int y = y0 + wy;
#pragma unroll
    for (int m = 0; m < 2; m++) {
        if (OUTM == 1) {
            int chan0 = oc0 + m*16 + 2*g;
            if (chan0 < COUT) {
                uint32_t* op = gbufu<(OUTM == 1) ? DSTID : 1>()
                    + (size_t)(b*OUTCTOT + (OUTC0 + chan0)/2)*(HOUT*WOUT) + (size_t)y*WOUT;
#pragma unroll
                for (int t = 0; t < 4; t++) {
                    int px = wn*32 + t*8 + 2*tg;
                    float v00 = acc[m][t][0], v01 = acc[m][t][1];
                    float v10 = acc[m][t][2], v11 = acc[m][t][3];
                    if (EPI == 2) {
                        int ay = (y * 62) >> 7;
                        int ax0 = (px * 62) >> 7, ax1 = ((px+1) * 62) >> 7;
                        const float* a0p = g_asmall + ((size_t)(b*166 + chan0)*62 + ay)*62;
                        const float* a1p = a0p + 62*62;
                        v00 *= a0p[ax0]; v01 *= a0p[ax1];
                        v10 *= a1p[ax0]; v11 *= a1p[ax1];
                    }
                    op[px]   = pack_bf16x2(v00, v10);
                    op[px+1] = pack_bf16x2(v01, v11);
                }
            }
        } else if (OUTM == 2) {
            int chan0 = oc0 + m*16 + 2*g;
            if (chan0 < COUT) {
                float2* op = g_offs2 + (size_t)(b*83 + chan0/2)*(HOUT*WOUT) + (size_t)y*WOUT;
#pragma unroll
                for (int t = 0; t < 4; t++) {
                    int px = wn*32 + t*8 + 2*tg;
                    op[px]   = make_float2(acc[m][t][0], acc[m][t][2]);
                    op[px+1] = make_float2(acc[m][t][1], acc[m][t][3]);
                }
            }
        } else {
            float* dst = gbuf<(OUTM == 0) ? DSTID : 6>();
            const int ocr0 = oc0 + m*16 + g;
#pragma unroll
            for (int t = 0; t < 4; t++) {
                int px = wn*32 + t*8 + 2*tg;
#pragma unroll
                for (int half = 0; half < 2; half++) {
                    int ocr = ocr0 + half*8;
                    if (ocr >= COUT) continue;
                    float v0 = acc[m][t][half*2 + 0];
                    float v1 = acc[m][t][half*2 + 1];
                    if (EPI == 1) {
                        v0 = 1.f / (1.f + expf(-v0));
                        v1 = 1.f / (1.f + expf(-v1));
                    }
                    float* opf = dst + (size_t)(b*OUTCTOT + OUTC0 + ocr)*(HOUT*WOUT) + (size_t)y*WOUT;
                    if (px   < WOUT) opf[px]   = v0;
                    if (px+1 < WOUT) opf[px+1] = v1;
                }
            }
        }
    }
}

// ---------------- fused LayerNorm + l1 + qkv (4-way channel split) ----------------
__global__ void k_ln_l1_qkv(const float* __restrict__ x, const float* __restrict__ ln_g,
                            const float* __restrict__ ln_b, const float* __restrict__ w_lp1,
                            const float* __restrict__ w_qkv) {
    __shared__ float sw[32*32];
    __shared__ float s_g[32], s_b[32];
    int tid = threadIdx.x;
    int gid = blockIdx.x*256 + tid;          // B*4*N
    int p = gid % NN;
    int q = (gid / NN) & 3;
    int b = gid / (4*NN);
    const float* wsrc = (q == 0) ? w_lp1 : w_qkv + (size_t)(q-1)*1024;
    for (int i = tid; i < 1024; i += 256) sw[i] = wsrc[i];
    if (tid < 32) { s_g[tid] = ln_g[tid]; s_b[tid] = ln_b[tid]; }
    __syncthreads();
    float xv[32];
#pragma unroll
    for (int c = 0; c < 32; c++) xv[c] = x[(size_t)(b*32 + c)*NN + p];
    if (q == 0) {
#pragma unroll
        for (int m = 0; m < 16; m++) {
            float a0 = 0.f, a1 = 0.f;
#pragma unroll
            for (int c = 0; c < 32; c++) {
                a0 += sw[(2*m)*32 + c]*xv[c];
                a1 += sw[(2*m+1)*32 + c]*xv[c];
            }
            g_cat96p16[(size_t)(b*48 + m)*NN + p] = pack_bf16x2(a0, a1);
        }
    } else {
        float mu = 0.f;
#pragma unroll
        for (int c = 0; c < 32; c++) mu += xv[c];
        mu *= (1.f/32.f);
        float var = 0.f;
#pragma unroll
        for (int c = 0; c < 32; c++) { float d = xv[c]-mu; var += d*d; }
        var *= (1.f/32.f);
        float inv = rsqrtf(var + 1e-5f);
        float vin[32];
#pragma unroll
        for (int c = 0; c < 32; c++) vin[c] = (xv[c]-mu)*inv*s_g[c] + s_b[c];
        float* outbase = g_qkv + (size_t)(b*96 + (q-1)*32)*NN;
        for (int o = 0; o < 32; o++) {
            float a = 0.f;
#pragma unroll
            for (int c = 0; c < 32; c++) a += sw[o*32+c]*vin[c];
            outbase[(size_t)o*NN + p] = a;
        }
    }
}

// ---------------- grouped 3x3 conv (96 ch, groups=32, in/out 3 per group) ----------------
__global__ void k_qkvd(const float* __restrict__ w) {
    __shared__ float ws[96*27];
    int tid = threadIdx.x;
    for (int i = tid; i < 96*27; i += 256) ws[i] = w[i];
    __syncthreads();
    int gid = blockIdx.x*256 + tid;
    int p = gid % NN;
    int g = (gid / NN) % 32;
    int b = gid / (32*NN);
    int y = p >> 7, xx = p & 127;
    float a0 = 0.f, a1 = 0.f, a2 = 0.f;
    const float* inb = g_qkv + (size_t)(b*96 + 3*g)*NN;
#pragma unroll
    for (int ky = 0; ky < 3; ky++) {
        int gy = y - 1 + ky;
        if (gy < 0 || gy >= HH) continue;
#pragma unroll
        for (int kx = 0; kx < 3; kx++) {
            int gx = xx - 1 + kx;
            if (gx < 0 || gx >= WW) continue;
            int kk = ky*3 + kx;
#pragma unroll
            for (int ci = 0; ci < 3; ci++) {
                float v = inb[ci*NN + gy*WW + gx];
                a0 += ws[(3*g+0)*27 + ci*9 + kk]*v;
                a1 += ws[(3*g+1)*27 + ci*9 + kk]*v;
                a2 += ws[(3*g+2)*27 + ci*9 + kk]*v;
            }
        }
    }
    g_qkvd[(size_t)(b*96 + 3*g+0)*NN + p] = a0;
    g_qkvd[(size_t)(b*96 + 3*g+1)*NN + p] = a1;
    g_qkvd[(size_t)(b*96 + 3*g+2)*NN + p] = a2;
}

// ---------------- sliced gram accumulate (dots + squared norms) ----------------
template<int MODE>
__global__ void k_gramacc(const float* __restrict__ xin) {
    constexpr int D = (MODE == 0) ? 4 : 8;
    constexpr int E = 4;
    constexpr int NS = D*E + D + E;          // 24 or 44
    constexpr int SL = 16;
    int bid = blockIdx.x;                    // BB*8*16
    int slice = bid & 15;
    int h = (bid >> 4) & 7;
    int b = bid >> 7;
    int tid = threadIdx.x;
    const float* qbase;
    if (MODE == 0) qbase = g_qkvd + (size_t)(b*96 + h*D)*NN;
    else qbase = (h < 4) ? xin + (size_t)(b*32 + h*8)*NN
                         : g_prompt + (size_t)(b*32 + (h-4)*8)*NN;
    const float* kbase = (MODE == 0) ? g_qkvd + (size_t)(b*96 + 32 + h*E)*NN
                                     : g_kfeat + (size_t)(b*32 + h*E)*NN;
    float acc[NS];
#pragma unroll
    for (int i = 0; i < NS; i++) acc[i] = 0.f;
    int n0 = slice * (NN/SL);
    for (int it = 0; it < (NN/SL)/256; it++) {
        int n = n0 + it*256 + tid;
        float qv[D], kv[E];
#pragma unroll
        for (int d = 0; d < D; d++) qv[d] = qbase[(size_t)d*NN + n];
#pragma unroll
        for (int e = 0; e < E; e++) kv[e] = kbase[(size_t)e*NN + n];
#pragma unroll
        for (int d = 0; d < D; d++)
#pragma unroll
            for (int e = 0; e < E; e++) acc[d*E+e] += qv[d]*kv[e];
#pragma unroll
        for (int d = 0; d < D; d++) acc[D*E + d] += qv[d]*qv[d];
#pragma unroll
        for (int e = 0; e < E; e++) acc[D*E + D + e] += kv[e]*kv[e];
    }
    __shared__ float red[NS];
    if (tid < NS) red[tid] = 0.f;
    __syncthreads();
    int lane = tid & 31;
#pragma unroll
    for (int i = 0; i < NS; i++) {
        float v = acc[i];
#pragma unroll
        for (int o = 16; o > 0; o >>= 1) v += __shfl_down_sync(0xffffffffu, v, o);
        if (lane == 0) atomicAdd(&red[i], v);
    }
    __syncthreads();
    float* st = (MODE == 0) ? g_stage_in + (b*8 + h)*24 : g_stage_f + (b*8 + h)*44;
    if (tid < NS) atomicAdd(&st[tid], red[tid]);
}

// ---------------- softmax + fold with 1x1 conv weights -> Meff ----------------
template<int MODE>
__global__ void k_meffsm(const float* __restrict__ wmat, const float* __restrict__ tempv) {
    constexpr int D = (MODE == 0) ? 4 : 8;
    int b = blockIdx.x;
    int t = threadIdx.x;                     // 1024 threads
    __shared__ float sA[8*D*4];
    if (t < 8*D) {
        int h = t / D, d = t % D;
        const float* st = (MODE == 0) ? g_stage_in + (b*8 + h)*24 : g_stage_f + (b*8 + h)*44;
        float qn = fmaxf(sqrtf(st[D*4 + d]), 1e-12f);
        float tp = tempv[h];
        float row[4];
        float mx = -1e30f;
#pragma unroll
        for (int e = 0; e < 4; e++) {
            float kn = fmaxf(sqrtf(st[D*4 + D + e]), 1e-12f);
            row[e] = st[d*4+e] / (qn*kn) * tp;
            mx = fmaxf(mx, row[e]);
        }
        float sum = 0.f;
#pragma unroll
        for (int e = 0; e < 4; e++) { row[e] = expf(row[e]-mx); sum += row[e]; }
        float isum = 1.f/sum;
#pragma unroll
        for (int e = 0; e < 4; e++) sA[(h*D + d)*4 + e] = row[e]*isum;
    }
    __syncthreads();
    int o = t >> 5, vc = t & 31, h = vc >> 2, e = vc & 3;
    float s = 0.f;
#pragma unroll
    for (int d = 0; d < D; d++)
        s += wmat[o*(8*D) + h*D + d] * sA[(h*D + d)*4 + e];
    float* M = (MODE == 0) ? g_Meff_in : g_Meff_f;
    M[b*1024 + o*32 + vc] = s;
}

// ---------------- per-pixel 32x32 matmul apply (4-way channel split) ----------------
template<int MODE>
__global__ void k_apply(const float* __restrict__ xin, float* __restrict__ outp) {
    __shared__ float sm[256];
    int tid = threadIdx.x;
    int gid = blockIdx.x*256 + tid;          // B*4*N
    int p = gid % NN;
    int q = (gid / NN) & 3;
    int b = gid / (4*NN);
    const float* M = (MODE == 0) ? g_Meff_in : g_Meff_f;
    if (tid < 256) sm[tid] = M[b*1024 + q*256 + tid];
    __syncthreads();
    float vv[32];
#pragma unroll
    for (int c = 0; c < 32; c++) {
        if (MODE == 0) vv[c] = g_qkvd[(size_t)(b*96 + 64 + c)*NN + p];
        else           vv[c] = xin[(size_t)(b*32 + c)*NN + p];
    }
    float av[8];
#pragma unroll
    for (int j = 0; j < 8; j++) {
        int o = q*8 + j;
        float a = (MODE == 0) ? xin[(size_t)(b*32 + o)*NN + p] : 0.f;
#pragma unroll
        for (int c = 0; c < 32; c++) a += sm[j*32+c]*vv[c];
        av[j] = a;
    }
    if (MODE == 0) {
#pragma unroll
        for (int m = 0; m < 4; m++)
            g_cat96p16[(size_t)(b*48 + 32 + q*4 + m)*NN + p] = pack_bf16x2(av[2*m], av[2*m+1]);
    } else {
#pragma unroll
        for (int j = 0; j < 8; j++)
            outp[(size_t)(b*32 + q*8 + j)*NN + p] = av[j];
    }
}

// ---------------- fused deformable convs (k=3,5,7; groups=8) ----------------
template<int K, int PAD>
__device__ __forceinline__ void deform_one(const float2* __restrict__ offp,
                                           const float* __restrict__ ws,
                                           const float* __restrict__ bsh,
                                           int yy, int xx, int b, int g, int p,
                                           int out0) {
    constexpr int K2 = K*K;
    float acc0 = 0.f, acc1 = 0.f, acc2 = 0.f, acc3 = 0.f;
    const float4* xb = g_xnhwc4 + (size_t)b*NN*8 + g;
    for (int k2 = 0; k2 < K2; k2++) {
        float2 d = offp[(size_t)k2*NN];
        float py = (float)(yy - PAD + k2 / K) + d.x;
        float px = (float)(xx - PAD + k2 % K) + d.y;
        float y0f = floorf(py), x0f = floorf(px);
        float wy = py - y0f, wx = px - x0f;
        int y0 = (int)y0f, x0 = (int)x0f;
        float w00 = (1.f-wy)*(1.f-wx), w01 = (1.f-wy)*wx, w10 = wy*(1.f-wx), w11 = wy*wx;
        bool iy0 = (y0 >= 0 && y0 < HH), iy1 = (y0+1 >= 0 && y0+1 < HH);
        bool ix0 = (x0 >= 0 && x0 < WW), ix1 = (x0+1 >= 0 && x0+1 < WW);
        float4 s = make_float4(0.f, 0.f, 0.f, 0.f);
        if (iy0 && ix0) {
            float4 v = xb[(size_t)(y0*WW + x0)*8];
            s.x += w00*v.x; s.y += w00*v.y; s.z += w00*v.z; s.w += w00*v.w;
        }
        if (iy0 && ix1) {
            float4 v = xb[(size_t)(y0*WW + x0 + 1)*8];
            s.x += w01*v.x; s.y += w01*v.y; s.z += w01*v.z; s.w += w01*v.w;
        }
        if (iy1 && ix0) {
            float4 v = xb[(size_t)((y0+1)*WW + x0)*8];
            s.x += w10*v.x; s.y += w10*v.y; s.z += w10*v.z; s.w += w10*v.w;
        }
        if (iy1 && ix1) {
            float4 v = xb[(size_t)((y0+1)*WW + x0 + 1)*8];
            s.x += w11*v.x; s.y += w11*v.y; s.z += w11*v.z; s.w += w11*v.w;
        }
        acc0 += ws[(0*4+0)*K2+k2]*s.x + ws[(0*4+1)*K2+k2]*s.y + ws[(0*4+2)*K2+k2]*s.z + ws[(0*4+3)*K2+k2]*s.w;
        acc1 += ws[(1*4+0)*K2+k2]*s.x + ws[(1*4+1)*K2+k2]*s.y + ws[(1*4+2)*K2+k2]*s.z + ws[(1*4+3)*K2+k2]*s.w;
        acc2 += ws[(2*4+0)*K2+k2]*s.x + ws[(2*4+1)*K2+k2]*s.y + ws[(2*4+2)*K2+k2]*s.z + ws[(2*4+3)*K2+k2]*s.w;
        acc3 += ws[(3*4+0)*K2+k2]*s.x + ws[(3*4+1)*K2+k2]*s.y + ws[(3*4+2)*K2+k2]*s.z + ws[(3*4+3)*K2+k2]*s.w;
    }
    float* ob = g_catf + (size_t)(b*96 + out0 + g*4)*NN + p;
    ob[0*NN] = fmaxf(acc0 + bsh[0], 0.f);
    ob[1*NN] = fmaxf(acc1 + bsh[1], 0.f);
    ob[2*NN] = fmaxf(acc2 + bsh[2], 0.f);
    ob[3*NN] = fmaxf(acc3 + bsh[3], 0.f);
}

__global__ void k_deform_all(const float* __restrict__ w3, const float* __restrict__ b3,
                             const float* __restrict__ w5, const float* __restrict__ b5,
                             const float* __restrict__ w7, const float* __restrict__ b7) {
    __shared__ float ws[16*83];              // [w3 144 | w5 400 | w7 784]
    __shared__ float bsh[12];
    int tid = threadIdx.x;
    int gid = blockIdx.x*256 + tid;          // B*8*N
    int p = gid % NN;
    int g = (gid / NN) & 7;
    int b = gid / (8*NN);
    for (int i = tid; i < 144; i += 256) ws[i] = w3[g*144 + i];
    for (int i = tid; i < 400; i += 256) ws[144 + i] = w5[g*400 + i];
    for (int i = tid; i < 784; i += 256) ws[544 + i] = w7[g*784 + i];
    if (tid < 4)       bsh[tid]   = b3[g*4 + tid];
    else if (tid < 8)  bsh[tid]   = b5[g*4 + tid - 4];
    else if (tid < 12) bsh[tid]   = b7[g*4 + tid - 8];
    __syncthreads();
    int yy = p >> 7, xx = p & 127;
    const float2* offbase = g_offs2 + (size_t)(b*83)*NN + p;
    deform_one<3,1>(offbase,                 ws,     bsh,    yy, xx, b, g, p, 0);
    deform_one<5,2>(offbase + (size_t)9*NN,  ws+144, bsh+4,  yy, xx, b, g, p, 32);
    deform_one<7,3>(offbase + (size_t)34*NN, ws+544, bsh+8,  yy, xx, b, g, p, 64);
}

// ---------------- pointwise conv 96->32 with bias (4-way split) ----------------
__global__ void k_pw(const float* __restrict__ w, const float* __restrict__ bias) {
    __shared__ float ws[8*96];
    __shared__ float bs[8];
    int tid = threadIdx.x;
    int gid = blockIdx.x*256 + tid;          // B*4*N
    int p = gid % NN;
    int q = (gid / NN) & 3;
    int b = gid / (4*NN);
    for (int i = tid; i < 768; i += 256) ws[i] = w[(size_t)(q*8 + i/96)*96 + i%96];
    if (tid < 8) bs[tid] = bias[q*8 + tid];
    __syncthreads();
    float acc[8];
#pragma unroll
    for (int j = 0; j < 8; j++) acc[j] = bs[j];
    for (int c = 0; c < 96; c++) {
        float v = g_catf[(size_t)(b*96 + c)*NN + p];
#pragma unroll
        for (int j = 0; j < 8; j++) acc[j] += ws[j*96 + c]*v;
    }
#pragma unroll
    for (int j = 0; j < 8; j++) g_kfeat[(size_t)(b*32 + q*8 + j)*NN + p] = acc[j];
}

// ---------------- launch (kernel launches ONLY) ----------------
extern "C" void kernel_launch(void* const* d_in, const int* in_sizes, int n_in,
                              void* d_out, int out_size) {
    const float* x       = (const float*)d_in[0];
    const float* y       = (const float*)d_in[1];
    const float* temp    = (const float*)d_in[2];
    const float* w_po    = (const float*)d_in[3];
    const float* w_lp1   = (const float*)d_in[4];
    const float* w_lp2   = (const float*)d_in[5];
    const float* ln_g    = (const float*)d_in[6];
    const float* ln_b    = (const float*)d_in[7];
    const float* temp_in = (const float*)d_in[8];
    const float* w_qkv   = (const float*)d_in[9];
    const float* w_qkvd  = (const float*)d_in[10];
    const float* w_mproj = (const float*)d_in[11];
    const float* w_c3    = (const float*)d_in[12];
    const float* w_k2    = (const float*)d_in[13];
    const float* w_k3    = (const float*)d_in[14];
    const float* w_k4    = (const float*)d_in[15];
    const float* w_d3    = (const float*)d_in[16];
    const float* b_d3    = (const float*)d_in[17];
    const float* w_d5    = (const float*)d_in[18];
    const float* b_d5    = (const float*)d_in[19];
    const float* w_d7    = (const float*)d_in[20];
    const float* b_d7    = (const float*)d_in[21];
    const float* w_pw    = (const float*)d_in[22];
    const float* b_pw    = (const float*)d_in[23];

    // ---- merged setup (prepack + pool16 + pack_xy + stage zero + nhwc) ----
    k_setup<<<dim3(256, 8), 256>>>(x, y, w_lp2, w_c3, w_k2, w_k3, w_k4);   // 0

    // ---- alignment branch ----
    // a = sigmoid(conv3x3(pool, w_k2, pad=0)) at 62x62
    k_conv3x3_tc<64,166,1, 2,32, 0,6, 0,166, 23040, 64,64,62,62, 0>
        <<<dim3(31, 6, BB), 256>>>();                                      // 1
    // bmid16 = conv3x3(concat(x,y), w_k3) * nearest_up(a)  (bf16 packed out)
    k_conv3x3_tc<64,166,2, 1,32, 1,3, 0,83, 92160, 128,128,128,128, 1>
        <<<dim3(64, 6, BB), 256>>>();                                      // 2
    // offs2 = conv3x3(bmid16, w_k4)  (float2 (dy,dx) planes)
    k_conv3x3_tc<166,166,0, 3,83, 2,6, 0,83, 161280, 128,128,128,128, 1>
        <<<dim3(64, 6, BB), 256>>>();                                      // 3 <- profiled
    k_deform_all<<<(BB*8*NN)/256, 256>>>(w_d3, b_d3, w_d5, b_d5, w_d7, b_d7); // 4
    k_pw<<<(BB*4*NN)/256, 256>>>(w_pw, b_pw);                              // 5

    // ---- prompt branch ----
    k_ln_l1_qkv<<<(BB*4*NN)/256, 256>>>(x, ln_g, ln_b, w_lp1, w_qkv);      // 6
    // l2 = conv3x3(x, w_lp2) -> cat96p16 cp16..31 (bf16 packed out)
    k_conv3x3_tc<32,32,0, 1,32, 1,4, 32,48, 0, 128,128,128,128, 1>
        <<<dim3(64, 1, BB), 256>>>();                                      // 7
    k_qkvd<<<(BB*32*NN)/256, 256>>>(w_qkvd);                               // 8
    k_gramacc<0><<<BB*8*16, 256>>>(x);                                     // 9
    k_meffsm<0><<<BB, 1024>>>(w_mproj, temp_in);                           // 10
    k_apply<0><<<(BB*4*NN)/256, 256>>>(x, nullptr);                        // 11
    // prompt = conv3x3(cat96p16, w_c3)
    k_conv3x3_tc<96,32,0, 4,48, 0,11, 0,32, 5760, 128,128,128,128, 1>
        <<<dim3(64, 1, BB), 256>>>();                                      // 12

    // ---- final prompted channel attention ----
    k_gramacc<1><<<BB*8*16, 256>>>(x);                                     // 13
    k_meffsm<1><<<BB, 1024>>>(w_po, temp);                                 // 14
    k_apply<1><<<(BB*4*NN)/256, 256>>>(x, (float*)d_out);                  // 15
}

// round 11
// speedup vs baseline: 2.9296x; 1.0602x over previous
#include <cuda_runtime.h>
#include <math.h>
#include <stdint.h>

#define BB 2
#define CCH 32
#define HH 128
#define WW 128
#define NN (HH*WW)
#define NHEADS 8

// ---------------- scratch (static device globals; no allocation) ----------------
__device__ float g_qkv[BB*96*NN];
__device__ float g_qkvd[BB*96*NN];     // q|k|v after grouped dwconv
__device__ float g_asmall[BB*166*62*62];
__device__ float2 g_offs2[BB*83*NN];   // k4 output: (dy,dx) float2 planes
__device__ float g_catf[BB*96*NN];     // [f3 | f5 | f7]
__device__ float g_kfeat[BB*CCH*NN];
__device__ float g_prompt[BB*CCH*NN];
__device__ float4 g_xnhwc4[BB*NN*8];   // x in NHWC, float4-grouped (16B aligned)
__device__ float g_stage_in[BB*8*24];  // dots[16] | q2[4] | k2[4]
__device__ float g_stage_f[BB*8*44];   // dots[32] | q2[8] | k2[4]
__device__ float g_Meff_in[BB*32*32];
__device__ float g_Meff_f[BB*32*32];

// bf16x2 pair-interleaved staging (u32 = channels (2c, 2c+1))
__device__ uint32_t g_xy16[BB*32*NN];      // cp 0..15 = x, 16..31 = y
__device__ uint32_t g_pool16[BB*32*64*64]; // pooled concat(x,y)
__device__ uint32_t g_bmid16[BB*83*NN];    // k3 output (166 ch -> 83 cp)
__device__ uint32_t g_cat96p16[BB*48*NN];  // [l1 cp0-15 | l2 cp16-31 | xg cp32-47]
__device__ uint32_t g_w16[351360];         // prepacked conv weights (sW image, pitch 40)

// compile-time scratch-buffer resolution
template<int ID> __device__ __forceinline__ float* gbuf();
template<> __device__ __forceinline__ float* gbuf<6>()  { return g_asmall; }
template<> __device__ __forceinline__ float* gbuf<11>() { return g_prompt; }
template<int ID> __device__ __forceinline__ uint32_t* gbufu();
template<> __device__ __forceinline__ uint32_t* gbufu<1>() { return g_xy16; }
template<> __device__ __forceinline__ uint32_t* gbufu<2>() { return g_pool16; }
template<> __device__ __forceinline__ uint32_t* gbufu<3>() { return g_bmid16; }
template<> __device__ __forceinline__ uint32_t* gbufu<4>() { return g_cat96p16; }

// ---------------- bf16 helpers ----------------
__device__ __forceinline__ uint32_t pack_bf16x2(float lo, float hi) {
    uint32_t r;
    asm("cvt.rn.bf16x2.f32 %0, %1, %2;" : "=r"(r) : "f"(hi), "f"(lo));
    return r;
}
__device__ __forceinline__ void mma_bf16(float* d, uint32_t a0, uint32_t a1,
                                         uint32_t a2, uint32_t a3,
                                         uint32_t b0, uint32_t b1) {
    asm volatile("mma.sync.aligned.m16n8k16.row.col.f32.bf16.bf16.f32 "
        "{%0,%1,%2,%3}, {%4,%5,%6,%7}, {%8,%9}, {%0,%1,%2,%3};\n"
        : "+f"(d[0]), "+f"(d[1]), "+f"(d[2]), "+f"(d[3])
        : "r"(a0), "r"(a1), "r"(a2), "r"(a3), "r"(b0), "r"(b1));
}

// ---------------- merged setup ----------------
// blockIdx.y: 0..4 = prepack conv, 5 = pool16 (+stage zero), 6 = pack_xy, 7 = nhwc
__global__ void k_setup(const float* __restrict__ x, const float* __restrict__ y,
                        const float* __restrict__ w_lp2, const float* __restrict__ w_c3,
                        const float* __restrict__ w_k2, const float* __restrict__ w_k3,
                        const float* __restrict__ w_k4) {
    __shared__ float s[32][65];
    const int cy = blockIdx.y;
    const int tid0 = blockIdx.x*256 + threadIdx.x;
    const int stride = gridDim.x*256;
    if (cy < 5) {
        const int CINs[5]  = {32, 96, 64, 64, 166};
        const int COUTs[5] = {32, 32, 166, 166, 166};
        const int NCHs[5]  = {2, 6, 4, 4, 11};
        const int OCTs[5]  = {1, 1, 6, 6, 6};
        const int PERMs[5] = {1, 0, 0, 1, 1};
        const int OFFs[5]  = {0, 5760, 23040, 92160, 161280};
        const float* wsv[5] = {w_lp2, w_c3, w_k2, w_k3, w_k4};
        const int CIN = CINs[cy], COUT = COUTs[cy], NCH = NCHs[cy], PERM = PERMs[cy];
        const float* w = wsv[cy];
        const int total = OCTs[cy]*NCH*2880;
        for (int i = tid0; i < total; i += stride) {
            int within = i % 2880;
            int tile   = i / 2880;
            int oc = within % 40;
            int ck = within / 40;
            int k  = ck % 9;
            int cp = ck / 9;
            int chunk  = tile % NCH;
            int octile = tile / NCH;
            uint32_t val = 0;
            if (oc < 32) {
                int pc = PERM ? ((oc & 16) + 2*(oc & 7) + ((oc >> 3) & 1)) : oc;
                int chn = octile*32 + pc;
                int c0 = chunk*16 + 2*cp;
                float v0 = 0.f, v1 = 0.f;
                if (chn < COUT && c0 < CIN) {
                    v0 = w[((size_t)chn*CIN + c0)*9 + k];
                    v1 = w[((size_t)chn*CIN + c0 + 1)*9 + k];
                }
                val = pack_bf16x2(v0, v1);
            }
            g_w16[OFFs[cy] + i] = val;
        }
    } else if (cy == 5) {
        if (blockIdx.x == 0) {
            for (int i = threadIdx.x; i < BB*8*24; i += 256) g_stage_in[i] = 0.f;
            for (int i = threadIdx.x; i < BB*8*44; i += 256) g_stage_f[i] = 0.f;
        }
        for (int gid = tid0; gid < BB*32*4096; gid += stride) {
            int px = gid & 63;
            int py = (gid >> 6) & 63;
            int cp = (gid >> 12) & 31;
            int b  = gid >> 17;
            const float* sp = (cp < 16) ? x + (size_t)(b*32 + 2*cp)*NN
                                        : y + (size_t)(b*32 + 2*(cp-16))*NN;
            int iy = 2*py, ix = 2*px;
            float v0 = 0.25f*(sp[iy*WW+ix] + sp[iy*WW+ix+1] + sp[(iy+1)*WW+ix] + sp[(iy+1)*WW+ix+1]);
            const float* s1 = sp + NN;
            float v1 = 0.25f*(s1[iy*WW+ix] + s1[iy*WW+ix+1] + s1[(iy+1)*WW+ix] + s1[(iy+1)*WW+ix+1]);
            g_pool16[(size_t)(b*32 + cp)*4096 + py*64 + px] = pack_bf16x2(v0, v1);
        }
    } else if (cy == 6) {
        for (int gid = tid0; gid < BB*32*NN; gid += stride) {
            int p = gid % NN;
            int cp = (gid / NN) % 32;
            int b = gid / (32*NN);
            const float* sp = (cp < 16) ? x + (size_t)(b*32 + 2*cp)*NN
                                        : y + (size_t)(b*32 + 2*(cp-16))*NN;
            g_xy16[(size_t)(b*32 + cp)*NN + p] = pack_bf16x2(sp[p], sp[NN + p]);
        }
    } else {
        // NHWC transpose of x via smem tiles
        const int tid = threadIdx.x;
        for (int blk = blockIdx.x; blk < BB*(NN/64); blk += gridDim.x) {
            int b = blk / (NN/64);
            int px0 = (blk % (NN/64)) * 64;
#pragma unroll
            for (int k = 0; k < 8; k++) {
                int ch = k*4 + (tid >> 6);
                int px = tid & 63;
                s[ch][px] = x[(size_t)(b*32 + ch)*NN + px0 + px];
            }
            __syncthreads();
            float* xn = (float*)g_xnhwc4;
#pragma unroll
            for (int k = 0; k < 8; k++) {
                int px = k*8 + (tid >> 5);
                int ch = tid & 31;
                xn[(size_t)(b*NN + px0 + px)*32 + ch] = s[ch][px];
            }
            __syncthreads();
        }
    }
}

// ---------------- tensor-core conv3x3, bf16 m16n8k16, 2-row tile, bank-clean ----------------
// Software-pipelined: chunk ch+1 is LDG'd into registers during chunk ch's mma phase,
// then STS'd after the barrier. Global latency hides under tensor work.
// EPI: 0 plain, 1 sigmoid, 2 multiply by nearest-upsampled sigmoid aux (g_asmall)
// OUTM: 0 = fp32 NCHW, 1 = bf16x2 pairs (permuted weights), 2 = float2 offs (permuted)
template<int CIN, int COUT, int EPI, int SRCU, int CPTOT, int OUTM, int DSTID,
         int OUTC0, int OUTCTOT, int W16OFF,
         int HIN, int WIN, int HOUT, int WOUT, int PAD>
__global__ void __launch_bounds__(256, 2) k_conv3x3_tc() {
    constexpr int CP = CIN/2;
    constexpr int NCHUNK = (CP + 7) / 8;
    constexpr int PITCH = 134;               // tg row-group stride 4*134 % 32 = 24 -> conflict-free
    const uint32_t* src16 = gbufu<SRCU>();
    __shared__ uint32_t sIn[8*4*PITCH];
    __shared__ uint32_t sW[2880];            // pitch 40: 9*40 % 32 = 8 -> conflict-free
    const int y0  = blockIdx.x * 2;
    const int oc0 = blockIdx.y * 32;
    const int b   = blockIdx.z;
    const int tid = threadIdx.x;
    const int lane = tid & 31, wid5 = tid >> 5;
    const int wy = wid5 >> 2, wn = wid5 & 3; // warp = (output row, pixel quarter)
    const int g = lane >> 2, tg = lane & 3;

    float acc[2][4][4];
#pragma unroll
    for (int m = 0; m < 2; m++)
#pragma unroll
        for (int t = 0; t < 4; t++)
#pragma unroll
            for (int r = 0; r < 4; r++) acc[m][t][r] = 0.f;

    const uint32_t* wbase = g_w16 + W16OFF + (size_t)(oc0 >> 5)*NCHUNK*2880;

    uint32_t ireg[20];
    uint32_t wreg[12];
    auto load_regs = [&](int ch) {
        int cpg = ch*8 + wid5;
        bool cpv = cpg < CP;
        const uint32_t* sp = src16 + (size_t)(b*CPTOT + cpg)*(HIN*WIN);
#pragma unroll
        for (int row = 0; row < 4; row++) {
            int gy = y0 - PAD + row;
            bool yv = cpv && ((unsigned)gy < (unsigned)HIN);
            const uint32_t* rp = sp + (size_t)gy*WIN;
#pragma unroll
            for (int kk = 0; kk < 5; kk++) {
                int px = lane + 32*kk;
                uint32_t v = 0;
                if (px < PITCH) {
                    int gx = px - PAD;
                    if (yv && (unsigned)gx < (unsigned)WIN) v = rp[gx];
                }
                ireg[row*5 + kk] = v;
            }
        }
        const uint32_t* wp = wbase + ch*2880;
#pragma unroll
        for (int j = 0; j < 12; j++) {
            int i = tid + j*256;
            wreg[j] = (i < 2880) ? wp[i] : 0u;
        }
    };
    auto store_smem = [&]() {
#pragma unroll
        for (int row = 0; row < 4; row++) {
            uint32_t* sd = sIn + (wid5*4 + row)*PITCH;
#pragma unroll
            for (int kk = 0; kk < 5; kk++) {
                int px = lane + 32*kk;
                if (px < PITCH) sd[px] = ireg[row*5 + kk];
            }
        }
#pragma unroll
        for (int j = 0; j < 12; j++) {
            int i = tid + j*256;
            if (i < 2880) sW[i] = wreg[j];
        }
    };

    load_regs(0);
    store_smem();
    __syncthreads();

    for (int ch = 0; ch < NCHUNK; ch++) {
        if (ch + 1 < NCHUNK) load_regs(ch + 1);   // LDGs in flight under the mma phase
        // ---- 9 shifted GEMMs; B fragment shared across the 2 oc-tiles ----
#pragma unroll
        for (int kpos = 0; kpos < 9; kpos++) {
            const int ky = kpos / 3, kx = kpos % 3;
            uint32_t a[2][4];
#pragma unroll
            for (int m = 0; m < 2; m++) {
                const int aoc = m*16 + g;
                a[m][0] = sW[(tg*9 + kpos)*40 + aoc];
                a[m][1] = sW[(tg*9 + kpos)*40 + aoc + 8];
                a[m][2] = sW[((tg+4)*9 + kpos)*40 + aoc];
                a[m][3] = sW[((tg+4)*9 + kpos)*40 + aoc + 8];
            }
            const int r0 = (tg*4 + wy + ky)*PITCH + kx;
            const int r1 = ((tg+4)*4 + wy + ky)*PITCH + kx;
#pragma unroll
            for (int t = 0; t < 4; t++) {
                int px = wn*32 + t*8 + g;
                uint32_t b0 = sIn[r0 + px], b1 = sIn[r1 + px];
                mma_bf16(acc[0][t], a[0][0], a[0][1], a[0][2], a[0][3], b0, b1);
                mma_bf16(acc[1][t], a[1][0], a[1][1], a[1][2], a[1][3], b0, b1);
            }
        }
        __syncthreads();
        if (ch + 1 < NCHUNK) {
            store_smem();                         // scoreboards mostly drained by now
            __syncthreads();
        }
    }
    // ---- epilogue: this warp owns row y0+wy, oc tiles m=0,1 ----
    const int y = y0 + wy;
#pragma unroll
    for (int m = 0; m < 2; m++) {
        if (OUTM == 1) {
            int chan0 = oc0 + m*16 + 2*g;
            if (chan0 < COUT) {
                uint32_t* op = gbufu<(OUTM == 1) ? DSTID : 1>()
                    + (size_t)(b*OUTCTOT + (OUTC0 + chan0)/2)*(HOUT*WOUT) + (size_t)y*WOUT;
#pragma unroll
                for (int t = 0; t < 4; t++) {
                    int px = wn*32 + t*8 + 2*tg;
                    float v00 = acc[m][t][0], v01 = acc[m][t][1];
                    float v10 = acc[m][t][2], v11 = acc[m][t][3];
                    if (EPI == 2) {
                        int ay = (y * 62) >> 7;
                        int ax0 = (px * 62) >> 7, ax1 = ((px+1) * 62) >> 7;
                        const float* a0p = g_asmall + ((size_t)(b*166 + chan0)*62 + ay)*62;
                        const float* a1p = a0p + 62*62;
                        v00 *= a0p[ax0]; v01 *= a0p[ax1];
                        v10 *= a1p[ax0]; v11 *= a1p[ax1];
                    }
                    op[px]   = pack_bf16x2(v00, v10);
                    op[px+1] = pack_bf16x2(v01, v11);
                }
            }
        } else if (OUTM == 2) {
            int chan0 = oc0 + m*16 + 2*g;
            if (chan0 < COUT) {
                float2* op = g_offs2 + (size_t)(b*83 + chan0/2)*(HOUT*WOUT) + (size_t)y*WOUT;
#pragma unroll
                for (int t = 0; t < 4; t++) {
                    int px = wn*32 + t*8 + 2*tg;
                    op[px]   = make_float2(acc[m][t][0], acc[m][t][2]);
                    op[px+1] = make_float2(acc[m][t][1], acc[m][t][3]);
                }
            }
        } else {
            float* dst = gbuf<(OUTM == 0) ? DSTID : 6>();
            const int ocr0 = oc0 + m*16 + g;
#pragma unroll
            for (int t = 0; t < 4; t++) {
                int px = wn*32 + t*8 + 2*tg;
#pragma unroll
                for (int half = 0; half < 2; half++) {
                    int ocr = ocr0 + half*8;
                    if (ocr >= COUT) continue;
                    float v0 = acc[m][t][half*2 + 0];
                    float v1 = acc[m][t][half*2 + 1];
                    if (EPI == 1) {
                        v0 = 1.f / (1.f + expf(-v0));
                        v1 = 1.f / (1.f + expf(-v1));
                    }
                    float* opf = dst + (size_t)(b*OUTCTOT + OUTC0 + ocr)*(HOUT*WOUT) + (size_t)y*WOUT;
                    if (px   < WOUT) opf[px]   = v0;
                    if (px+1 < WOUT) opf[px+1] = v1;
                }
            }
        }
    }
}

// ---------------- fused LayerNorm + l1 + qkv (4-way channel split) ----------------
__global__ void k_ln_l1_qkv(const float* __restrict__ x, const float* __restrict__ ln_g,
                            const float* __restrict__ ln_b, const float* __restrict__ w_lp1,
                            const float* __restrict__ w_qkv) {
    __shared__ float sw[32*32];
    __shared__ float s_g[32], s_b[32];
    int tid = threadIdx.x;
    int gid = blockIdx.x*256 + tid;          // B*4*N
    int p = gid % NN;
    int q = (gid / NN) & 3;
    int b = gid / (4*NN);
    const float* wsrc = (q == 0) ? w_lp1 : w_qkv + (size_t)(q-1)*1024;
    for (int i = tid; i < 1024; i += 256) sw[i] = wsrc[i];
    if (tid < 32) { s_g[tid] = ln_g[tid]; s_b[tid] = ln_b[tid]; }
    __syncthreads();
    float xv[32];
#pragma unroll
    for (int c = 0; c < 32; c++) xv[c] = x[(size_t)(b*32 + c)*NN + p];
    if (q == 0) {
#pragma unroll
        for (int m = 0; m < 16; m++) {
            float a0 = 0.f, a1 = 0.f;
#pragma unroll
            for (int c = 0; c < 32; c++) {
                a0 += sw[(2*m)*32 + c]*xv[c];
                a1 += sw[(2*m+1)*32 + c]*xv[c];
            }
            g_cat96p16[(size_t)(b*48 + m)*NN + p] = pack_bf16x2(a0, a1);
        }
    } else {
        float mu = 0.f;
#pragma unroll
        for (int c = 0; c < 32; c++) mu += xv[c];
        mu *= (1.f/32.f);
        float var = 0.f;
#pragma unroll
        for (int c = 0; c < 32; c++) { float d = xv[c]-mu; var += d*d; }
        var *= (1.f/32.f);
        float inv = rsqrtf(var + 1e-5f);
        float vin[32];
#pragma unroll
        for (int c = 0; c < 32; c++) vin[c] = (xv[c]-mu)*inv*s_g[c] + s_b[c];
        float* outbase = g_qkv + (size_t)(b*96 + (q-1)*32)*NN;
        for (int o = 0; o < 32; o++) {
            float a = 0.f;
#pragma unroll
            for (int c = 0; c < 32; c++) a += sw[o*32+c]*vin[c];
            outbase[(size_t)o*NN + p] = a;
        }
    }
}

// ---------------- grouped 3x3 conv (96 ch, groups=32, in/out 3 per group) ----------------
__global__ void k_qkvd(const float* __restrict__ w) {
    __shared__ float ws[96*27];
    int tid = threadIdx.x;
    for (int i = tid; i < 96*27; i += 256) ws[i] = w[i];
    __syncthreads();
    int gid = blockIdx.x*256 + tid;
    int p = gid % NN;
    int g = (gid / NN) % 32;
    int b = gid / (32*NN);
    int y = p >> 7, xx = p & 127;
    float a0 = 0.f, a1 = 0.f, a2 = 0.f;
    const float* inb = g_qkv + (size_t)(b*96 + 3*g)*NN;
#pragma unroll
    for (int ky = 0; ky < 3; ky++) {
        int gy = y - 1 + ky;
        if (gy < 0 || gy >= HH) continue;
#pragma unroll
        for (int kx = 0; kx < 3; kx++) {
            int gx = xx - 1 + kx;
            if (gx < 0 || gx >= WW) continue;
            int kk = ky*3 + kx;
#pragma unroll
            for (int ci = 0; ci < 3; ci++) {
                float v = inb[ci*NN + gy*WW + gx];
                a0 += ws[(3*g+0)*27 + ci*9 + kk]*v;
                a1 += ws[(3*g+1)*27 + ci*9 + kk]*v;
                a2 += ws[(3*g+2)*27 + ci*9 + kk]*v;
            }
        }
    }
    g_qkvd[(size_t)(b*96 + 3*g+0)*NN + p] = a0;
    g_qkvd[(size_t)(b*96 + 3*g+1)*NN + p] = a1;
    g_qkvd[(size_t)(b*96 + 3*g+2)*NN + p] = a2;
}

// ---------------- sliced gram accumulate (dots + squared norms) ----------------
template<int MODE>
__global__ void k_gramacc(const float* __restrict__ xin) {
    constexpr int D = (MODE == 0) ? 4 : 8;
    constexpr int E = 4;
    constexpr int NS = D*E + D + E;          // 24 or 44
    constexpr int SL = 16;
    int bid = blockIdx.x;                    // BB*8*16
    int slice = bid & 15;
    int h = (bid >> 4) & 7;
    int b = bid >> 7;
    int tid = threadIdx.x;
    const float* qbase;
    if (MODE == 0) qbase = g_qkvd + (size_t)(b*96 + h*D)*NN;
    else qbase = (h < 4) ? xin + (size_t)(b*32 + h*8)*NN
                         : g_prompt + (size_t)(b*32 + (h-4)*8)*NN;
    const float* kbase = (MODE == 0) ? g_qkvd + (size_t)(b*96 + 32 + h*E)*NN
                                     : g_kfeat + (size_t)(b*32 + h*E)*NN;
    float acc[NS];
#pragma unroll
    for (int i = 0; i < NS; i++) acc[i] = 0.f;
    int n0 = slice * (NN/SL);
    for (int it = 0; it < (NN/SL)/256; it++) {
        int n = n0 + it*256 + tid;
        float qv[D], kv[E];
#pragma unroll
        for (int d = 0; d < D; d++) qv[d] = qbase[(size_t)d*NN + n];
#pragma unroll
        for (int e = 0; e < E; e++) kv[e] = kbase[(size_t)e*NN + n];
#pragma unroll
        for (int d = 0; d < D; d++)
#pragma unroll
            for (int e = 0; e < E; e++) acc[d*E+e] += qv[d]*kv[e];
#pragma unroll
        for (int d = 0; d < D; d++) acc[D*E + d] += qv[d]*qv[d];
#pragma unroll
        for (int e = 0; e < E; e++) acc[D*E + D + e] += kv[e]*kv[e];
    }
    __shared__ float red[NS];
    if (tid < NS) red[tid] = 0.f;
    __syncthreads();
    int lane = tid & 31;
#pragma unroll
    for (int i = 0; i < NS; i++) {
        float v = acc[i];
#pragma unroll
        for (int o = 16; o > 0; o >>= 1) v += __shfl_down_sync(0xffffffffu, v, o);
        if (lane == 0) atomicAdd(&red[i], v);
    }
    __syncthreads();
    float* st = (MODE == 0) ? g_stage_in + (b*8 + h)*24 : g_stage_f + (b*8 + h)*44;
    if (tid < NS) atomicAdd(&st[tid], red[tid]);
}

// ---------------- softmax + fold with 1x1 conv weights -> Meff ----------------
template<int MODE>
__global__ void k_meffsm(const float* __restrict__ wmat, const float* __restrict__ tempv) {
    constexpr int D = (MODE == 0) ? 4 : 8;
    int b = blockIdx.x;
    int t = threadIdx.x;                     // 1024 threads
    __shared__ float sA[8*D*4];
    if (t < 8*D) {
        int h = t / D, d = t % D;
        const float* st = (MODE == 0) ? g_stage_in + (b*8 + h)*24 : g_stage_f + (b*8 + h)*44;
        float qn = fmaxf(sqrtf(st[D*4 + d]), 1e-12f);
        float tp = tempv[h];
        float row[4];
        float mx = -1e30f;
#pragma unroll
        for (int e = 0; e < 4; e++) {
            float kn = fmaxf(sqrtf(st[D*4 + D + e]), 1e-12f);
            row[e] = st[d*4+e] / (qn*kn) * tp;
            mx = fmaxf(mx, row[e]);
        }
        float sum = 0.f;
#pragma unroll
        for (int e = 0; e < 4; e++) { row[e] = expf(row[e]-mx); sum += row[e]; }
        float isum = 1.f/sum;
#pragma unroll
        for (int e = 0; e < 4; e++) sA[(h*D + d)*4 + e] = row[e]*isum;
    }
    __syncthreads();
    int o = t >> 5, vc = t & 31, h = vc >> 2, e = vc & 3;
    float s = 0.f;
#pragma unroll
    for (int d = 0; d < D; d++)
        s += wmat[o*(8*D) + h*D + d] * sA[(h*D + d)*4 + e];
    float* M = (MODE == 0) ? g_Meff_in : g_Meff_f;
    M[b*1024 + o*32 + vc] = s;
}

// ---------------- per-pixel 32x32 matmul apply (4-way channel split) ----------------
template<int MODE>
__global__ void k_apply(const float* __restrict__ xin, float* __restrict__ outp) {
    __shared__ float sm[256];
    int tid = threadIdx.x;
    int gid = blockIdx.x*256 + tid;          // B*4*N
    int p = gid % NN;
    int q = (gid / NN) & 3;
    int b = gid / (4*NN);
    const float* M = (MODE == 0) ? g_Meff_in : g_Meff_f;
    if (tid < 256) sm[tid] = M[b*1024 + q*256 + tid];
    __syncthreads();
    float vv[32];
#pragma unroll
    for (int c = 0; c < 32; c++) {
        if (MODE == 0) vv[c] = g_qkvd[(size_t)(b*96 + 64 + c)*NN + p];
        else           vv[c] = xin[(size_t)(b*32 + c)*NN + p];
    }
    float av[8];
#pragma unroll
    for (int j = 0; j < 8; j++) {
        int o = q*8 + j;
        float a = (MODE == 0) ? xin[(size_t)(b*32 + o)*NN + p] : 0.f;
#pragma unroll
        for (int c = 0; c < 32; c++) a += sm[j*32+c]*vv[c];
        av[j] = a;
    }
    if (MODE == 0) {
#pragma unroll
        for (int m = 0; m < 4; m++)
            g_cat96p16[(size_t)(b*48 + 32 + q*4 + m)*NN + p] = pack_bf16x2(av[2*m], av[2*m+1]);
    } else {
#pragma unroll
        for (int j = 0; j < 8; j++)
            outp[(size_t)(b*32 + q*8 + j)*NN + p] = av[j];
    }
}

// ---------------- fused deformable convs (k=3,5,7; groups=8) ----------------
template<int K, int PAD>
__device__ __forceinline__ void deform_one(const float2* __restrict__ offp,
                                           const float* __restrict__ ws,
                                           const float* __restrict__ bsh,
                                           int yy, int xx, int b, int g, int p,
                                           int out0) {
    constexpr int K2 = K*K;
    float acc0 = 0.f, acc1 = 0.f, acc2 = 0.f, acc3 = 0.f;
    const float4* xb = g_xnhwc4 + (size_t)b*NN*8 + g;
    for (int k2 = 0; k2 < K2; k2++) {
        float2 d = offp[(size_t)k2*NN];
        float py = (float)(yy - PAD + k2 / K) + d.x;
        float px = (float)(xx - PAD + k2 % K) + d.y;
        float y0f = floorf(py), x0f = floorf(px);
        float wy = py - y0f, wx = px - x0f;
        int y0 = (int)y0f, x0 = (int)x0f;
        float w00 = (1.f-wy)*(1.f-wx), w01 = (1.f-wy)*wx, w10 = wy*(1.f-wx), w11 = wy*wx;
        bool iy0 = (y0 >= 0 && y0 < HH), iy1 = (y0+1 >= 0 && y0+1 < HH);
        bool ix0 = (x0 >= 0 && x0 < WW), ix1 = (x0+1 >= 0 && x0+1 < WW);
        float4 s = make_float4(0.f, 0.f, 0.f, 0.f);
        if (iy0 && ix0) {
            float4 v = xb[(size_t)(y0*WW + x0)*8];
            s.x += w00*v.x; s.y += w00*v.y; s.z += w00*v.z; s.w += w00*v.w;
        }
        if (iy0 && ix1) {
            float4 v = xb[(size_t)(y0*WW + x0 + 1)*8];
            s.x += w01*v.x; s.y += w01*v.y; s.z += w01*v.z; s.w += w01*v.w;
        }
        if (iy1 && ix0) {
            float4 v = xb[(size_t)((y0+1)*WW + x0)*8];
            s.x += w10*v.x; s.y += w10*v.y; s.z += w10*v.z; s.w += w10*v.w;
        }
        if (iy1 && ix1) {
            float4 v = xb[(size_t)((y0+1)*WW + x0 + 1)*8];
            s.x += w11*v.x; s.y += w11*v.y; s.z += w11*v.z; s.w += w11*v.w;
        }
        acc0 += ws[(0*4+0)*K2+k2]*s.x + ws[(0*4+1)*K2+k2]*s.y + ws[(0*4+2)*K2+k2]*s.z + ws[(0*4+3)*K2+k2]*s.w;
        acc1 += ws[(1*4+0)*K2+k2]*s.x + ws[(1*4+1)*K2+k2]*s.y + ws[(1*4+2)*K2+k2]*s.z + ws[(1*4+3)*K2+k2]*s.w;
        acc2 += ws[(2*4+0)*K2+k2]*s.x + ws[(2*4+1)*K2+k2]*s.y + ws[(2*4+2)*K2+k2]*s.z + ws[(2*4+3)*K2+k2]*s.w;
        acc3 += ws[(3*4+0)*K2+k2]*s.x + ws[(3*4+1)*K2+k2]*s.y + ws[(3*4+2)*K2+k2]*s.z + ws[(3*4+3)*K2+k2]*s.w;
    }
    float* ob = g_catf + (size_t)(b*96 + out0 + g*4)*NN + p;
    ob[0*NN] = fmaxf(acc0 + bsh[0], 0.f);
    ob[1*NN] = fmaxf(acc1 + bsh[1], 0.f);
    ob[2*NN] = fmaxf(acc2 + bsh[2], 0.f);
    ob[3*NN] = fmaxf(acc3 + bsh[3], 0.f);
}

__global__ void k_deform_all(const float* __restrict__ w3, const float* __restrict__ b3,
                             const float* __restrict__ w5, const float* __restrict__ b5,
                             const float* __restrict__ w7, const float* __restrict__ b7) {
    __shared__ float ws[16*83];              // [w3 144 | w5 400 | w7 784]
    __shared__ float bsh[12];
    int tid = threadIdx.x;
    int gid = blockIdx.x*256 + tid;          // B*8*N
    int p = gid % NN;
    int g = (gid / NN) & 7;
    int b = gid / (8*NN);
    for (int i = tid; i < 144; i += 256) ws[i] = w3[g*144 + i];
    for (int i = tid; i < 400; i += 256) ws[144 + i] = w5[g*400 + i];
    for (int i = tid; i < 784; i += 256) ws[544 + i] = w7[g*784 + i];
    if (tid < 4)       bsh[tid]   = b3[g*4 + tid];
    else if (tid < 8)  bsh[tid]   = b5[g*4 + tid - 4];
    else if (tid < 12) bsh[tid]   = b7[g*4 + tid - 8];
    __syncthreads();
    int yy = p >> 7, xx = p & 127;
    const float2* offbase = g_offs2 + (size_t)(b*83)*NN + p;
    deform_one<3,1>(offbase,                 ws,     bsh,    yy, xx, b, g, p, 0);
    deform_one<5,2>(offbase + (size_t)9*NN,  ws+144, bsh+4,  yy, xx, b, g, p, 32);
    deform_one<7,3>(offbase + (size_t)34*NN, ws+544, bsh+8,  yy, xx, b, g, p, 64);
}

// ---------------- pointwise conv 96->32 with bias (4-way split) ----------------
__global__ void k_pw(const float* __restrict__ w, const float* __restrict__ bias) {
    __shared__ float ws[8*96];
    __shared__ float bs[8];
    int tid = threadIdx.x;
    int gid = blockIdx.x*256 + tid;          // B*4*N
    int p = gid % NN;
    int q = (gid / NN) & 3;
    int b = gid / (4*NN);
    for (int i = tid; i < 768; i += 256) ws[i] = w[(size_t)(q*8 + i/96)*96 + i%96];
    if (tid < 8) bs[tid] = bias[q*8 + tid];
    __syncthreads();
    float acc[8];
#pragma unroll
    for (int j = 0; j < 8; j++) acc[j] = bs[j];
    for (int c = 0; c < 96; c++) {
        float v = g_catf[(size_t)(b*96 + c)*NN + p];
#pragma unroll
        for (int j = 0; j < 8; j++) acc[j] += ws[j*96 + c]*v;
    }
#pragma unroll
    for (int j = 0; j < 8; j++) g_kfeat[(size_t)(b*32 + q*8 + j)*NN + p] = acc[j];
}

// ---------------- launch (kernel launches ONLY) ----------------
extern "C" void kernel_launch(void* const* d_in, const int* in_sizes, int n_in,
                              void* d_out, int out_size) {
    const float* x       = (const float*)d_in[0];
    const float* y       = (const float*)d_in[1];
    const float* temp    = (const float*)d_in[2];
    const float* w_po    = (const float*)d_in[3];
    const float* w_lp1   = (const float*)d_in[4];
    const float* w_lp2   = (const float*)d_in[5];
    const float* ln_g    = (const float*)d_in[6];
    const float* ln_b    = (const float*)d_in[7];
    const float* temp_in = (const float*)d_in[8];
    const float* w_qkv   = (const float*)d_in[9];
    const float* w_qkvd  = (const float*)d_in[10];
    const float* w_mproj = (const float*)d_in[11];
    const float* w_c3    = (const float*)d_in[12];
    const float* w_k2    = (const float*)d_in[13];
    const float* w_k3    = (const float*)d_in[14];
    const float* w_k4    = (const float*)d_in[15];
    const float* w_d3    = (const float*)d_in[16];
    const float* b_d3    = (const float*)d_in[17];
    const float* w_d5    = (const float*)d_in[18];
    const float* b_d5    = (const float*)d_in[19];
    const float* w_d7    = (const float*)d_in[20];
    const float* b_d7    = (const float*)d_in[21];
    const float* w_pw    = (const float*)d_in[22];
    const float* b_pw    = (const float*)d_in[23];

    // ---- merged setup (prepack + pool16 + pack_xy + stage zero + nhwc) ----
    k_setup<<<dim3(256, 8), 256>>>(x, y, w_lp2, w_c3, w_k2, w_k3, w_k4);   // 0

    // ---- alignment branch ----
    // a = sigmoid(conv3x3(pool, w_k2, pad=0)) at 62x62
    k_conv3x3_tc<64,166,1, 2,32, 0,6, 0,166, 23040, 64,64,62,62, 0>
        <<<dim3(31, 6, BB), 256>>>();                                      // 1
    // bmid16 = conv3x3(concat(x,y), w_k3) * nearest_up(a)  (bf16 packed out)
    k_conv3x3_tc<64,166,2, 1,32, 1,3, 0,83, 92160, 128,128,128,128, 1>
        <<<dim3(64, 6, BB), 256>>>();                                      // 2
    // offs2 = conv3x3(bmid16, w_k4)  (float2 (dy,dx) planes)
    k_conv3x3_tc<166,166,0, 3,83, 2,6, 0,83, 161280, 128,128,128,128, 1>
        <<<dim3(64, 6, BB), 256>>>();                                      // 3 <- profiled
    k_deform_all<<<(BB*8*NN)/256, 256>>>(w_d3, b_d3, w_d5, b_d5, w_d7, b_d7); // 4
    k_pw<<<(BB*4*NN)/256, 256>>>(w_pw, b_pw);                              // 5

    // ---- prompt branch ----
    k_ln_l1_qkv<<<(BB*4*NN)/256, 256>>>(x, ln_g, ln_b, w_lp1, w_qkv);      // 6
    // l2 = conv3x3(x, w_lp2) -> cat96p16 cp16..31 (bf16 packed out)
    k_conv3x3_tc<32,32,0, 1,32, 1,4, 32,48, 0, 128,128,128,128, 1>
        <<<dim3(64, 1, BB), 256>>>();                                      // 7
    k_qkvd<<<(BB*32*NN)/256, 256>>>(w_qkvd);                               // 8
    k_gramacc<0><<<BB*8*16, 256>>>(x);                                     // 9
    k_meffsm<0><<<BB, 1024>>>(w_mproj, temp_in);                           // 10
    k_apply<0><<<(BB*4*NN)/256, 256>>>(x, nullptr);                        // 11
    // prompt = conv3x3(cat96p16, w_c3)
    k_conv3x3_tc<96,32,0, 4,48, 0,11, 0,32, 5760, 128,128,128,128, 1>
        <<<dim3(64, 1, BB), 256>>>();                                      // 12

    // ---- final prompted channel attention ----
    k_gramacc<1><<<BB*8*16, 256>>>(x);                                     // 13
    k_meffsm<1><<<BB, 1024>>>(w_po, temp);                                 // 14
    k_apply<1><<<(BB*4*NN)/256, 256>>>(x, (float*)d_out);                  // 15
}

// round 12
// speedup vs baseline: 3.1425x; 1.0727x over previous
#include <cuda_runtime.h>
#include <math.h>
#include <stdint.h>

#define BB 2
#define CCH 32
#define HH 128
#define WW 128
#define NN (HH*WW)
#define NHEADS 8

// ---------------- scratch (static device globals; no allocation) ----------------
__device__ float g_qkv[BB*96*NN];
__device__ float g_qkvd[BB*96*NN];     // q|k|v after grouped dwconv
__device__ float g_asmall[BB*166*62*62];
__device__ float2 g_offs2[BB*83*NN];   // k4 output: (dy,dx) float2 planes
__device__ float g_catf[BB*96*NN];     // [f3 | f5 | f7]
__device__ float g_kfeat[BB*CCH*NN];
__device__ float g_prompt[BB*CCH*NN];
__device__ float4 g_xnhwc4[BB*NN*8];   // x in NHWC, float4-grouped (16B aligned)
__device__ float g_stage_in[BB*8*24];  // dots[16] | q2[4] | k2[4]
__device__ float g_stage_f[BB*8*44];   // dots[32] | q2[8] | k2[4]
__device__ float g_Meff_in[BB*32*32];
__device__ float g_Meff_f[BB*32*32];

// bf16x2 pair-interleaved staging (u32 = channels (2c, 2c+1))
__device__ uint32_t g_xy16[BB*32*NN];      // cp 0..15 = x, 16..31 = y
__device__ uint32_t g_pool16[BB*32*64*64]; // pooled concat(x,y)
__device__ uint32_t g_bmid16[BB*83*NN];    // k3 output (166 ch -> 83 cp)
__device__ uint32_t g_cat96p16[BB*48*NN];  // [l1 cp0-15 | l2 cp16-31 | xg cp32-47]
__device__ uint32_t g_w16[351360];         // prepacked conv weights (sW image, pitch 40)

// compile-time scratch-buffer resolution
template<int ID> __device__ __forceinline__ float* gbuf();
template<> __device__ __forceinline__ float* gbuf<6>()  { return g_asmall; }
template<> __device__ __forceinline__ float* gbuf<11>() { return g_prompt; }
template<int ID> __device__ __forceinline__ uint32_t* gbufu();
template<> __device__ __forceinline__ uint32_t* gbufu<1>() { return g_xy16; }
template<> __device__ __forceinline__ uint32_t* gbufu<2>() { return g_pool16; }
template<> __device__ __forceinline__ uint32_t* gbufu<3>() { return g_bmid16; }
template<> __device__ __forceinline__ uint32_t* gbufu<4>() { return g_cat96p16; }

// ---------------- bf16 helpers ----------------
__device__ __forceinline__ uint32_t pack_bf16x2(float lo, float hi) {
    uint32_t r;
    asm("cvt.rn.bf16x2.f32 %0, %1, %2;" : "=r"(r) : "f"(hi), "f"(lo));
    return r;
}
__device__ __forceinline__ void mma_bf16(float* d, uint32_t a0, uint32_t a1,
                                         uint32_t a2, uint32_t a3,
                                         uint32_t b0, uint32_t b1) {
    asm volatile("mma.sync.aligned.m16n8k16.row.col.f32.bf16.bf16.f32 "
        "{%0,%1,%2,%3}, {%4,%5,%6,%7}, {%8,%9}, {%0,%1,%2,%3};\n"
        : "+f"(d[0]), "+f"(d[1]), "+f"(d[2]), "+f"(d[3])
        : "r"(a0), "r"(a1), "r"(a2), "r"(a3), "r"(b0), "r"(b1));
}

// ---------------- merged setup ----------------
// blockIdx.y: 0..4 = prepack conv, 5 = pool16 (+stage zero), 6 = pack_xy, 7 = nhwc
__global__ void k_setup(const float* __restrict__ x, const float* __restrict__ y,
                        const float* __restrict__ w_lp2, const float* __restrict__ w_c3,
                        const float* __restrict__ w_k2, const float* __restrict__ w_k3,
                        const float* __restrict__ w_k4) {
    __shared__ float s[32][65];
    const int cy = blockIdx.y;
    const int tid0 = blockIdx.x*256 + threadIdx.x;
    const int stride = gridDim.x*256;
    if (cy < 5) {
        const int CINs[5]  = {32, 96, 64, 64, 166};
        const int COUTs[5] = {32, 32, 166, 166, 166};
        const int NCHs[5]  = {2, 6, 4, 4, 11};
        const int OCTs[5]  = {1, 1, 6, 6, 6};
        const int PERMs[5] = {1, 0, 0, 1, 1};
        const int OFFs[5]  = {0, 5760, 23040, 92160, 161280};
        const float* wsv[5] = {w_lp2, w_c3, w_k2, w_k3, w_k4};
        const int CIN = CINs[cy], COUT = COUTs[cy], NCH = NCHs[cy], PERM = PERMs[cy];
        const float* w = wsv[cy];
        const int total = OCTs[cy]*NCH*2880;
        for (int i = tid0; i < total; i += stride) {
            int within = i % 2880;
            int tile   = i / 2880;
            int oc = within % 40;
            int ck = within / 40;
            int k  = ck % 9;
            int cp = ck / 9;
            int chunk  = tile % NCH;
            int octile = tile / NCH;
            uint32_t val = 0;
            if (oc < 32) {
                int pc = PERM ? ((oc & 16) + 2*(oc & 7) + ((oc >> 3) & 1)) : oc;
                int chn = octile*32 + pc;
                int c0 = chunk*16 + 2*cp;
                float v0 = 0.f, v1 = 0.f;
                if (chn < COUT && c0 < CIN) {
                    v0 = w[((size_t)chn*CIN + c0)*9 + k];
                    v1 = w[((size_t)chn*CIN + c0 + 1)*9 + k];
                }
                val = pack_bf16x2(v0, v1);
            }
            g_w16[OFFs[cy] + i] = val;
        }
    } else if (cy == 5) {
        if (blockIdx.x == 0) {
            for (int i = threadIdx.x; i < BB*8*24; i += 256) g_stage_in[i] = 0.f;
            for (int i = threadIdx.x; i < BB*8*44; i += 256) g_stage_f[i] = 0.f;
        }
        for (int gid = tid0; gid < BB*32*4096; gid += stride) {
            int px = gid & 63;
            int py = (gid >> 6) & 63;
            int cp = (gid >> 12) & 31;
            int b  = gid >> 17;
            const float* sp = (cp < 16) ? x + (size_t)(b*32 + 2*cp)*NN
                                        : y + (size_t)(b*32 + 2*(cp-16))*NN;
            int iy = 2*py, ix = 2*px;
            float v0 = 0.25f*(sp[iy*WW+ix] + sp[iy*WW+ix+1] + sp[(iy+1)*WW+ix] + sp[(iy+1)*WW+ix+1]);
            const float* s1 = sp + NN;
            float v1 = 0.25f*(s1[iy*WW+ix] + s1[iy*WW+ix+1] + s1[(iy+1)*WW+ix] + s1[(iy+1)*WW+ix+1]);
            g_pool16[(size_t)(b*32 + cp)*4096 + py*64 + px] = pack_bf16x2(v0, v1);
        }
    } else if (cy == 6) {
        for (int gid = tid0; gid < BB*32*NN; gid += stride) {
            int p = gid % NN;
            int cp = (gid / NN) % 32;
            int b = gid / (32*NN);
            const float* sp = (cp < 16) ? x + (size_t)(b*32 + 2*cp)*NN
                                        : y + (size_t)(b*32 + 2*(cp-16))*NN;
            g_xy16[(size_t)(b*32 + cp)*NN + p] = pack_bf16x2(sp[p], sp[NN + p]);
        }
    } else {
        const int tid = threadIdx.x;
        for (int blk = blockIdx.x; blk < BB*(NN/64); blk += gridDim.x) {
            int b = blk / (NN/64);
            int px0 = (blk % (NN/64)) * 64;
#pragma unroll
            for (int k = 0; k < 8; k++) {
                int ch = k*4 + (tid >> 6);
                int px = tid & 63;
                s[ch][px] = x[(size_t)(b*32 + ch)*NN + px0 + px];
            }
            __syncthreads();
            float* xn = (float*)g_xnhwc4;
#pragma unroll
            for (int k = 0; k < 8; k++) {
                int px = k*8 + (tid >> 5);
                int ch = tid & 31;
                xn[(size_t)(b*NN + px0 + px)*32 + ch] = s[ch][px];
            }
            __syncthreads();
        }
    }
}

// ---------------- conv3x3 body (device fn; smem passed in) ----------------
// identical math/pipeline to R11; flat bid decoded inside.
template<int CIN, int COUT, int EPI, int SRCU, int CPTOT, int OUTM, int DSTID,
         int OUTC0, int OUTCTOT, int W16OFF,
         int HIN, int WIN, int HOUT, int WOUT, int PAD>
__device__ __forceinline__ void conv3x3_body(uint32_t* sIn, uint32_t* sW, int bid) {
    constexpr int CP = CIN/2;
    constexpr int NCHUNK = (CP + 7) / 8;
    constexpr int PITCH = 134;
    constexpr int ROWS = HOUT/2;
    constexpr int OCT = (COUT + 31)/32;
    const uint32_t* src16 = gbufu<SRCU>();
    const int y0  = (bid % ROWS) * 2;
    const int oc0 = ((bid / ROWS) % OCT) * 32;
    const int b   = bid / (ROWS*OCT);
    const int tid = threadIdx.x;
    const int lane = tid & 31, wid5 = tid >> 5;
    const int wy = wid5 >> 2, wn = wid5 & 3;
    const int g = lane >> 2, tg = lane & 3;

    float acc[2][4][4];
#pragma unroll
    for (int m = 0; m < 2; m++)
#pragma unroll
        for (int t = 0; t < 4; t++)
#pragma unroll
            for (int r = 0; r < 4; r++) acc[m][t][r] = 0.f;

    const uint32_t* wbase = g_w16 + W16OFF + (size_t)(oc0 >> 5)*NCHUNK*2880;

    uint32_t ireg[20];
    uint32_t wreg[12];
    auto load_regs = [&](int ch) {
        int cpg = ch*8 + wid5;
        bool cpv = cpg < CP;
        const uint32_t* sp = src16 + (size_t)(b*CPTOT + cpg)*(HIN*WIN);
#pragma unroll
        for (int row = 0; row < 4; row++) {
            int gy = y0 - PAD + row;
            bool yv = cpv && ((unsigned)gy < (unsigned)HIN);
            const uint32_t* rp = sp + (size_t)gy*WIN;
#pragma unroll
            for (int kk = 0; kk < 5; kk++) {
                int px = lane + 32*kk;
                uint32_t v = 0;
                if (px < PITCH) {
                    int gx = px - PAD;
                    if (yv && (unsigned)gx < (unsigned)WIN) v = rp[gx];
                }
                ireg[row*5 + kk] = v;
            }
        }
        const uint32_t* wp = wbase + ch*2880;
#pragma unroll
        for (int j = 0; j < 12; j++) {
            int i = tid + j*256;
            wreg[j] = (i < 2880) ? wp[i] : 0u;
        }
    };
    auto store_smem = [&]() {
#pragma unroll
        for (int row = 0; row < 4; row++) {
            uint32_t* sd = sIn + (wid5*4 + row)*PITCH;
#pragma unroll
            for (int kk = 0; kk < 5; kk++) {
                int px = lane + 32*kk;
                if (px < PITCH) sd[px] = ireg[row*5 + kk];
            }
        }
#pragma unroll
        for (int j = 0; j < 12; j++) {
            int i = tid + j*256;
            if (i < 2880) sW[i] = wreg[j];
        }
    };

    load_regs(0);
    store_smem();
    __syncthreads();

    for (int ch = 0; ch < NCHUNK; ch++) {
        if (ch + 1 < NCHUNK) load_regs(ch + 1);
#pragma unroll
        for (int kpos = 0; kpos < 9; kpos++) {
            const int ky = kpos / 3, kx = kpos % 3;
            uint32_t a[2][4];
#pragma unroll
            for (int m = 0; m < 2; m++) {
                const int aoc = m*16 + g;
                a[m][0] = sW[(tg*9 + kpos)*40 + aoc];
                a[m][1] = sW[(tg*9 + kpos)*40 + aoc + 8];
                a[m][2] = sW[((tg+4)*9 + kpos)*40 + aoc];
                a[m][3] = sW[((tg+4)*9 + kpos)*40 + aoc + 8];
            }
            const int r0 = (tg*4 + wy + ky)*PITCH + kx;
            const int r1 = ((tg+4)*4 + wy + ky)*PITCH + kx;
#pragma unroll
            for (int t = 0; t < 4; t++) {
                int px = wn*32 + t*8 + g;
                uint32_t b0 = sIn[r0 + px], b1 = sIn[r1 + px];
                mma_bf16(acc[0][t], a[0][0], a[0][1], a[0][2], a[0][3], b0, b1);
                mma_bf16(acc[1][t], a[1][0], a[1][1], a[1][2], a[1][3], b0, b1);
            }
        }
        __syncthreads();
        if (ch + 1 < NCHUNK) {
            store_smem();
            __syncthreads();
        }
    }
    const int y = y0 + wy;
#pragma unroll
    for (int m = 0; m < 2; m++) {
        if (OUTM == 1) {
            int chan0 = oc0 + m*16 + 2*g;
            if (chan0 < COUT) {
                uint32_t* op = gbufu<(OUTM == 1) ? DSTID : 1>()
                    + (size_t)(b*OUTCTOT + (OUTC0 + chan0)/2)*(HOUT*WOUT) + (size_t)y*WOUT;
#pragma unroll
                for (int t = 0; t < 4; t++) {
                    int px = wn*32 + t*8 + 2*tg;
                    float v00 = acc[m][t][0], v01 = acc[m][t][1];
                    float v10 = acc[m][t][2], v11 = acc[m][t][3];
                    if (EPI == 2) {
                        int ay = (y * 62) >> 7;
                        int ax0 = (px * 62) >> 7, ax1 = ((px+1) * 62) >> 7;
                        const float* a0p = g_asmall + ((size_t)(b*166 + chan0)*62 + ay)*62;
                        const float* a1p = a0p + 62*62;
                        v00 *= a0p[ax0]; v01 *= a0p[ax1];
                        v10 *= a1p[ax0]; v11 *= a1p[ax1];
                    }
                    op[px]   = pack_bf16x2(v00, v10);
                    op[px+1] = pack_bf16x2(v01, v11);
                }
            }
        } else if (OUTM == 2) {
            int chan0 = oc0 + m*16 + 2*g;
            if (chan0 < COUT) {
                float2* op = g_offs2 + (size_t)(b*83 + chan0/2)*(HOUT*WOUT) + (size_t)y*WOUT;
#pragma unroll
                for (int t = 0; t < 4; t++) {
                    int px = wn*32 + t*8 + 2*tg;
                    op[px]   = make_float2(acc[m][t][0], acc[m][t][2]);
                    op[px+1] = make_float2(acc[m][t][1], acc[m][t][3]);
                }
            }
        } else {
            float* dst = gbuf<(OUTM == 0) ? DSTID : 6>();
            const int ocr0 = oc0 + m*16 + g;
#pragma unroll
            for (int t = 0; t < 4; t++) {
                int px = wn*32 + t*8 + 2*tg;
#pragma unroll
                for (int half = 0; half < 2; half++) {
                    int ocr = ocr0 + half*8;
                    if (ocr >= COUT) continue;
                    float v0 = acc[m][t][half*2 + 0];
                    float v1 = acc[m][t][half*2 + 1];
                    if (EPI == 1) {
                        v0 = 1.f / (1.f + expf(-v0));
                        v1 = 1.f / (1.f + expf(-v1));
                    }
                    float* opf = dst + (size_t)(b*OUTCTOT + OUTC0 + ocr)*(HOUT*WOUT) + (size_t)y*WOUT;
                    if (px   < WOUT) opf[px]   = v0;
                    if (px+1 < WOUT) opf[px+1] = v1;
                }
            }
        }
    }
}

// ---------------- other bodies (device fns, smem passed in) ----------------
__device__ __forceinline__ void ln_l1_qkv_body(float* sf, int blk,
        const float* __restrict__ x, const float* __restrict__ ln_g,
        const float* __restrict__ ln_b, const float* __restrict__ w_lp1,
        const float* __restrict__ w_qkv) {
    float* sw = sf;            // 1024
    float* s_g = sf + 1024;    // 32
    float* s_b = sf + 1056;    // 32
    int tid = threadIdx.x;
    int gid = blk*256 + tid;                 // B*4*N
    int p = gid % NN;
    int q = (gid / NN) & 3;
    int b = gid / (4*NN);
    const float* wsrc = (q == 0) ? w_lp1 : w_qkv + (size_t)(q-1)*1024;
    for (int i = tid; i < 1024; i += 256) sw[i] = wsrc[i];
    if (tid < 32) { s_g[tid] = ln_g[tid]; s_b[tid] = ln_b[tid]; }
    __syncthreads();
    float xv[32];
#pragma unroll
    for (int c = 0; c < 32; c++) xv[c] = x[(size_t)(b*32 + c)*NN + p];
    if (q == 0) {
#pragma unroll
        for (int m = 0; m < 16; m++) {
            float a0 = 0.f, a1 = 0.f;
#pragma unroll
            for (int c = 0; c < 32; c++) {
                a0 += sw[(2*m)*32 + c]*xv[c];
                a1 += sw[(2*m+1)*32 + c]*xv[c];
            }
            g_cat96p16[(size_t)(b*48 + m)*NN + p] = pack_bf16x2(a0, a1);
        }
    } else {
        float mu = 0.f;
#pragma unroll
        for (int c = 0; c < 32; c++) mu += xv[c];
        mu *= (1.f/32.f);
        float var = 0.f;
#pragma unroll
        for (int c = 0; c < 32; c++) { float d = xv[c]-mu; var += d*d; }
        var *= (1.f/32.f);
        float inv = rsqrtf(var + 1e-5f);
        float vin[32];
#pragma unroll
        for (int c = 0; c < 32; c++) vin[c] = (xv[c]-mu)*inv*s_g[c] + s_b[c];
        float* outbase = g_qkv + (size_t)(b*96 + (q-1)*32)*NN;
        for (int o = 0; o < 32; o++) {
            float a = 0.f;
#pragma unroll
            for (int c = 0; c < 32; c++) a += sw[o*32+c]*vin[c];
            outbase[(size_t)o*NN + p] = a;
        }
    }
}

__device__ __forceinline__ void qkvd_body(float* ws, int blk, const float* __restrict__ w) {
    int tid = threadIdx.x;
    for (int i = tid; i < 96*27; i += 256) ws[i] = w[i];
    __syncthreads();
    int gid = blk*256 + tid;
    int p = gid % NN;
    int g = (gid / NN) % 32;
    int b = gid / (32*NN);
    int y = p >> 7, xx = p & 127;
    float a0 = 0.f, a1 = 0.f, a2 = 0.f;
    const float* inb = g_qkv + (size_t)(b*96 + 3*g)*NN;
#pragma unroll
    for (int ky = 0; ky < 3; ky++) {
        int gy = y - 1 + ky;
        if (gy < 0 || gy >= HH) continue;
#pragma unroll
        for (int kx = 0; kx < 3; kx++) {
            int gx = xx - 1 + kx;
            if (gx < 0 || gx >= WW) continue;
            int kk = ky*3 + kx;
#pragma unroll
            for (int ci = 0; ci < 3; ci++) {
                float v = inb[ci*NN + gy*WW + gx];
                a0 += ws[(3*g+0)*27 + ci*9 + kk]*v;
                a1 += ws[(3*g+1)*27 + ci*9 + kk]*v;
                a2 += ws[(3*g+2)*27 + ci*9 + kk]*v;
            }
        }
    }
    g_qkvd[(size_t)(b*96 + 3*g+0)*NN + p] = a0;
    g_qkvd[(size_t)(b*96 + 3*g+1)*NN + p] = a1;
    g_qkvd[(size_t)(b*96 + 3*g+2)*NN + p] = a2;
}

template<int MODE>
__device__ __forceinline__ void gramacc_body(float* red, int b, int h, int slice,
                                             const float* __restrict__ xin) {
    constexpr int D = (MODE == 0) ? 4 : 8;
    constexpr int E = 4;
    constexpr int NS = D*E + D + E;
    constexpr int SL = 16;
    int tid = threadIdx.x;
    const float* qbase;
    if (MODE == 0) qbase = g_qkvd + (size_t)(b*96 + h*D)*NN;
    else qbase = (h < 4) ? xin + (size_t)(b*32 + h*8)*NN
                         : g_prompt + (size_t)(b*32 + (h-4)*8)*NN;
    const float* kbase = (MODE == 0) ? g_qkvd + (size_t)(b*96 + 32 + h*E)*NN
                                     : g_kfeat + (size_t)(b*32 + h*E)*NN;
    float acc[NS];
#pragma unroll
    for (int i = 0; i < NS; i++) acc[i] = 0.f;
    int n0 = slice * (NN/SL);
    for (int it = 0; it < (NN/SL)/256; it++) {
        int n = n0 + it*256 + tid;
        float qv[D], kv[E];
#pragma unroll
        for (int d = 0; d < D; d++) qv[d] = qbase[(size_t)d*NN + n];
#pragma unroll
        for (int e = 0; e < E; e++) kv[e] = kbase[(size_t)e*NN + n];
#pragma unroll
        for (int d = 0; d < D; d++)
#pragma unroll
            for (int e = 0; e < E; e++) acc[d*E+e] += qv[d]*kv[e];
#pragma unroll
        for (int d = 0; d < D; d++) acc[D*E + d] += qv[d]*qv[d];
#pragma unroll
        for (int e = 0; e < E; e++) acc[D*E + D + e] += kv[e]*kv[e];
    }
    if (tid < NS) red[tid] = 0.f;
    __syncthreads();
    int lane = tid & 31;
#pragma unroll
    for (int i = 0; i < NS; i++) {
        float v = acc[i];
#pragma unroll
        for (int o = 16; o > 0; o >>= 1) v += __shfl_down_sync(0xffffffffu, v, o);
        if (lane == 0) atomicAdd(&red[i], v);
    }
    __syncthreads();
    float* st = (MODE == 0) ? g_stage_in + (b*8 + h)*24 : g_stage_f + (b*8 + h)*44;
    if (tid < NS) atomicAdd(&st[tid], red[tid]);
}

// 256-thread meffsm for MODE 0 (D=4)
__device__ __forceinline__ void meffsm0_body(float* sA, int b,
        const float* __restrict__ wmat, const float* __restrict__ tempv) {
    int t = threadIdx.x;
    if (t < 32) {
        int h = t >> 2, d = t & 3;
        const float* st = g_stage_in + (b*8 + h)*24;
        float qn = fmaxf(sqrtf(st[16 + d]), 1e-12f);
        float tp = tempv[h];
        float row[4];
        float mx = -1e30f;
#pragma unroll
        for (int e = 0; e < 4; e++) {
            float kn = fmaxf(sqrtf(st[20 + e]), 1e-12f);
            row[e] = st[d*4+e] / (qn*kn) * tp;
            mx = fmaxf(mx, row[e]);
        }
        float sum = 0.f;
#pragma unroll
        for (int e = 0; e < 4; e++) { row[e] = expf(row[e]-mx); sum += row[e]; }
        float isum = 1.f/sum;
#pragma unroll
        for (int e = 0; e < 4; e++) sA[(h*4 + d)*4 + e] = row[e]*isum;
    }
    __syncthreads();
#pragma unroll
    for (int r = 0; r < 4; r++) {
        int idx = r*256 + t;
        int o = idx >> 5, vc = idx & 31, h = vc >> 2, e = vc & 3;
        float s = 0.f;
#pragma unroll
        for (int d = 0; d < 4; d++)
            s += wmat[o*32 + h*4 + d] * sA[(h*4 + d)*4 + e];
        g_Meff_in[b*1024 + o*32 + vc] = s;
    }
}

// standalone 1024-thread meffsm for MODE 1 (D=8)
__global__ void k_meffsm1(const float* __restrict__ wmat, const float* __restrict__ tempv) {
    constexpr int D = 8;
    int b = blockIdx.x;
    int t = threadIdx.x;
    __shared__ float sA[8*D*4];
    if (t < 8*D) {
        int h = t / D, d = t % D;
        const float* st = g_stage_f + (b*8 + h)*44;
        float qn = fmaxf(sqrtf(st[D*4 + d]), 1e-12f);
        float tp = tempv[h];
        float row[4];
        float mx = -1e30f;
#pragma unroll
        for (int e = 0; e < 4; e++) {
            float kn = fmaxf(sqrtf(st[D*4 + D + e]), 1e-12f);
            row[e] = st[d*4+e] / (qn*kn) * tp;
            mx = fmaxf(mx, row[e]);
        }
        float sum = 0.f;
#pragma unroll
        for (int e = 0; e < 4; e++) { row[e] = expf(row[e]-mx); sum += row[e]; }
        float isum = 1.f/sum;
#pragma unroll
        for (int e = 0; e < 4; e++) sA[(h*D + d)*4 + e] = row[e]*isum;
    }
    __syncthreads();
    int o = t >> 5, vc = t & 31, h = vc >> 2, e = vc & 3;
    float s = 0.f;
#pragma unroll
    for (int d = 0; d < D; d++)
        s += wmat[o*(8*D) + h*D + d] * sA[(h*D + d)*4 + e];
    g_Meff_f[b*1024 + o*32 + vc] = s;
}

template<int MODE>
__device__ __forceinline__ void apply_body(float* sm, int blk,
        const float* __restrict__ xin, float* __restrict__ outp) {
    int tid = threadIdx.x;
    int gid = blk*256 + tid;                 // B*4*N
    int p = gid % NN;
    int q = (gid / NN) & 3;
    int b = gid / (4*NN);
    const float* M = (MODE == 0) ? g_Meff_in : g_Meff_f;
    if (tid < 256) sm[tid] = M[b*1024 + q*256 + tid];
    __syncthreads();
    float vv[32];
#pragma unroll
    for (int c = 0; c < 32; c++) {
        if (MODE == 0) vv[c] = g_qkvd[(size_t)(b*96 + 64 + c)*NN + p];
        else           vv[c] = xin[(size_t)(b*32 + c)*NN + p];
    }
    float av[8];
#pragma unroll
    for (int j = 0; j < 8; j++) {
        int o = q*8 + j;
        float a = (MODE == 0) ? xin[(size_t)(b*32 + o)*NN + p] : 0.f;
#pragma unroll
        for (int c = 0; c < 32; c++) a += sm[j*32+c]*vv[c];
        av[j] = a;
    }
    if (MODE == 0) {
#pragma unroll
        for (int m = 0; m < 4; m++)
            g_cat96p16[(size_t)(b*48 + 32 + q*4 + m)*NN + p] = pack_bf16x2(av[2*m], av[2*m+1]);
    } else {
#pragma unroll
        for (int j = 0; j < 8; j++)
            outp[(size_t)(b*32 + q*8 + j)*NN + p] = av[j];
    }
}

template<int K, int PAD>
__device__ __forceinline__ void deform_one(const float2* __restrict__ offp,
                                           const float* __restrict__ ws,
                                           const float* __restrict__ bsh,
                                           int yy, int xx, int b, int g, int p,
                                           int out0) {
    constexpr int K2 = K*K;
    float acc0 = 0.f, acc1 = 0.f, acc2 = 0.f, acc3 = 0.f;
    const float4* xb = g_xnhwc4 + (size_t)b*NN*8 + g;
    for (int k2 = 0; k2 < K2; k2++) {
        float2 d = offp[(size_t)k2*NN];
        float py = (float)(yy - PAD + k2 / K) + d.x;
        float px = (float)(xx - PAD + k2 % K) + d.y;
        float y0f = floorf(py), x0f = floorf(px);
        float wy = py - y0f, wx = px - x0f;
        int y0 = (int)y0f, x0 = (int)x0f;
        float w00 = (1.f-wy)*(1.f-wx), w01 = (1.f-wy)*wx, w10 = wy*(1.f-wx), w11 = wy*wx;
        bool iy0 = (y0 >= 0 && y0 < HH), iy1 = (y0+1 >= 0 && y0+1 < HH);
        bool ix0 = (x0 >= 0 && x0 < WW), ix1 = (x0+1 >= 0 && x0+1 < WW);
        float4 s = make_float4(0.f, 0.f, 0.f, 0.f);
        if (iy0 && ix0) {
            float4 v = xb[(size_t)(y0*WW + x0)*8];
            s.x += w00*v.x; s.y += w00*v.y; s.z += w00*v.z; s.w += w00*v.w;
        }
        if (iy0 && ix1) {
            float4 v = xb[(size_t)(y0*WW + x0 + 1)*8];
            s.x += w01*v.x; s.y += w01*v.y; s.z += w01*v.z; s.w += w01*v.w;
        }
        if (iy1 && ix0) {
            float4 v = xb[(size_t)((y0+1)*WW + x0)*8];
            s.x += w10*v.x; s.y += w10*v.y; s.z += w10*v.z; s.w += w10*v.w;
        }
        if (iy1 && ix1) {
            float4 v = xb[(size_t)((y0+1)*WW + x0 + 1)*8];
            s.x += w11*v.x; s.y += w11*v.y; s.z += w11*v.z; s.w += w11*v.w;
        }
        acc0 += ws[(0*4+0)*K2+k2]*s.x + ws[(0*4+1)*K2+k2]*s.y + ws[(0*4+2)*K2+k2]*s.z + ws[(0*4+3)*K2+k2]*s.w;
        acc1 += ws[(1*4+0)*K2+k2]*s.x + ws[(1*4+1)*K2+k2]*s.y + ws[(1*4+2)*K2+k2]*s.z + ws[(1*4+3)*K2+k2]*s.w;
        acc2 += ws[(2*4+0)*K2+k2]*s.x + ws[(2*4+1)*K2+k2]*s.y + ws[(2*4+2)*K2+k2]*s.z + ws[(2*4+3)*K2+k2]*s.w;
        acc3 += ws[(3*4+0)*K2+k2]*s.x + ws[(3*4+1)*K2+k2]*s.y + ws[(3*4+2)*K2+k2]*s.z + ws[(3*4+3)*K2+k2]*s.w;
    }
    float* ob = g_catf + (size_t)(b*96 + out0 + g*4)*NN + p;
    ob[0*NN] = fmaxf(acc0 + bsh[0], 0.f);
    ob[1*NN] = fmaxf(acc1 + bsh[1], 0.f);
    ob[2*NN] = fmaxf(acc2 + bsh[2], 0.f);
    ob[3*NN] = fmaxf(acc3 + bsh[3], 0.f);
}

__device__ __forceinline__ void deform_all_body(float* ws, int blk,
        const float* __restrict__ w3, const float* __restrict__ b3,
        const float* __restrict__ w5, const float* __restrict__ b5,
        const float* __restrict__ w7, const float* __restrict__ b7) {
    float* bsh = ws + 1328;
    int tid = threadIdx.x;
    int gid = blk*256 + tid;                 // B*8*N
    int p = gid % NN;
    int g = (gid / NN) & 7;
    int b = gid / (8*NN);
    for (int i = tid; i < 144; i += 256) ws[i] = w3[g*144 + i];
    for (int i = tid; i < 400; i += 256) ws[144 + i] = w5[g*400 + i];
    for (int i = tid; i < 784; i += 256) ws[544 + i] = w7[g*784 + i];
    if (tid < 4)       bsh[tid] = b3[g*4 + tid];
    else if (tid < 8)  bsh[tid] = b5[g*4 + tid - 4];
    else if (tid < 12) bsh[tid] = b7[g*4 + tid - 8];
    __syncthreads();
    int yy = p >> 7, xx = p & 127;
    const float2* offbase = g_offs2 + (size_t)(b*83)*NN + p;
    deform_one<3,1>(offbase,                 ws,     bsh,    yy, xx, b, g, p, 0);
    deform_one<5,2>(offbase + (size_t)9*NN,  ws+144, bsh+4,  yy, xx, b, g, p, 32);
    deform_one<7,3>(offbase + (size_t)34*NN, ws+544, bsh+8,  yy, xx, b, g, p, 64);
}

__device__ __forceinline__ void pw_body(float* ws, int blk,
        const float* __restrict__ w, const float* __restrict__ bias) {
    float* bs = ws + 768;
    int tid = threadIdx.x;
    int gid = blk*256 + tid;                 // B*4*N
    int p = gid % NN;
    int q = (gid / NN) & 3;
    int b = gid / (4*NN);
    for (int i = tid; i < 768; i += 256) ws[i] = w[(size_t)(q*8 + i/96)*96 + i%96];
    if (tid < 8) bs[tid] = bias[q*8 + tid];
    __syncthreads();
    float acc[8];
#pragma unroll
    for (int j = 0; j < 8; j++) acc[j] = bs[j];
    for (int c = 0; c < 96; c++) {
        float v = g_catf[(size_t)(b*96 + c)*NN + p];
#pragma unroll
        for (int j = 0; j < 8; j++) acc[j] += ws[j*96 + c]*v;
    }
#pragma unroll
    for (int j = 0; j < 8; j++) g_kfeat[(size_t)(b*32 + q*8 + j)*NN + p] = acc[j];
}

// ---------------- merged launch wrappers ----------------
// M1: [0,372) k2conv | [372,884) ln_l1_qkv | [884,1012) l2conv
__global__ void __launch_bounds__(256, 2) k_m1(const float* __restrict__ x,
        const float* __restrict__ ln_g, const float* __restrict__ ln_b,
        const float* __restrict__ w_lp1, const float* __restrict__ w_qkv) {
    __shared__ uint32_t sbuf[7168];
    int bid = blockIdx.x;
    if (bid < 372) {
        conv3x3_body<64,166,1, 2,32, 0,6, 0,166, 23040, 64,64,62,62, 0>(sbuf, sbuf + 4288, bid);
    } else if (bid < 884) {
        ln_l1_qkv_body((float*)sbuf, bid - 372, x, ln_g, ln_b, w_lp1, w_qkv);
    } else {
        conv3x3_body<32,32,0, 1,32, 1,4, 32,48, 0, 128,128,128,128, 1>(sbuf, sbuf + 4288, bid - 884);
    }
}

// M2: [0,768) k3conv | [768,1792) qkvd
__global__ void __launch_bounds__(256, 2) k_m2(const float* __restrict__ w_qkvd) {
    __shared__ uint32_t sbuf[7168];
    int bid = blockIdx.x;
    if (bid < 768) {
        conv3x3_body<64,166,2, 1,32, 1,3, 0,83, 92160, 128,128,128,128, 1>(sbuf, sbuf + 4288, bid);
    } else {
        qkvd_body((float*)sbuf, bid - 768, w_qkvd);
    }
}

// M3: [0,768) k4conv | [768,1024) gramacc0
__global__ void __launch_bounds__(256, 2) k_m3(const float* __restrict__ x) {
    __shared__ uint32_t sbuf[7168];
    int bid = blockIdx.x;
    if (bid < 768) {
        conv3x3_body<166,166,0, 3,83, 2,6, 0,83, 161280, 128,128,128,128, 1>(sbuf, sbuf + 4288, bid);
    } else {
        int i = bid - 768;                  // b*128 + h*16 + slice
        gramacc_body<0>((float*)sbuf, i >> 7, (i >> 4) & 7, i & 15, x);
    }
}

// M4: [0,1024) deform | [1024,1026) meffsm0
__global__ void k_m4(const float* __restrict__ w3, const float* __restrict__ b3,
                     const float* __restrict__ w5, const float* __restrict__ b5,
                     const float* __restrict__ w7, const float* __restrict__ b7,
                     const float* __restrict__ w_mproj, const float* __restrict__ temp_in) {
    __shared__ float sf[1344];
    int bid = blockIdx.x;
    if (bid < 1024) {
        deform_all_body(sf, bid, w3, b3, w5, b5, w7, b7);
    } else {
        meffsm0_body(sf, bid - 1024, w_mproj, temp_in);
    }
}

// M5: [0,512) pw | [512,1024) apply0
__global__ void k_m5(const float* __restrict__ w_pw, const float* __restrict__ b_pw,
                     const float* __restrict__ x) {
    __shared__ float sf[800];
    int bid = blockIdx.x;
    if (bid < 512) {
        pw_body(sf, bid, w_pw, b_pw);
    } else {
        apply_body<0>(sf, bid - 512, x, nullptr);
    }
}

// M6: [0,128) c3conv | [128,256) gramacc1 with h<4 (x-half; needs only x+kfeat)
__global__ void __launch_bounds__(256, 2) k_m6(const float* __restrict__ x) {
    __shared__ uint32_t sbuf[7168];
    int bid = blockIdx.x;
    if (bid < 128) {
        conv3x3_body<96,32,0, 4,48, 0,11, 0,32, 5760, 128,128,128,128, 1>(sbuf, sbuf + 4288, bid);
    } else {
        int i = bid - 128;                  // 128: b(1) x h(2) x slice(4) bits
        gramacc_body<1>((float*)sbuf, i >> 6, (i >> 4) & 3, i & 15, x);
    }
}

// M7: gramacc1 with h>=4 (prompt-half)
__global__ void k_m7(const float* __restrict__ x) {
    __shared__ float sf[64];
    int i = blockIdx.x;                     // 128
    gramacc_body<1>(sf, i >> 6, 4 + ((i >> 4) & 3), i & 15, x);
}

// final apply
__global__ void k_apply1(const float* __restrict__ x, float* __restrict__ outp) {
    __shared__ float sf[256];
    apply_body<1>(sf, blockIdx.x, x, outp);
}

// ---------------- launch (kernel launches ONLY) ----------------
extern "C" void kernel_launch(void* const* d_in, const int* in_sizes, int n_in,
                              void* d_out, int out_size) {
    const float* x       = (const float*)d_in[0];
    const float* y       = (const float*)d_in[1];
    const float* temp    = (const float*)d_in[2];
    const float* w_po    = (const float*)d_in[3];
    const float* w_lp1   = (const float*)d_in[4];
    const float* w_lp2   = (const float*)d_in[5];
    const float* ln_g    = (const float*)d_in[6];
    const float* ln_b    = (const float*)d_in[7];
    const float* temp_in = (const float*)d_in[8];
    const float* w_qkv   = (const float*)d_in[9];
    const float* w_qkvd  = (const float*)d_in[10];
    const float* w_mproj = (const float*)d_in[11];
    const float* w_c3    = (const float*)d_in[12];
    const float* w_k2    = (const float*)d_in[13];
    const float* w_k3    = (const float*)d_in[14];
    const float* w_k4    = (const float*)d_in[15];
    const float* w_d3    = (const float*)d_in[16];
    const float* b_d3    = (const float*)d_in[17];
    const float* w_d5    = (const float*)d_in[18];
    const float* b_d5    = (const float*)d_in[19];
    const float* w_d7    = (const float*)d_in[20];
    const float* b_d7    = (const float*)d_in[21];
    const float* w_pw    = (const float*)d_in[22];
    const float* b_pw    = (const float*)d_in[23];

    k_setup<<<dim3(256, 8), 256>>>(x, y, w_lp2, w_c3, w_k2, w_k3, w_k4);  // 0
    k_m1<<<1012, 256>>>(x, ln_g, ln_b, w_lp1, w_qkv);                      // 1: k2 | ln+l1+qkv | l2
    k_m2<<<1792, 256>>>(w_qkvd);                                           // 2: k3 | qkvd
    k_m3<<<1024, 256>>>(x);                                                // 3: k4 | gramacc0  <- profiled
    k_m4<<<1026, 256>>>(w_d3, b_d3, w_d5, b_d5, w_d7, b_d7, w_mproj, temp_in); // 4: deform | meffsm0
    k_m5<<<1024, 256>>>(w_pw, b_pw, x);                                    // 5: pw | apply0
    k_m6<<<256, 256>>>(x);                                                 // 6: c3 | gramacc1(h<4)
    k_m7<<<128, 256>>>(x);                                                 // 7: gramacc1(h>=4)
    k_meffsm1<<<BB, 1024>>>(w_po, temp);                                   // 8
    k_apply1<<<(BB*4*NN)/256, 256>>>(x, (float*)d_out);                    // 9
}